// round 2
// baseline (speedup 1.0000x reference)
#include <cuda_runtime.h>
#include <cuda_bf16.h>
#include <math.h>

// Problem dims (fixed by the reference)
#define BATCH 8
#define HW    4096     // 64*64 query positions
#define LCTX  1024     // 32*32 context positions
#define EMB   512

// ---------------- scratch (device globals; no allocs allowed) ----------------
__device__ float g_Wq[EMB * EMB];                       // folded proj_in^T @ wq
__device__ float g_bq[EMB];                             // folded bias
__device__ float g_Q [(long)BATCH * HW   * EMB];        // 64 MB
__device__ float g_K [(long)BATCH * LCTX * EMB];        // 16 MB
__device__ float g_V [(long)BATCH * LCTX * EMB];        // 16 MB
__device__ float g_S [(long)BATCH * HW   * LCTX];       // 128 MB attention logits/probs
__device__ float g_Z [(long)BATCH * (EMB + EMB) * HW];  // 128 MB concat buffer [b][1024][4096]

// ---------------- generic tiled SGEMM ----------------
// C[m,n] = alpha * sum_k A(k,m)*B(k,n) + biasM[m] + biasN[n]
//   AT=true : A stored [K,M]  -> A[k*lda+m]
//   AT=false: A stored [M,K]  -> A[m*lda+k]
//   BT=false: B stored [K,N]  -> B[k*ldb+n]
//   BT=true : B stored [N,K]  -> B[n*ldb+k]
// Requires M%128==0, N%128==0, K%16==0. blockIdx.z = batch.
#define BM 128
#define BN 128
#define BKD 16
#define TM 8
#define TN 8

template<bool AT, bool BT>
__global__ void __launch_bounds__(256)
sgemm_kernel(const float* __restrict__ A, int lda, long strideA,
             const float* __restrict__ B, int ldb, long strideB,
             float* __restrict__ C, int ldc, long strideC,
             int M, int N, int K, float alpha,
             const float* __restrict__ biasM, const float* __restrict__ biasN)
{
    __shared__ float As[BKD][BM + 4];
    __shared__ float Bs[BKD][BN + 4];

    const int bz = blockIdx.z;
    A += (long)bz * strideA;
    B += (long)bz * strideB;
    C += (long)bz * strideC;

    const int m0 = blockIdx.y * BM;
    const int n0 = blockIdx.x * BN;
    const int tid = threadIdx.x;
    const int tx = tid % (BN / TN);   // 0..15 (n)
    const int ty = tid / (BN / TN);   // 0..15 (m)

    float acc[TM][TN];
#pragma unroll
    for (int i = 0; i < TM; i++)
#pragma unroll
        for (int j = 0; j < TN; j++) acc[i][j] = 0.f;

    for (int k0 = 0; k0 < K; k0 += BKD) {
        // ---- stage A tile ----
        if (AT) {
#pragma unroll
            for (int t = 0; t < (BKD * BM) / 256; t++) {
                int i = tid + t * 256;
                int k = i / BM, m = i % BM;
                As[k][m] = A[(long)(k0 + k) * lda + (m0 + m)];
            }
        } else {
#pragma unroll
            for (int t = 0; t < (BKD * BM) / 256; t++) {
                int i = tid + t * 256;
                int m = i / BKD, k = i % BKD;
                As[k][m] = A[(long)(m0 + m) * lda + (k0 + k)];
            }
        }
        // ---- stage B tile ----
        if (!BT) {
#pragma unroll
            for (int t = 0; t < (BKD * BN) / 256; t++) {
                int i = tid + t * 256;
                int k = i / BN, n = i % BN;
                Bs[k][n] = B[(long)(k0 + k) * ldb + (n0 + n)];
            }
        } else {
#pragma unroll
            for (int t = 0; t < (BKD * BN) / 256; t++) {
                int i = tid + t * 256;
                int n = i / BKD, k = i % BKD;
                Bs[k][n] = B[(long)(n0 + n) * ldb + (k0 + k)];
            }
        }
        __syncthreads();

#pragma unroll
        for (int k = 0; k < BKD; k++) {
            float a[TM], bb[TN];
#pragma unroll
            for (int i = 0; i < TM; i++) a[i] = As[k][ty * TM + i];
#pragma unroll
            for (int j = 0; j < TN; j++) bb[j] = Bs[k][tx * TN + j];
#pragma unroll
            for (int i = 0; i < TM; i++)
#pragma unroll
                for (int j = 0; j < TN; j++)
                    acc[i][j] = fmaf(a[i], bb[j], acc[i][j]);
        }
        __syncthreads();
    }

#pragma unroll
    for (int i = 0; i < TM; i++) {
        int m = m0 + ty * TM + i;
        float bm = biasM ? biasM[m] : 0.f;
#pragma unroll
        for (int j = 0; j < TN; j++) {
            int n = n0 + tx * TN + j;
            float bn = biasN ? biasN[n] : 0.f;
            C[(long)m * ldc + n] = alpha * acc[i][j] + bm + bn;
        }
    }
}

// ---------------- helpers ----------------

// bq_eff[f] = sum_e proj_in_b[e]*wq_w[e,f] + wq_b[f]
__global__ void fold_bias_kernel(const float* __restrict__ pib,
                                 const float* __restrict__ wq,
                                 const float* __restrict__ wqb,
                                 float* __restrict__ out)
{
    int f = blockIdx.x * blockDim.x + threadIdx.x;
    if (f >= EMB) return;
    float s = wqb[f];
    for (int e = 0; e < EMB; e++) s = fmaf(pib[e], wq[e * EMB + f], s);
    out[f] = s;
}

// row-wise softmax over [rows, 1024]; one block (256 thr) per row
__global__ void __launch_bounds__(256) softmax_rows_kernel(float* __restrict__ S)
{
    float* row = S + (long)blockIdx.x * LCTX;
    const int t = threadIdx.x;
    float v[4];
    float mx = -INFINITY;
#pragma unroll
    for (int j = 0; j < 4; j++) {
        v[j] = row[t + j * 256];
        mx = fmaxf(mx, v[j]);
    }
    __shared__ float red[256];
    red[t] = mx;
    __syncthreads();
    for (int s = 128; s > 0; s >>= 1) {
        if (t < s) red[t] = fmaxf(red[t], red[t + s]);
        __syncthreads();
    }
    mx = red[0];
    __syncthreads();
    float sum = 0.f;
#pragma unroll
    for (int j = 0; j < 4; j++) {
        v[j] = __expf(v[j] - mx);
        sum += v[j];
    }
    red[t] = sum;
    __syncthreads();
    for (int s = 128; s > 0; s >>= 1) {
        if (t < s) red[t] += red[t + s];
        __syncthreads();
    }
    float inv = 1.f / red[0];
#pragma unroll
    for (int j = 0; j < 4; j++) row[t + j * 256] = v[j] * inv;
}

// copy input [b][512][4096] into Z rows [0,512) of [b][1024][4096]
__global__ void copy_input_to_Z_kernel(const float4* __restrict__ in, float4* __restrict__ Z)
{
    long idx = (long)blockIdx.x * blockDim.x + threadIdx.x;   // over BATCH*512*4096/4
    const long per_b = (long)EMB * HW / 4;                    // 524288
    long b = idx / per_b;
    long r = idx - b * per_b;
    Z[b * ((long)2 * EMB * HW / 4) + r] = in[idx];
}

// ---------------- launch ----------------
extern "C" void kernel_launch(void* const* d_in, const int* in_sizes, int n_in,
                              void* d_out, int out_size)
{
    const float* input      = (const float*)d_in[0];   // [8,512,64,64]
    const float* context    = (const float*)d_in[1];   // [8,512,32,32]
    const float* proj_in_w  = (const float*)d_in[2];   // [512,512] (e,c)
    const float* proj_in_b  = (const float*)d_in[3];   // [512]
    const float* wq_w       = (const float*)d_in[4];   // [512,512] (in,out)
    const float* wq_b       = (const float*)d_in[5];
    const float* wk_w       = (const float*)d_in[6];
    const float* wk_b       = (const float*)d_in[7];
    const float* wv_w       = (const float*)d_in[8];
    const float* wv_b       = (const float*)d_in[9];
    const float* proj_out_w = (const float*)d_in[10];  // [512,1024]
    const float* proj_out_b = (const float*)d_in[11];  // [512]
    float* out = (float*)d_out;                        // [8,512,64,64]

    float *Wq, *bq, *Q, *Kb, *Vb, *S, *Z;
    cudaGetSymbolAddress((void**)&Wq, g_Wq);
    cudaGetSymbolAddress((void**)&bq, g_bq);
    cudaGetSymbolAddress((void**)&Q,  g_Q);
    cudaGetSymbolAddress((void**)&Kb, g_K);
    cudaGetSymbolAddress((void**)&Vb, g_V);
    cudaGetSymbolAddress((void**)&S,  g_S);
    cudaGetSymbolAddress((void**)&Z,  g_Z);

    const float scale = 1.0f / sqrtf((float)EMB);

    // 1) Wq_eff[c,f] = sum_e proj_in_w[e,c] * wq_w[e,f]   (TN, K=512)
    {
        dim3 grid(EMB / BN, EMB / BM, 1);
        sgemm_kernel<true, false><<<grid, 256>>>(
            proj_in_w, EMB, 0, wq_w, EMB, 0, Wq, EMB, 0,
            EMB, EMB, EMB, 1.0f, nullptr, nullptr);
    }
    // 2) folded bias
    fold_bias_kernel<<<2, 256>>>(proj_in_b, wq_w, wq_b, bq);

    // 3) Q[b,p,f] = sum_c input[b,c,p] * Wq_eff[c,f] + bq[f]   (TN)
    {
        dim3 grid(EMB / BN, HW / BM, BATCH);
        sgemm_kernel<true, false><<<grid, 256>>>(
            input, HW, (long)EMB * HW,
            Wq, EMB, 0,
            Q, EMB, (long)HW * EMB,
            HW, EMB, EMB, 1.0f, nullptr, bq);
    }
    // 4) K[b,l,f] = sum_c context[b,c,l] * wk_w[c,f] + wk_b[f]   (TN)
    {
        dim3 grid(EMB / BN, LCTX / BM, BATCH);
        sgemm_kernel<true, false><<<grid, 256>>>(
            context, LCTX, (long)EMB * LCTX,
            wk_w, EMB, 0,
            Kb, EMB, (long)LCTX * EMB,
            LCTX, EMB, EMB, 1.0f, nullptr, wk_b);
    }
    // 5) V[b,l,f]
    {
        dim3 grid(EMB / BN, LCTX / BM, BATCH);
        sgemm_kernel<true, false><<<grid, 256>>>(
            context, LCTX, (long)EMB * LCTX,
            wv_w, EMB, 0,
            Vb, EMB, (long)LCTX * EMB,
            LCTX, EMB, EMB, 1.0f, nullptr, wv_b);
    }
    // 6) S[b,p,l] = scale * sum_f Q[b,p,f]*K[b,l,f]   (NT)
    {
        dim3 grid(LCTX / BN, HW / BM, BATCH);
        sgemm_kernel<false, true><<<grid, 256>>>(
            Q, EMB, (long)HW * EMB,
            Kb, EMB, (long)LCTX * EMB,
            S, LCTX, (long)HW * LCTX,
            HW, LCTX, EMB, scale, nullptr, nullptr);
    }
    // 7) softmax over L
    softmax_rows_kernel<<<BATCH * HW, 256>>>(S);

    // 8) copy input into Z rows [0,512)
    {
        long n4 = (long)BATCH * EMB * HW / 4;
        copy_input_to_Z_kernel<<<(int)(n4 / 256), 256>>>((const float4*)input, (float4*)Z);
    }
    // 9) Z[b, 512+e, p] = O^T[e,p] = sum_l V[b,l,e] * P[b,p,l]   (TT: A=V [K=L,M=E], B=S [N=P,K=L])
    {
        dim3 grid(HW / BN, EMB / BM, BATCH);
        sgemm_kernel<true, true><<<grid, 256>>>(
            Vb, EMB, (long)LCTX * EMB,
            S, LCTX, (long)HW * LCTX,
            Z + (long)EMB * HW, HW, (long)2 * EMB * HW,
            EMB, HW, LCTX, 1.0f, nullptr, nullptr);
    }
    // 10) out[b,o,p] = sum_k proj_out_w[o,k] * Z[b,k,p] + proj_out_b[o]   (NN)
    {
        dim3 grid(HW / BN, EMB / BM, BATCH);
        sgemm_kernel<false, false><<<grid, 256>>>(
            proj_out_w, 2 * EMB, 0,
            Z, HW, (long)2 * EMB * HW,
            out, HW, (long)EMB * HW,
            EMB, HW, 2 * EMB, 1.0f, proj_out_b, nullptr);
    }
}

// round 4
// speedup vs baseline: 2.3847x; 2.3847x over previous
#include <cuda_runtime.h>
#include <cuda_bf16.h>
#include <math.h>
#include <stdint.h>

#define BATCH 8
#define HW    4096
#define LCTX  1024
#define EMB   512

typedef __nv_bfloat16 bf16;

// ---------------- device scratch ----------------
__device__ __align__(128) float g_bq[EMB];
__device__ __align__(128) float g_S[(long)BATCH * HW * LCTX];

__device__ __align__(128) bf16 g_wqT0_h[EMB*EMB], g_wqT0_l[EMB*EMB];   // wq^T [f][e]
__device__ __align__(128) bf16 g_piT_h [EMB*EMB], g_piT_l [EMB*EMB];   // pi^T [c][e]
__device__ __align__(128) bf16 g_WqT_h [EMB*EMB], g_WqT_l [EMB*EMB];   // folded [f][c]
__device__ __align__(128) bf16 g_wkT_h [EMB*EMB], g_wkT_l [EMB*EMB];   // [f][c]
__device__ __align__(128) bf16 g_wvT_h [EMB*EMB], g_wvT_l [EMB*EMB];   // [e][c]
__device__ __align__(128) bf16 g_po_h[EMB*2*EMB], g_po_l[EMB*2*EMB];   // [o][k]

__device__ __align__(128) bf16 g_Z_h[(long)BATCH*HW*2*EMB], g_Z_l[(long)BATCH*HW*2*EMB];
__device__ __align__(128) bf16 g_ctxT_h[(long)BATCH*LCTX*EMB], g_ctxT_l[(long)BATCH*LCTX*EMB];
__device__ __align__(128) bf16 g_Q_h[(long)BATCH*HW*EMB],   g_Q_l[(long)BATCH*HW*EMB];
__device__ __align__(128) bf16 g_K_h[(long)BATCH*LCTX*EMB], g_K_l[(long)BATCH*LCTX*EMB];
__device__ __align__(128) bf16 g_VT_h[(long)BATCH*EMB*LCTX], g_VT_l[(long)BATCH*EMB*LCTX];
__device__ __align__(128) bf16 g_P_h[(long)BATCH*HW*LCTX],  g_P_l[(long)BATCH*HW*LCTX];

// ---------------- helpers ----------------
__device__ __forceinline__ uint32_t smem_u32(const void* p) {
    uint32_t r;
    asm("{ .reg .u64 t; cvta.to.shared.u64 t, %1; cvt.u32.u64 %0, t; }" : "=r"(r) : "l"(p));
    return r;
}
__device__ __forceinline__ void cp_async16(uint32_t dst, const void* src) {
    asm volatile("cp.async.cg.shared.global [%0], [%1], 16;" :: "r"(dst), "l"(src) : "memory");
}
#define CP_COMMIT() asm volatile("cp.async.commit_group;" ::: "memory")
#define CP_WAIT(n)  asm volatile("cp.async.wait_group %0;" :: "n"(n) : "memory")

__device__ __forceinline__ void ldsm_x4(uint32_t (&r)[4], uint32_t addr) {
    asm volatile("ldmatrix.sync.aligned.m8n8.x4.shared.b16 {%0,%1,%2,%3}, [%4];"
                 : "=r"(r[0]), "=r"(r[1]), "=r"(r[2]), "=r"(r[3]) : "r"(addr));
}
__device__ __forceinline__ void mma16816(float (&d)[4], const uint32_t (&a)[4],
                                         uint32_t b0, uint32_t b1) {
    asm volatile(
        "mma.sync.aligned.m16n8k16.row.col.f32.bf16.bf16.f32 "
        "{%0,%1,%2,%3}, {%4,%5,%6,%7}, {%8,%9}, {%0,%1,%2,%3};"
        : "+f"(d[0]), "+f"(d[1]), "+f"(d[2]), "+f"(d[3])
        : "r"(a[0]), "r"(a[1]), "r"(a[2]), "r"(a[3]), "r"(b0), "r"(b1));
}
__device__ __forceinline__ uint32_t pack2(bf16 a, bf16 b) {
    return (uint32_t)__bfloat16_as_ushort(a) | ((uint32_t)__bfloat16_as_ushort(b) << 16);
}

// ---------------- mma.sync bf16x3 GEMM ----------------
// D[m,n] = alpha * sum_k (Ah+Al)[m,k]*(Bh+Bl)[n,k] + biasM[m] + biasN[n]
// A,B row-major [rows][K] bf16 planes. BM=BN=128, K chunk 32, double buffered.
#define PAD 40
#define PLANE_ELEMS (128 * PAD)
#define PLANE_B (PLANE_ELEMS * 2)
#define STAGE_B (4 * PLANE_B)          // Ah, Al, Bh, Bl
#define GEMM_SMEM (2 * STAGE_B)        // 81920 B

// stage one plane chunk: 128 rows x 32 cols bf16
__device__ __forceinline__ void stage_plane(uint32_t sb, const bf16* __restrict__ g,
                                            int ld, int kofs, int tid) {
    const int q = tid & 3;             // 16B chunk within row (cols q*8..q*8+7)
    const int r0 = tid >> 2;           // rows tid/4 and +64
#pragma unroll
    for (int p = 0; p < 2; p++) {
        int r = r0 + p * 64;
        cp_async16(sb + (uint32_t)(r * PAD + q * 8) * 2,
                   g + (long)r * ld + kofs + q * 8);
    }
}

template <bool SPLIT>
__global__ void __launch_bounds__(256)
gemm_mma_kernel(const bf16* __restrict__ Ah, const bf16* __restrict__ Al, int lda, long sA,
                const bf16* __restrict__ Bh, const bf16* __restrict__ Bl, int ldb, long sB,
                float* __restrict__ Cf, bf16* __restrict__ Ch, bf16* __restrict__ Cl,
                int ldc, long sC, int K, float alpha,
                const float* __restrict__ biasM, const float* __restrict__ biasN)
{
    extern __shared__ __align__(128) char smem[];

    const int tid = threadIdx.x, wid = tid >> 5, lane = tid & 31;
    const int b = blockIdx.z;
    const int m0 = blockIdx.y * 128, n0 = blockIdx.x * 128;
    const int wm = (wid & 3) * 32;     // warp m offset in tile
    const int wn = (wid >> 2) * 64;    // warp n offset in tile

    const bf16* pAh = Ah + (long)b * sA + (long)m0 * lda;
    const bf16* pAl = Al + (long)b * sA + (long)m0 * lda;
    const bf16* pBh = Bh + (long)b * sB + (long)n0 * ldb;
    const bf16* pBl = Bl + (long)b * sB + (long)n0 * ldb;

    const uint32_t s_base = smem_u32(smem);

    float acc[2][8][4];
#pragma unroll
    for (int i = 0; i < 2; i++)
#pragma unroll
        for (int j = 0; j < 8; j++)
#pragma unroll
            for (int q = 0; q < 4; q++) acc[i][j][q] = 0.f;

    const int nch = K >> 5;

    // prefetch chunk 0
    {
        uint32_t sb = s_base;
        stage_plane(sb + 0 * PLANE_B, pAh, lda, 0, tid);
        stage_plane(sb + 1 * PLANE_B, pAl, lda, 0, tid);
        stage_plane(sb + 2 * PLANE_B, pBh, ldb, 0, tid);
        stage_plane(sb + 3 * PLANE_B, pBl, ldb, 0, tid);
        CP_COMMIT();
    }

    // ldmatrix lane addressing (element offsets within plane)
    const int lrow = lane & 15;                 // row within 16-row group
    const int lkof = (lane >> 4) * 8;           // k sub-offset

    for (int c = 0; c < nch; c++) {
        const uint32_t cur = s_base + (uint32_t)(c & 1) * STAGE_B;
        if (c + 1 < nch) {
            const uint32_t nxt = s_base + (uint32_t)((c + 1) & 1) * STAGE_B;
            const int kofs = (c + 1) << 5;
            stage_plane(nxt + 0 * PLANE_B, pAh, lda, kofs, tid);
            stage_plane(nxt + 1 * PLANE_B, pAl, lda, kofs, tid);
            stage_plane(nxt + 2 * PLANE_B, pBh, ldb, kofs, tid);
            stage_plane(nxt + 3 * PLANE_B, pBl, ldb, kofs, tid);
            CP_COMMIT();
            CP_WAIT(1);
        } else {
            CP_WAIT(0);
        }
        __syncthreads();

#pragma unroll
        for (int ks = 0; ks < 2; ks++) {
            const int kk = ks * 16 + lkof;
            uint32_t ah[2][4], al[2][4];
#pragma unroll
            for (int i = 0; i < 2; i++) {
                uint32_t off = (uint32_t)((wm + i * 16 + lrow) * PAD + kk) * 2;
                ldsm_x4(ah[i], cur + 0 * PLANE_B + off);
                ldsm_x4(al[i], cur + 1 * PLANE_B + off);
            }
            uint32_t bh[4][4], bl[4][4];
#pragma unroll
            for (int jj = 0; jj < 4; jj++) {
                uint32_t off = (uint32_t)((wn + jj * 16 + lrow) * PAD + kk) * 2;
                ldsm_x4(bh[jj], cur + 2 * PLANE_B + off);
                ldsm_x4(bl[jj], cur + 3 * PLANE_B + off);
            }
#pragma unroll
            for (int i = 0; i < 2; i++) {
#pragma unroll
                for (int j = 0; j < 8; j++) {
                    const int jj = j >> 1, sel = j & 1;
                    mma16816(acc[i][j], ah[i], bh[jj][sel], bh[jj][sel + 2]);
                    mma16816(acc[i][j], ah[i], bl[jj][sel], bl[jj][sel + 2]);
                    mma16816(acc[i][j], al[i], bh[jj][sel], bh[jj][sel + 2]);
                }
            }
        }
        __syncthreads();
    }

    // ---------------- epilogue ----------------
    const int mrow = m0 + wm + (lane >> 2);       // fragment row (c0,c1); +8 for c2,c3
    const int ncol0 = n0 + wn + 2 * (lane & 3);

#pragma unroll
    for (int i = 0; i < 2; i++) {
        const int m = mrow + i * 16;
        const float bm0 = biasM ? biasM[m] : 0.f;
        const float bm8 = biasM ? biasM[m + 8] : 0.f;
#pragma unroll
        for (int j = 0; j < 8; j++) {
            const int n = ncol0 + j * 8;
            const float bn0 = biasN ? biasN[n] : 0.f;
            const float bn1 = biasN ? biasN[n + 1] : 0.f;
            float v0 = alpha * acc[i][j][0] + bm0 + bn0;
            float v1 = alpha * acc[i][j][1] + bm0 + bn1;
            float v2 = alpha * acc[i][j][2] + bm8 + bn0;
            float v3 = alpha * acc[i][j][3] + bm8 + bn1;
            if (SPLIT) {
                bf16* ch = Ch + (long)b * sC;
                bf16* cl = Cl + (long)b * sC;
                bf16 h0 = __float2bfloat16(v0), h1 = __float2bfloat16(v1);
                bf16 h2 = __float2bfloat16(v2), h3 = __float2bfloat16(v3);
                *reinterpret_cast<uint32_t*>(ch + (long)m * ldc + n) = pack2(h0, h1);
                *reinterpret_cast<uint32_t*>(ch + (long)(m + 8) * ldc + n) = pack2(h2, h3);
                *reinterpret_cast<uint32_t*>(cl + (long)m * ldc + n) =
                    pack2(__float2bfloat16(v0 - __bfloat162float(h0)),
                          __float2bfloat16(v1 - __bfloat162float(h1)));
                *reinterpret_cast<uint32_t*>(cl + (long)(m + 8) * ldc + n) =
                    pack2(__float2bfloat16(v2 - __bfloat162float(h2)),
                          __float2bfloat16(v3 - __bfloat162float(h3)));
            } else {
                float* co = Cf + (long)b * sC;
                *reinterpret_cast<float2*>(co + (long)m * ldc + n) = make_float2(v0, v1);
                *reinterpret_cast<float2*>(co + (long)(m + 8) * ldc + n) = make_float2(v2, v3);
            }
        }
    }
}

// ---------------- aux kernels ----------------
__global__ void trans_convert_kernel(const float* __restrict__ src, long sstride, int src_ld,
                                     bf16* __restrict__ dh, bf16* __restrict__ dl,
                                     long dstride, int dst_ld)
{
    __shared__ float t[32][33];
    const float* S = src + (long)blockIdx.z * sstride;
    bf16* DH = dh + (long)blockIdx.z * dstride;
    bf16* DL = dl + (long)blockIdx.z * dstride;
    const int c0 = blockIdx.x * 32, r0 = blockIdx.y * 32;
    const int tx = threadIdx.x, ty = threadIdx.y;
#pragma unroll
    for (int k = 0; k < 4; k++)
        t[ty + 8*k][tx] = S[(long)(r0 + ty + 8*k) * src_ld + c0 + tx];
    __syncthreads();
#pragma unroll
    for (int k = 0; k < 4; k++) {
        float x = t[tx][ty + 8*k];
        bf16 h = __float2bfloat16(x);
        long o = (long)(c0 + ty + 8*k) * dst_ld + r0 + tx;
        DH[o] = h;
        DL[o] = __float2bfloat16(x - __bfloat162float(h));
    }
}

__global__ void convert_split_kernel(const float* __restrict__ s,
                                     bf16* __restrict__ dh, bf16* __restrict__ dl, int n)
{
    int i = blockIdx.x * blockDim.x + threadIdx.x;
    if (i >= n) return;
    float x = s[i];
    bf16 h = __float2bfloat16(x);
    dh[i] = h;
    dl[i] = __float2bfloat16(x - __bfloat162float(h));
}

__global__ void fold_bias_kernel(const float* __restrict__ pib, const float* __restrict__ wq,
                                 const float* __restrict__ wqb, float* __restrict__ out)
{
    int f = blockIdx.x * blockDim.x + threadIdx.x;
    if (f >= EMB) return;
    float s = wqb[f];
    for (int e = 0; e < EMB; e++) s = fmaf(pib[e], wq[e * EMB + f], s);
    out[f] = s;
}

__global__ void __launch_bounds__(256) softmax_split_kernel(const float* __restrict__ S,
                                                            bf16* __restrict__ Ph,
                                                            bf16* __restrict__ Pl)
{
    const float* row = S + (long)blockIdx.x * LCTX;
    const int t = threadIdx.x;
    float v[4], mx = -INFINITY;
#pragma unroll
    for (int j = 0; j < 4; j++) { v[j] = row[t + j*256]; mx = fmaxf(mx, v[j]); }
    __shared__ float red[256];
    red[t] = mx; __syncthreads();
    for (int s = 128; s > 0; s >>= 1) { if (t < s) red[t] = fmaxf(red[t], red[t+s]); __syncthreads(); }
    mx = red[0]; __syncthreads();
    float sum = 0.f;
#pragma unroll
    for (int j = 0; j < 4; j++) { v[j] = __expf(v[j] - mx); sum += v[j]; }
    red[t] = sum; __syncthreads();
    for (int s = 128; s > 0; s >>= 1) { if (t < s) red[t] += red[t+s]; __syncthreads(); }
    const float inv = 1.f / red[0];
    long base = (long)blockIdx.x * LCTX;
#pragma unroll
    for (int j = 0; j < 4; j++) {
        float p = v[j] * inv;
        bf16 h = __float2bfloat16(p);
        Ph[base + t + j*256] = h;
        Pl[base + t + j*256] = __float2bfloat16(p - __bfloat162float(h));
    }
}

// ---------------- launch ----------------
extern "C" void kernel_launch(void* const* d_in, const int* in_sizes, int n_in,
                              void* d_out, int out_size)
{
    const float* input      = (const float*)d_in[0];
    const float* context    = (const float*)d_in[1];
    const float* proj_in_w  = (const float*)d_in[2];
    const float* proj_in_b  = (const float*)d_in[3];
    const float* wq_w       = (const float*)d_in[4];
    const float* wq_b       = (const float*)d_in[5];
    const float* wk_w       = (const float*)d_in[6];
    const float* wk_b       = (const float*)d_in[7];
    const float* wv_w       = (const float*)d_in[8];
    const float* wv_b       = (const float*)d_in[9];
    const float* proj_out_w = (const float*)d_in[10];
    const float* proj_out_b = (const float*)d_in[11];
    float* out = (float*)d_out;

    cudaFuncSetAttribute(gemm_mma_kernel<true>,  cudaFuncAttributeMaxDynamicSharedMemorySize, GEMM_SMEM);
    cudaFuncSetAttribute(gemm_mma_kernel<false>, cudaFuncAttributeMaxDynamicSharedMemorySize, GEMM_SMEM);

    float *bq, *S;
    bf16 *wqT0h,*wqT0l,*piTh,*piTl,*WqTh,*WqTl,*wkTh,*wkTl,*wvTh,*wvTl,*poh,*pol;
    bf16 *Zh,*Zl,*cth,*ctl,*Qh,*Ql,*Kh,*Kl,*VTh,*VTl,*Ph,*Pl;
    cudaGetSymbolAddress((void**)&bq, g_bq);         cudaGetSymbolAddress((void**)&S, g_S);
    cudaGetSymbolAddress((void**)&wqT0h, g_wqT0_h);  cudaGetSymbolAddress((void**)&wqT0l, g_wqT0_l);
    cudaGetSymbolAddress((void**)&piTh, g_piT_h);    cudaGetSymbolAddress((void**)&piTl, g_piT_l);
    cudaGetSymbolAddress((void**)&WqTh, g_WqT_h);    cudaGetSymbolAddress((void**)&WqTl, g_WqT_l);
    cudaGetSymbolAddress((void**)&wkTh, g_wkT_h);    cudaGetSymbolAddress((void**)&wkTl, g_wkT_l);
    cudaGetSymbolAddress((void**)&wvTh, g_wvT_h);    cudaGetSymbolAddress((void**)&wvTl, g_wvT_l);
    cudaGetSymbolAddress((void**)&poh, g_po_h);      cudaGetSymbolAddress((void**)&pol, g_po_l);
    cudaGetSymbolAddress((void**)&Zh, g_Z_h);        cudaGetSymbolAddress((void**)&Zl, g_Z_l);
    cudaGetSymbolAddress((void**)&cth, g_ctxT_h);    cudaGetSymbolAddress((void**)&ctl, g_ctxT_l);
    cudaGetSymbolAddress((void**)&Qh, g_Q_h);        cudaGetSymbolAddress((void**)&Ql, g_Q_l);
    cudaGetSymbolAddress((void**)&Kh, g_K_h);        cudaGetSymbolAddress((void**)&Kl, g_K_l);
    cudaGetSymbolAddress((void**)&VTh, g_VT_h);      cudaGetSymbolAddress((void**)&VTl, g_VT_l);
    cudaGetSymbolAddress((void**)&Ph, g_P_h);        cudaGetSymbolAddress((void**)&Pl, g_P_l);

    const float scale = 1.0f / sqrtf((float)EMB);
    dim3 tb(32, 8);

    // weight prep
    fold_bias_kernel<<<2, 256>>>(proj_in_b, wq_w, wq_b, bq);
    trans_convert_kernel<<<dim3(16,16,1), tb>>>(wq_w, 0, EMB, wqT0h, wqT0l, 0, EMB);
    trans_convert_kernel<<<dim3(16,16,1), tb>>>(proj_in_w, 0, EMB, piTh, piTl, 0, EMB);
    trans_convert_kernel<<<dim3(16,16,1), tb>>>(wk_w, 0, EMB, wkTh, wkTl, 0, EMB);
    trans_convert_kernel<<<dim3(16,16,1), tb>>>(wv_w, 0, EMB, wvTh, wvTl, 0, EMB);
    convert_split_kernel<<<(EMB*2*EMB)/256, 256>>>(proj_out_w, poh, pol, EMB*2*EMB);
    trans_convert_kernel<<<dim3(32,16,BATCH), tb>>>(context, (long)EMB*LCTX, LCTX,
                                                    cth, ctl, (long)LCTX*EMB, EMB);
    trans_convert_kernel<<<dim3(128,16,BATCH), tb>>>(input, (long)EMB*HW, HW,
                                                     Zh, Zl, (long)HW*2*EMB, 2*EMB);

    // 1) WqT[f][c] = wqT0 · piT^T
    gemm_mma_kernel<true><<<dim3(4,4,1), 256, GEMM_SMEM>>>(
        wqT0h, wqT0l, EMB, 0, piTh, piTl, EMB, 0,
        nullptr, WqTh, WqTl, EMB, 0, EMB, 1.0f, nullptr, nullptr);
    // 2) K[l][f] = ctxT · wkT^T + wk_b
    gemm_mma_kernel<true><<<dim3(4,8,BATCH), 256, GEMM_SMEM>>>(
        cth, ctl, EMB, (long)LCTX*EMB, wkTh, wkTl, EMB, 0,
        nullptr, Kh, Kl, EMB, (long)LCTX*EMB, EMB, 1.0f, nullptr, wk_b);
    // 3) VT[e][l] = wvT · ctxT^T + wv_b[e]
    gemm_mma_kernel<true><<<dim3(8,4,BATCH), 256, GEMM_SMEM>>>(
        wvTh, wvTl, EMB, 0, cth, ctl, EMB, (long)LCTX*EMB,
        nullptr, VTh, VTl, LCTX, (long)EMB*LCTX, EMB, 1.0f, wv_b, nullptr);
    // 4) Q[p][f] = Z[:, :512] · WqT^T + bq
    gemm_mma_kernel<true><<<dim3(4,32,BATCH), 256, GEMM_SMEM>>>(
        Zh, Zl, 2*EMB, (long)HW*2*EMB, WqTh, WqTl, EMB, 0,
        nullptr, Qh, Ql, EMB, (long)HW*EMB, EMB, 1.0f, nullptr, bq);
    // 5) S[p][l] = scale * Q · K^T (fp32)
    gemm_mma_kernel<false><<<dim3(8,32,BATCH), 256, GEMM_SMEM>>>(
        Qh, Ql, EMB, (long)HW*EMB, Kh, Kl, EMB, (long)LCTX*EMB,
        S, nullptr, nullptr, LCTX, (long)HW*LCTX, EMB, scale, nullptr, nullptr);
    // 6) softmax + split
    softmax_split_kernel<<<BATCH*HW, 256>>>(S, Ph, Pl);
    // 7) O[p][e] = P · VT^T  -> Z cols [512,1024)
    gemm_mma_kernel<true><<<dim3(4,32,BATCH), 256, GEMM_SMEM>>>(
        Ph, Pl, LCTX, (long)HW*LCTX, VTh, VTl, LCTX, (long)EMB*LCTX,
        nullptr, Zh + EMB, Zl + EMB, 2*EMB, (long)HW*2*EMB, LCTX, 1.0f, nullptr, nullptr);
    // 8) out[o][p] = po · Z^T + proj_out_b[o] (fp32)
    gemm_mma_kernel<false><<<dim3(32,4,BATCH), 256, GEMM_SMEM>>>(
        poh, pol, 2*EMB, 0, Zh, Zl, 2*EMB, (long)HW*2*EMB,
        out, nullptr, nullptr, HW, (long)EMB*HW, 2*EMB, 1.0f, proj_out_b, nullptr);
}

// round 5
// speedup vs baseline: 2.5886x; 1.0855x over previous
#include <cuda_runtime.h>
#include <cuda_bf16.h>
#include <math.h>
#include <stdint.h>

#define BATCH 8
#define HW    4096
#define LCTX  1024
#define EMB   512

typedef __nv_bfloat16 bf16;

// ---------------- device scratch ----------------
__device__ __align__(128) float g_bq[EMB];
__device__ __align__(128) float g_S[(long)BATCH * HW * LCTX];

__device__ __align__(128) bf16 g_wqT0_h[EMB*EMB], g_wqT0_l[EMB*EMB];   // wq^T [f][e]
__device__ __align__(128) bf16 g_piT_h [EMB*EMB], g_piT_l [EMB*EMB];   // pi^T [c][e]
__device__ __align__(128) bf16 g_WqT_h [EMB*EMB], g_WqT_l [EMB*EMB];   // folded [f][c]
__device__ __align__(128) bf16 g_wkT_h [EMB*EMB], g_wkT_l [EMB*EMB];   // [f][c]
__device__ __align__(128) bf16 g_wvT_h [EMB*EMB], g_wvT_l [EMB*EMB];   // [e][c]
__device__ __align__(128) bf16 g_po_h[EMB*2*EMB], g_po_l[EMB*2*EMB];   // [o][k]

__device__ __align__(128) bf16 g_Z_h[(long)BATCH*HW*2*EMB], g_Z_l[(long)BATCH*HW*2*EMB];
__device__ __align__(128) bf16 g_ctxT_h[(long)BATCH*LCTX*EMB], g_ctxT_l[(long)BATCH*LCTX*EMB];
__device__ __align__(128) bf16 g_Q_h[(long)BATCH*HW*EMB],   g_Q_l[(long)BATCH*HW*EMB];
__device__ __align__(128) bf16 g_K_h[(long)BATCH*LCTX*EMB], g_K_l[(long)BATCH*LCTX*EMB];
__device__ __align__(128) bf16 g_VT_h[(long)BATCH*EMB*LCTX], g_VT_l[(long)BATCH*EMB*LCTX];
__device__ __align__(128) bf16 g_P_h[(long)BATCH*HW*LCTX],  g_P_l[(long)BATCH*HW*LCTX];

// ---------------- helpers ----------------
__device__ __forceinline__ uint32_t smem_u32(const void* p) {
    uint32_t r;
    asm("{ .reg .u64 t; cvta.to.shared.u64 t, %1; cvt.u32.u64 %0, t; }" : "=r"(r) : "l"(p));
    return r;
}
__device__ __forceinline__ void cp_async16(uint32_t dst, const void* src) {
    asm volatile("cp.async.cg.shared.global [%0], [%1], 16;" :: "r"(dst), "l"(src) : "memory");
}
#define CP_COMMIT() asm volatile("cp.async.commit_group;" ::: "memory")
#define CP_WAIT(n)  asm volatile("cp.async.wait_group %0;" :: "n"(n) : "memory")

__device__ __forceinline__ void ldsm_x4(uint32_t (&r)[4], uint32_t addr) {
    asm volatile("ldmatrix.sync.aligned.m8n8.x4.shared.b16 {%0,%1,%2,%3}, [%4];"
                 : "=r"(r[0]), "=r"(r[1]), "=r"(r[2]), "=r"(r[3]) : "r"(addr));
}
__device__ __forceinline__ void mma16816(float (&d)[4], const uint32_t (&a)[4],
                                         uint32_t b0, uint32_t b1) {
    asm volatile(
        "mma.sync.aligned.m16n8k16.row.col.f32.bf16.bf16.f32 "
        "{%0,%1,%2,%3}, {%4,%5,%6,%7}, {%8,%9}, {%0,%1,%2,%3};"
        : "+f"(d[0]), "+f"(d[1]), "+f"(d[2]), "+f"(d[3])
        : "r"(a[0]), "r"(a[1]), "r"(a[2]), "r"(a[3]), "r"(b0), "r"(b1));
}
__device__ __forceinline__ uint32_t pack2(bf16 a, bf16 b) {
    return (uint32_t)__bfloat16_as_ushort(a) | ((uint32_t)__bfloat16_as_ushort(b) << 16);
}

// ---------------- mma.sync bf16x3 GEMM ----------------
// D[m,n] = alpha * sum_k (Ah+Al)[m,k]*(Bh+Bl)[n,k] + biasM[m] + biasN[n]
// BM=BN=128, K chunk 64, double buffered, term-major MMA order (no acc RAW chains).
#define PAD 72
#define PLANE_ELEMS (128 * PAD)
#define PLANE_B (PLANE_ELEMS * 2)      // 18432
#define STAGE_B (4 * PLANE_B)          // 73728
#define GEMM_SMEM (2 * STAGE_B)        // 147456

// stage one plane chunk: 128 rows x 64 cols bf16
__device__ __forceinline__ void stage_plane(uint32_t sb, const bf16* __restrict__ g,
                                            int ld, int kofs, int tid) {
    const int q = tid & 7;             // 16B chunk within row
    const int r0 = tid >> 3;           // 32 rows per pass
#pragma unroll
    for (int p = 0; p < 4; p++) {
        int r = r0 + p * 32;
        cp_async16(sb + (uint32_t)(r * PAD + q * 8) * 2,
                   g + (long)r * ld + kofs + q * 8);
    }
}

template <bool SPLIT>
__global__ void __launch_bounds__(256)
gemm_mma_kernel(const bf16* __restrict__ Ah, const bf16* __restrict__ Al, int lda, long sA,
                const bf16* __restrict__ Bh, const bf16* __restrict__ Bl, int ldb, long sB,
                float* __restrict__ Cf, bf16* __restrict__ Ch, bf16* __restrict__ Cl,
                int ldc, long sC, int K, float alpha,
                const float* __restrict__ biasM, const float* __restrict__ biasN)
{
    extern __shared__ __align__(128) char smem[];

    const int tid = threadIdx.x, wid = tid >> 5, lane = tid & 31;
    const int b = blockIdx.z;
    const int m0 = blockIdx.y * 128, n0 = blockIdx.x * 128;
    const int wm = (wid & 3) * 32;     // warp m offset
    const int wn = (wid >> 2) * 64;    // warp n offset

    const bf16* pAh = Ah + (long)b * sA + (long)m0 * lda;
    const bf16* pAl = Al + (long)b * sA + (long)m0 * lda;
    const bf16* pBh = Bh + (long)b * sB + (long)n0 * ldb;
    const bf16* pBl = Bl + (long)b * sB + (long)n0 * ldb;

    const uint32_t s_base = smem_u32(smem);

    float acc[2][8][4];
#pragma unroll
    for (int i = 0; i < 2; i++)
#pragma unroll
        for (int j = 0; j < 8; j++)
#pragma unroll
            for (int q = 0; q < 4; q++) acc[i][j][q] = 0.f;

    const int nch = K >> 6;

    // prefetch chunk 0
    stage_plane(s_base + 0 * PLANE_B, pAh, lda, 0, tid);
    stage_plane(s_base + 1 * PLANE_B, pAl, lda, 0, tid);
    stage_plane(s_base + 2 * PLANE_B, pBh, ldb, 0, tid);
    stage_plane(s_base + 3 * PLANE_B, pBl, ldb, 0, tid);
    CP_COMMIT();

    const int lrow = lane & 15;
    const int lkof = (lane >> 4) * 8;

    for (int c = 0; c < nch; c++) {
        const uint32_t cur = s_base + (uint32_t)(c & 1) * STAGE_B;
        if (c + 1 < nch) {
            const uint32_t nxt = s_base + (uint32_t)((c + 1) & 1) * STAGE_B;
            const int kofs = (c + 1) << 6;
            stage_plane(nxt + 0 * PLANE_B, pAh, lda, kofs, tid);
            stage_plane(nxt + 1 * PLANE_B, pAl, lda, kofs, tid);
            stage_plane(nxt + 2 * PLANE_B, pBh, ldb, kofs, tid);
            stage_plane(nxt + 3 * PLANE_B, pBl, ldb, kofs, tid);
            CP_COMMIT();
            CP_WAIT(1);
        } else {
            CP_WAIT(0);
        }
        __syncthreads();

#pragma unroll
        for (int ks = 0; ks < 4; ks++) {
            const int kk = ks * 16 + lkof;
            uint32_t ah[2][4], al[2][4];
#pragma unroll
            for (int i = 0; i < 2; i++) {
                uint32_t off = (uint32_t)((wm + i * 16 + lrow) * PAD + kk) * 2;
                ldsm_x4(ah[i], cur + 0 * PLANE_B + off);
                ldsm_x4(al[i], cur + 1 * PLANE_B + off);
            }
            uint32_t bh[4][4], bl[4][4];
#pragma unroll
            for (int jj = 0; jj < 4; jj++) {
                uint32_t off = (uint32_t)((wn + jj * 16 + lrow) * PAD + kk) * 2;
                ldsm_x4(bh[jj], cur + 2 * PLANE_B + off);
                ldsm_x4(bl[jj], cur + 3 * PLANE_B + off);
            }
            // term-major order: 16 independent accumulators between reuses
#pragma unroll
            for (int t = 0; t < 3; t++) {
#pragma unroll
                for (int i = 0; i < 2; i++) {
#pragma unroll
                    for (int j = 0; j < 8; j++) {
                        const int jj = j >> 1, sel = j & 1;
                        if (t == 0)
                            mma16816(acc[i][j], ah[i], bh[jj][sel], bh[jj][sel + 2]);
                        else if (t == 1)
                            mma16816(acc[i][j], ah[i], bl[jj][sel], bl[jj][sel + 2]);
                        else
                            mma16816(acc[i][j], al[i], bh[jj][sel], bh[jj][sel + 2]);
                    }
                }
            }
        }
        __syncthreads();
    }

    // ---------------- epilogue ----------------
    const int mrow = m0 + wm + (lane >> 2);
    const int ncol0 = n0 + wn + 2 * (lane & 3);

#pragma unroll
    for (int i = 0; i < 2; i++) {
        const int m = mrow + i * 16;
        const float bm0 = biasM ? biasM[m] : 0.f;
        const float bm8 = biasM ? biasM[m + 8] : 0.f;
#pragma unroll
        for (int j = 0; j < 8; j++) {
            const int n = ncol0 + j * 8;
            const float bn0 = biasN ? biasN[n] : 0.f;
            const float bn1 = biasN ? biasN[n + 1] : 0.f;
            float v0 = alpha * acc[i][j][0] + bm0 + bn0;
            float v1 = alpha * acc[i][j][1] + bm0 + bn1;
            float v2 = alpha * acc[i][j][2] + bm8 + bn0;
            float v3 = alpha * acc[i][j][3] + bm8 + bn1;
            if (SPLIT) {
                bf16* ch = Ch + (long)b * sC;
                bf16* cl = Cl + (long)b * sC;
                bf16 h0 = __float2bfloat16(v0), h1 = __float2bfloat16(v1);
                bf16 h2 = __float2bfloat16(v2), h3 = __float2bfloat16(v3);
                *reinterpret_cast<uint32_t*>(ch + (long)m * ldc + n) = pack2(h0, h1);
                *reinterpret_cast<uint32_t*>(ch + (long)(m + 8) * ldc + n) = pack2(h2, h3);
                *reinterpret_cast<uint32_t*>(cl + (long)m * ldc + n) =
                    pack2(__float2bfloat16(v0 - __bfloat162float(h0)),
                          __float2bfloat16(v1 - __bfloat162float(h1)));
                *reinterpret_cast<uint32_t*>(cl + (long)(m + 8) * ldc + n) =
                    pack2(__float2bfloat16(v2 - __bfloat162float(h2)),
                          __float2bfloat16(v3 - __bfloat162float(h3)));
            } else {
                float* co = Cf + (long)b * sC;
                *reinterpret_cast<float2*>(co + (long)m * ldc + n) = make_float2(v0, v1);
                *reinterpret_cast<float2*>(co + (long)(m + 8) * ldc + n) = make_float2(v2, v3);
            }
        }
    }
}

// ---------------- aux kernels ----------------
__global__ void trans_convert_kernel(const float* __restrict__ src, long sstride, int src_ld,
                                     bf16* __restrict__ dh, bf16* __restrict__ dl,
                                     long dstride, int dst_ld)
{
    __shared__ float t[32][33];
    const float* S = src + (long)blockIdx.z * sstride;
    bf16* DH = dh + (long)blockIdx.z * dstride;
    bf16* DL = dl + (long)blockIdx.z * dstride;
    const int c0 = blockIdx.x * 32, r0 = blockIdx.y * 32;
    const int tx = threadIdx.x, ty = threadIdx.y;
#pragma unroll
    for (int k = 0; k < 4; k++)
        t[ty + 8*k][tx] = S[(long)(r0 + ty + 8*k) * src_ld + c0 + tx];
    __syncthreads();
#pragma unroll
    for (int k = 0; k < 4; k++) {
        float x = t[tx][ty + 8*k];
        bf16 h = __float2bfloat16(x);
        long o = (long)(c0 + ty + 8*k) * dst_ld + r0 + tx;
        DH[o] = h;
        DL[o] = __float2bfloat16(x - __bfloat162float(h));
    }
}

__global__ void convert_split_kernel(const float* __restrict__ s,
                                     bf16* __restrict__ dh, bf16* __restrict__ dl, int n)
{
    int i = blockIdx.x * blockDim.x + threadIdx.x;
    if (i >= n) return;
    float x = s[i];
    bf16 h = __float2bfloat16(x);
    dh[i] = h;
    dl[i] = __float2bfloat16(x - __bfloat162float(h));
}

__global__ void fold_bias_kernel(const float* __restrict__ pib, const float* __restrict__ wq,
                                 const float* __restrict__ wqb, float* __restrict__ out)
{
    int f = blockIdx.x * blockDim.x + threadIdx.x;
    if (f >= EMB) return;
    float s = wqb[f];
    for (int e = 0; e < EMB; e++) s = fmaf(pib[e], wq[e * EMB + f], s);
    out[f] = s;
}

__global__ void __launch_bounds__(256) softmax_split_kernel(const float* __restrict__ S,
                                                            bf16* __restrict__ Ph,
                                                            bf16* __restrict__ Pl)
{
    const float* row = S + (long)blockIdx.x * LCTX;
    const int t = threadIdx.x;
    float v[4], mx = -INFINITY;
#pragma unroll
    for (int j = 0; j < 4; j++) { v[j] = row[t + j*256]; mx = fmaxf(mx, v[j]); }
    __shared__ float red[256];
    red[t] = mx; __syncthreads();
    for (int s = 128; s > 0; s >>= 1) { if (t < s) red[t] = fmaxf(red[t], red[t+s]); __syncthreads(); }
    mx = red[0]; __syncthreads();
    float sum = 0.f;
#pragma unroll
    for (int j = 0; j < 4; j++) { v[j] = __expf(v[j] - mx); sum += v[j]; }
    red[t] = sum; __syncthreads();
    for (int s = 128; s > 0; s >>= 1) { if (t < s) red[t] += red[t+s]; __syncthreads(); }
    const float inv = 1.f / red[0];
    long base = (long)blockIdx.x * LCTX;
#pragma unroll
    for (int j = 0; j < 4; j++) {
        float p = v[j] * inv;
        bf16 h = __float2bfloat16(p);
        Ph[base + t + j*256] = h;
        Pl[base + t + j*256] = __float2bfloat16(p - __bfloat162float(h));
    }
}

// ---------------- launch ----------------
extern "C" void kernel_launch(void* const* d_in, const int* in_sizes, int n_in,
                              void* d_out, int out_size)
{
    const float* input      = (const float*)d_in[0];
    const float* context    = (const float*)d_in[1];
    const float* proj_in_w  = (const float*)d_in[2];
    const float* proj_in_b  = (const float*)d_in[3];
    const float* wq_w       = (const float*)d_in[4];
    const float* wq_b       = (const float*)d_in[5];
    const float* wk_w       = (const float*)d_in[6];
    const float* wk_b       = (const float*)d_in[7];
    const float* wv_w       = (const float*)d_in[8];
    const float* wv_b       = (const float*)d_in[9];
    const float* proj_out_w = (const float*)d_in[10];
    const float* proj_out_b = (const float*)d_in[11];
    float* out = (float*)d_out;

    cudaFuncSetAttribute(gemm_mma_kernel<true>,  cudaFuncAttributeMaxDynamicSharedMemorySize, GEMM_SMEM);
    cudaFuncSetAttribute(gemm_mma_kernel<false>, cudaFuncAttributeMaxDynamicSharedMemorySize, GEMM_SMEM);

    float *bq, *S;
    bf16 *wqT0h,*wqT0l,*piTh,*piTl,*WqTh,*WqTl,*wkTh,*wkTl,*wvTh,*wvTl,*poh,*pol;
    bf16 *Zh,*Zl,*cth,*ctl,*Qh,*Ql,*Kh,*Kl,*VTh,*VTl,*Ph,*Pl;
    cudaGetSymbolAddress((void**)&bq, g_bq);         cudaGetSymbolAddress((void**)&S, g_S);
    cudaGetSymbolAddress((void**)&wqT0h, g_wqT0_h);  cudaGetSymbolAddress((void**)&wqT0l, g_wqT0_l);
    cudaGetSymbolAddress((void**)&piTh, g_piT_h);    cudaGetSymbolAddress((void**)&piTl, g_piT_l);
    cudaGetSymbolAddress((void**)&WqTh, g_WqT_h);    cudaGetSymbolAddress((void**)&WqTl, g_WqT_l);
    cudaGetSymbolAddress((void**)&wkTh, g_wkT_h);    cudaGetSymbolAddress((void**)&wkTl, g_wkT_l);
    cudaGetSymbolAddress((void**)&wvTh, g_wvT_h);    cudaGetSymbolAddress((void**)&wvTl, g_wvT_l);
    cudaGetSymbolAddress((void**)&poh, g_po_h);      cudaGetSymbolAddress((void**)&pol, g_po_l);
    cudaGetSymbolAddress((void**)&Zh, g_Z_h);        cudaGetSymbolAddress((void**)&Zl, g_Z_l);
    cudaGetSymbolAddress((void**)&cth, g_ctxT_h);    cudaGetSymbolAddress((void**)&ctl, g_ctxT_l);
    cudaGetSymbolAddress((void**)&Qh, g_Q_h);        cudaGetSymbolAddress((void**)&Ql, g_Q_l);
    cudaGetSymbolAddress((void**)&Kh, g_K_h);        cudaGetSymbolAddress((void**)&Kl, g_K_l);
    cudaGetSymbolAddress((void**)&VTh, g_VT_h);      cudaGetSymbolAddress((void**)&VTl, g_VT_l);
    cudaGetSymbolAddress((void**)&Ph, g_P_h);        cudaGetSymbolAddress((void**)&Pl, g_P_l);

    const float scale = 1.0f / sqrtf((float)EMB);
    dim3 tb(32, 8);

    // weight prep
    fold_bias_kernel<<<2, 256>>>(proj_in_b, wq_w, wq_b, bq);
    trans_convert_kernel<<<dim3(16,16,1), tb>>>(wq_w, 0, EMB, wqT0h, wqT0l, 0, EMB);
    trans_convert_kernel<<<dim3(16,16,1), tb>>>(proj_in_w, 0, EMB, piTh, piTl, 0, EMB);
    trans_convert_kernel<<<dim3(16,16,1), tb>>>(wk_w, 0, EMB, wkTh, wkTl, 0, EMB);
    trans_convert_kernel<<<dim3(16,16,1), tb>>>(wv_w, 0, EMB, wvTh, wvTl, 0, EMB);
    convert_split_kernel<<<(EMB*2*EMB)/256, 256>>>(proj_out_w, poh, pol, EMB*2*EMB);
    trans_convert_kernel<<<dim3(32,16,BATCH), tb>>>(context, (long)EMB*LCTX, LCTX,
                                                    cth, ctl, (long)LCTX*EMB, EMB);
    trans_convert_kernel<<<dim3(128,16,BATCH), tb>>>(input, (long)EMB*HW, HW,
                                                     Zh, Zl, (long)HW*2*EMB, 2*EMB);

    // 1) WqT[f][c] = wqT0 · piT^T
    gemm_mma_kernel<true><<<dim3(4,4,1), 256, GEMM_SMEM>>>(
        wqT0h, wqT0l, EMB, 0, piTh, piTl, EMB, 0,
        nullptr, WqTh, WqTl, EMB, 0, EMB, 1.0f, nullptr, nullptr);
    // 2) K[l][f] = ctxT · wkT^T + wk_b
    gemm_mma_kernel<true><<<dim3(4,8,BATCH), 256, GEMM_SMEM>>>(
        cth, ctl, EMB, (long)LCTX*EMB, wkTh, wkTl, EMB, 0,
        nullptr, Kh, Kl, EMB, (long)LCTX*EMB, EMB, 1.0f, nullptr, wk_b);
    // 3) VT[e][l] = wvT · ctxT^T + wv_b[e]
    gemm_mma_kernel<true><<<dim3(8,4,BATCH), 256, GEMM_SMEM>>>(
        wvTh, wvTl, EMB, 0, cth, ctl, EMB, (long)LCTX*EMB,
        nullptr, VTh, VTl, LCTX, (long)EMB*LCTX, EMB, 1.0f, wv_b, nullptr);
    // 4) Q[p][f] = Z[:, :512] · WqT^T + bq
    gemm_mma_kernel<true><<<dim3(4,32,BATCH), 256, GEMM_SMEM>>>(
        Zh, Zl, 2*EMB, (long)HW*2*EMB, WqTh, WqTl, EMB, 0,
        nullptr, Qh, Ql, EMB, (long)HW*EMB, EMB, 1.0f, nullptr, bq);
    // 5) S[p][l] = scale * Q · K^T (fp32)
    gemm_mma_kernel<false><<<dim3(8,32,BATCH), 256, GEMM_SMEM>>>(
        Qh, Ql, EMB, (long)HW*EMB, Kh, Kl, EMB, (long)LCTX*EMB,
        S, nullptr, nullptr, LCTX, (long)HW*LCTX, EMB, scale, nullptr, nullptr);
    // 6) softmax + split
    softmax_split_kernel<<<BATCH*HW, 256>>>(S, Ph, Pl);
    // 7) O[p][e] = P · VT^T  -> Z cols [512,1024)
    gemm_mma_kernel<true><<<dim3(4,32,BATCH), 256, GEMM_SMEM>>>(
        Ph, Pl, LCTX, (long)HW*LCTX, VTh, VTl, LCTX, (long)EMB*LCTX,
        nullptr, Zh + EMB, Zl + EMB, 2*EMB, (long)HW*2*EMB, LCTX, 1.0f, nullptr, nullptr);
    // 8) out[o][p] = po · Z^T + proj_out_b[o] (fp32)
    gemm_mma_kernel<false><<<dim3(32,4,BATCH), 256, GEMM_SMEM>>>(
        poh, pol, 2*EMB, 0, Zh, Zl, 2*EMB, (long)HW*2*EMB,
        out, nullptr, nullptr, HW, (long)EMB*HW, 2*EMB, 1.0f, proj_out_b, nullptr);
}

// round 6
// speedup vs baseline: 3.1801x; 1.2285x over previous
#include <cuda_runtime.h>
#include <cuda_bf16.h>
#include <math.h>
#include <stdint.h>

#define BATCH 8
#define HW    4096
#define LCTX  1024
#define EMB   512

typedef __nv_bfloat16 bf16;

// blocked layout: [rowblk][kblk][128x64 swizzled] ; 16KB per block
#define BLK_ELEMS 8192
#define BLK_BYTES 16384
#define STAGE_BYTES (4 * BLK_BYTES)
#define NSTAGE 3
#define GEMM_SMEM (NSTAGE * STAGE_BYTES)   // 196608

// ---------------- device scratch ----------------
__device__ __align__(128) float g_bq[EMB];
__device__ __align__(128) float g_S[(long)BATCH * HW * LCTX];

__device__ __align__(128) bf16 g_wqT0_h[EMB*EMB], g_wqT0_l[EMB*EMB];   // wq^T [f][e]
__device__ __align__(128) bf16 g_piT_h [EMB*EMB], g_piT_l [EMB*EMB];   // pi^T [c][e]
__device__ __align__(128) bf16 g_WqT_h [EMB*EMB], g_WqT_l [EMB*EMB];   // folded [f][c]
__device__ __align__(128) bf16 g_wkT_h [EMB*EMB], g_wkT_l [EMB*EMB];   // [f][c]
__device__ __align__(128) bf16 g_wvT_h [EMB*EMB], g_wvT_l [EMB*EMB];   // [e][c]
__device__ __align__(128) bf16 g_po_h[EMB*2*EMB], g_po_l[EMB*2*EMB];   // [o][k]

__device__ __align__(128) bf16 g_Z_h[(long)BATCH*HW*2*EMB], g_Z_l[(long)BATCH*HW*2*EMB];
__device__ __align__(128) bf16 g_ctxT_h[(long)BATCH*LCTX*EMB], g_ctxT_l[(long)BATCH*LCTX*EMB];
__device__ __align__(128) bf16 g_Q_h[(long)BATCH*HW*EMB],   g_Q_l[(long)BATCH*HW*EMB];
__device__ __align__(128) bf16 g_K_h[(long)BATCH*LCTX*EMB], g_K_l[(long)BATCH*LCTX*EMB];
__device__ __align__(128) bf16 g_VT_h[(long)BATCH*EMB*LCTX], g_VT_l[(long)BATCH*EMB*LCTX];
__device__ __align__(128) bf16 g_P_h[(long)BATCH*HW*LCTX],  g_P_l[(long)BATCH*HW*LCTX];

// ---------------- helpers ----------------
__device__ __forceinline__ uint32_t smem_u32(const void* p) {
    uint32_t r;
    asm("{ .reg .u64 t; cvta.to.shared.u64 t, %1; cvt.u32.u64 %0, t; }" : "=r"(r) : "l"(p));
    return r;
}
__device__ __forceinline__ void mbar_init(uint32_t a, uint32_t c) {
    asm volatile("mbarrier.init.shared.b64 [%0], %1;" :: "r"(a), "r"(c) : "memory");
}
__device__ __forceinline__ void mbar_expect(uint32_t a, uint32_t bytes) {
    asm volatile("mbarrier.arrive.expect_tx.shared.b64 _, [%0], %1;" :: "r"(a), "r"(bytes) : "memory");
}
__device__ __forceinline__ void mbar_wait(uint32_t a, uint32_t par) {
    asm volatile(
        "{\n\t.reg .pred P1;\n\tW%=:\n\t"
        "mbarrier.try_wait.parity.acquire.cta.shared::cta.b64 P1, [%0], %1, 0x989680;\n\t"
        "@P1 bra D%=;\n\tbra W%=;\n\tD%=:\n\t}" :: "r"(a), "r"(par) : "memory");
}
__device__ __forceinline__ void bulk_g2s(uint32_t dst, const void* src, uint32_t bytes, uint32_t bar) {
    asm volatile("cp.async.bulk.shared::cluster.global.mbarrier::complete_tx::bytes [%0], [%1], %2, [%3];"
                 :: "r"(dst), "l"(src), "r"(bytes), "r"(bar) : "memory");
}
__device__ __forceinline__ void ldsm_x4(uint32_t (&r)[4], uint32_t addr) {
    asm volatile("ldmatrix.sync.aligned.m8n8.x4.shared.b16 {%0,%1,%2,%3}, [%4];"
                 : "=r"(r[0]), "=r"(r[1]), "=r"(r[2]), "=r"(r[3]) : "r"(addr));
}
__device__ __forceinline__ void mma16816(float (&d)[4], const uint32_t (&a)[4],
                                         uint32_t b0, uint32_t b1) {
    asm volatile(
        "mma.sync.aligned.m16n8k16.row.col.f32.bf16.bf16.f32 "
        "{%0,%1,%2,%3}, {%4,%5,%6,%7}, {%8,%9}, {%0,%1,%2,%3};"
        : "+f"(d[0]), "+f"(d[1]), "+f"(d[2]), "+f"(d[3])
        : "r"(a[0]), "r"(a[1]), "r"(a[2]), "r"(a[3]), "r"(b0), "r"(b1));
}
__device__ __forceinline__ uint32_t pack2(bf16 a, bf16 b) {
    return (uint32_t)__bfloat16_as_ushort(a) | ((uint32_t)__bfloat16_as_ushort(b) << 16);
}
// element offset (bf16 units) of (row, k) in a blocked+swizzled plane with total K = Kt
__device__ __forceinline__ long blk_off(int row, int k, int Kt) {
    long blk = (long)(row >> 7) * (Kt >> 6) + (k >> 6);
    uint32_t off = (uint32_t)((row & 127) * 128 + (k & 63) * 2);
    off ^= (off >> 3) & 0x70;
    return blk * BLK_ELEMS + (off >> 1);
}
__device__ __forceinline__ uint32_t swz_row(int r, int kbyte) {
    uint32_t o = (uint32_t)(r * 128 + kbyte);
    return o ^ ((o >> 3) & 0x70);
}

// ---------------- blocked bf16x3 GEMM, bulk-copy staging ----------------
// D[m,n] = alpha * sum_k (Ah+Al)[m,k]*(Bh+Bl)[n,k] + biasM[m] + biasN[n]
template <bool SPLIT>
__global__ void __launch_bounds__(256)
gemm_blk_kernel(const bf16* __restrict__ Ah, const bf16* __restrict__ Al, int KtA, long sA,
                const bf16* __restrict__ Bh, const bf16* __restrict__ Bl, int KtB, long sB,
                float* __restrict__ Cf, bf16* __restrict__ Ch, bf16* __restrict__ Cl,
                int ldKtC, long sC, int cOff,
                int K, float alpha, const float* __restrict__ biasM, const float* __restrict__ biasN)
{
    extern __shared__ __align__(128) char smem[];
    __shared__ __align__(8) uint64_t barsto[NSTAGE];

    const int tid = threadIdx.x, wid = tid >> 5, lane = tid & 31;
    const int b = blockIdx.z;
    const int m0 = blockIdx.y * 128, n0 = blockIdx.x * 128;
    const int wm = (wid & 3) * 32;     // warp m offset
    const int wn = (wid >> 2) * 64;    // warp n offset

    const bf16* pAh = Ah + (long)b * sA + (long)(m0 >> 7) * (KtA >> 6) * BLK_ELEMS;
    const bf16* pAl = Al + (long)b * sA + (long)(m0 >> 7) * (KtA >> 6) * BLK_ELEMS;
    const bf16* pBh = Bh + (long)b * sB + (long)(n0 >> 7) * (KtB >> 6) * BLK_ELEMS;
    const bf16* pBl = Bl + (long)b * sB + (long)(n0 >> 7) * (KtB >> 6) * BLK_ELEMS;

    const uint32_t s_base = smem_u32(smem);
    const uint32_t bar0 = smem_u32(barsto);
    const int nch = K >> 6;

    auto issue = [&](int c) {
        const int s = c % NSTAGE;
        const uint32_t sb = s_base + (uint32_t)s * STAGE_BYTES;
        const uint32_t bar = bar0 + (uint32_t)s * 8;
        mbar_expect(bar, 4 * BLK_BYTES);
        bulk_g2s(sb + 0 * BLK_BYTES, pAh + (long)c * BLK_ELEMS, BLK_BYTES, bar);
        bulk_g2s(sb + 1 * BLK_BYTES, pAl + (long)c * BLK_ELEMS, BLK_BYTES, bar);
        bulk_g2s(sb + 2 * BLK_BYTES, pBh + (long)c * BLK_ELEMS, BLK_BYTES, bar);
        bulk_g2s(sb + 3 * BLK_BYTES, pBl + (long)c * BLK_ELEMS, BLK_BYTES, bar);
    };

    if (tid == 0) {
        for (int s = 0; s < NSTAGE; s++) mbar_init(bar0 + s * 8, 1);
        asm volatile("fence.proxy.async.shared::cta;" ::: "memory");
        const int pre = nch < NSTAGE ? nch : NSTAGE;
        for (int c = 0; c < pre; c++) issue(c);
    }
    __syncthreads();

    float acc[2][8][4];
#pragma unroll
    for (int i = 0; i < 2; i++)
#pragma unroll
        for (int j = 0; j < 8; j++)
#pragma unroll
            for (int q = 0; q < 4; q++) acc[i][j][q] = 0.f;

    const int lrow = lane & 15;
    const int lkby = ((lane >> 4) * 8) * 2;      // byte offset of k sub-group

    for (int c = 0; c < nch; c++) {
        const int s = c % NSTAGE;
        mbar_wait(bar0 + s * 8, (uint32_t)((c / NSTAGE) & 1));
        const uint32_t sb = s_base + (uint32_t)s * STAGE_BYTES;

#pragma unroll
        for (int ks = 0; ks < 4; ks++) {
            const int kb = ks * 32 + lkby;       // byte col offset within 128B row
            uint32_t ah[2][4], al[2][4];
#pragma unroll
            for (int i = 0; i < 2; i++) {
                uint32_t o = swz_row(wm + i * 16 + lrow, kb);
                ldsm_x4(ah[i], sb + o);
                ldsm_x4(al[i], sb + BLK_BYTES + o);
            }
            uint32_t bh[4][4], bl[4][4];
#pragma unroll
            for (int jj = 0; jj < 4; jj++) {
                uint32_t o = swz_row(wn + jj * 16 + lrow, kb);
                ldsm_x4(bh[jj], sb + 2 * BLK_BYTES + o);
                ldsm_x4(bl[jj], sb + 3 * BLK_BYTES + o);
            }
            // term-major: no accumulator RAW chains
#pragma unroll
            for (int t = 0; t < 3; t++) {
#pragma unroll
                for (int i = 0; i < 2; i++) {
#pragma unroll
                    for (int j = 0; j < 8; j++) {
                        const int jj = j >> 1, sel = j & 1;
                        if (t == 0)
                            mma16816(acc[i][j], ah[i], bh[jj][sel], bh[jj][sel + 2]);
                        else if (t == 1)
                            mma16816(acc[i][j], ah[i], bl[jj][sel], bl[jj][sel + 2]);
                        else
                            mma16816(acc[i][j], al[i], bh[jj][sel], bh[jj][sel + 2]);
                    }
                }
            }
        }
        __syncthreads();
        if (tid == 0 && c + NSTAGE < nch) issue(c + NSTAGE);
    }

    // ---------------- epilogue ----------------
    const int mrow = m0 + wm + (lane >> 2);
    const int ncol0 = n0 + wn + 2 * (lane & 3);

#pragma unroll
    for (int i = 0; i < 2; i++) {
        const int m = mrow + i * 16;
        const float bm0 = biasM ? biasM[m] : 0.f;
        const float bm8 = biasM ? biasM[m + 8] : 0.f;
#pragma unroll
        for (int j = 0; j < 8; j++) {
            const int n = ncol0 + j * 8;
            const float bn0 = biasN ? biasN[n] : 0.f;
            const float bn1 = biasN ? biasN[n + 1] : 0.f;
            float v0 = alpha * acc[i][j][0] + bm0 + bn0;
            float v1 = alpha * acc[i][j][1] + bm0 + bn1;
            float v2 = alpha * acc[i][j][2] + bm8 + bn0;
            float v3 = alpha * acc[i][j][3] + bm8 + bn1;
            if (SPLIT) {
                bf16* ch = Ch + (long)b * sC;
                bf16* cl = Cl + (long)b * sC;
                const long o0 = blk_off(m,     n + cOff, ldKtC);
                const long o8 = blk_off(m + 8, n + cOff, ldKtC);
                bf16 h0 = __float2bfloat16(v0), h1 = __float2bfloat16(v1);
                bf16 h2 = __float2bfloat16(v2), h3 = __float2bfloat16(v3);
                *reinterpret_cast<uint32_t*>(ch + o0) = pack2(h0, h1);
                *reinterpret_cast<uint32_t*>(ch + o8) = pack2(h2, h3);
                *reinterpret_cast<uint32_t*>(cl + o0) =
                    pack2(__float2bfloat16(v0 - __bfloat162float(h0)),
                          __float2bfloat16(v1 - __bfloat162float(h1)));
                *reinterpret_cast<uint32_t*>(cl + o8) =
                    pack2(__float2bfloat16(v2 - __bfloat162float(h2)),
                          __float2bfloat16(v3 - __bfloat162float(h3)));
            } else {
                float* co = Cf + (long)b * sC;
                *reinterpret_cast<float2*>(co + (long)m * ldKtC + n) = make_float2(v0, v1);
                *reinterpret_cast<float2*>(co + (long)(m + 8) * ldKtC + n) = make_float2(v2, v3);
            }
        }
    }
}

// ---------------- aux kernels (blocked writers) ----------------
__global__ void trans_convert_kernel(const float* __restrict__ src, long sstride, int src_ld,
                                     bf16* __restrict__ dh, bf16* __restrict__ dl,
                                     long dstride, int KtD)
{
    __shared__ float t[32][33];
    const float* S = src + (long)blockIdx.z * sstride;
    bf16* DH = dh + (long)blockIdx.z * dstride;
    bf16* DL = dl + (long)blockIdx.z * dstride;
    const int c0 = blockIdx.x * 32, r0 = blockIdx.y * 32;
    const int tx = threadIdx.x, ty = threadIdx.y;
#pragma unroll
    for (int k = 0; k < 4; k++)
        t[ty + 8*k][tx] = S[(long)(r0 + ty + 8*k) * src_ld + c0 + tx];
    __syncthreads();
#pragma unroll
    for (int k = 0; k < 4; k++) {
        float x = t[tx][ty + 8*k];
        bf16 h = __float2bfloat16(x);
        long o = blk_off(c0 + ty + 8*k, r0 + tx, KtD);
        DH[o] = h;
        DL[o] = __float2bfloat16(x - __bfloat162float(h));
    }
}

__global__ void convert_split_kernel(const float* __restrict__ s,
                                     bf16* __restrict__ dh, bf16* __restrict__ dl,
                                     int Kt, int n)
{
    int i = blockIdx.x * blockDim.x + threadIdx.x;
    if (i >= n) return;
    float x = s[i];
    bf16 h = __float2bfloat16(x);
    long o = blk_off(i / Kt, i % Kt, Kt);
    dh[o] = h;
    dl[o] = __float2bfloat16(x - __bfloat162float(h));
}

__global__ void fold_bias_kernel(const float* __restrict__ pib, const float* __restrict__ wq,
                                 const float* __restrict__ wqb, float* __restrict__ out)
{
    int f = blockIdx.x * blockDim.x + threadIdx.x;
    if (f >= EMB) return;
    float s = wqb[f];
    for (int e = 0; e < EMB; e++) s = fmaf(pib[e], wq[e * EMB + f], s);
    out[f] = s;
}

__global__ void __launch_bounds__(256) softmax_split_kernel(const float* __restrict__ S,
                                                            bf16* __restrict__ Ph,
                                                            bf16* __restrict__ Pl)
{
    const float* row = S + (long)blockIdx.x * LCTX;
    const int t = threadIdx.x;
    float v[4], mx = -INFINITY;
#pragma unroll
    for (int j = 0; j < 4; j++) { v[j] = row[t + j*256]; mx = fmaxf(mx, v[j]); }
    __shared__ float red[256];
    red[t] = mx; __syncthreads();
    for (int s = 128; s > 0; s >>= 1) { if (t < s) red[t] = fmaxf(red[t], red[t+s]); __syncthreads(); }
    mx = red[0]; __syncthreads();
    float sum = 0.f;
#pragma unroll
    for (int j = 0; j < 4; j++) { v[j] = __expf(v[j] - mx); sum += v[j]; }
    red[t] = sum; __syncthreads();
    for (int s = 128; s > 0; s >>= 1) { if (t < s) red[t] += red[t+s]; __syncthreads(); }
    const float inv = 1.f / red[0];
    const int b = blockIdx.x >> 12;
    const int p = blockIdx.x & 4095;
    const long base = (long)b * ((long)HW * LCTX);
#pragma unroll
    for (int j = 0; j < 4; j++) {
        float pr = v[j] * inv;
        bf16 h = __float2bfloat16(pr);
        long o = base + blk_off(p, t + j*256, LCTX);
        Ph[o] = h;
        Pl[o] = __float2bfloat16(pr - __bfloat162float(h));
    }
}

// ---------------- launch ----------------
extern "C" void kernel_launch(void* const* d_in, const int* in_sizes, int n_in,
                              void* d_out, int out_size)
{
    const float* input      = (const float*)d_in[0];
    const float* context    = (const float*)d_in[1];
    const float* proj_in_w  = (const float*)d_in[2];
    const float* proj_in_b  = (const float*)d_in[3];
    const float* wq_w       = (const float*)d_in[4];
    const float* wq_b       = (const float*)d_in[5];
    const float* wk_w       = (const float*)d_in[6];
    const float* wk_b       = (const float*)d_in[7];
    const float* wv_w       = (const float*)d_in[8];
    const float* wv_b       = (const float*)d_in[9];
    const float* proj_out_w = (const float*)d_in[10];
    const float* proj_out_b = (const float*)d_in[11];
    float* out = (float*)d_out;

    cudaFuncSetAttribute(gemm_blk_kernel<true>,  cudaFuncAttributeMaxDynamicSharedMemorySize, GEMM_SMEM);
    cudaFuncSetAttribute(gemm_blk_kernel<false>, cudaFuncAttributeMaxDynamicSharedMemorySize, GEMM_SMEM);

    float *bq, *S;
    bf16 *wqT0h,*wqT0l,*piTh,*piTl,*WqTh,*WqTl,*wkTh,*wkTl,*wvTh,*wvTl,*poh,*pol;
    bf16 *Zh,*Zl,*cth,*ctl,*Qh,*Ql,*Kh,*Kl,*VTh,*VTl,*Ph,*Pl;
    cudaGetSymbolAddress((void**)&bq, g_bq);         cudaGetSymbolAddress((void**)&S, g_S);
    cudaGetSymbolAddress((void**)&wqT0h, g_wqT0_h);  cudaGetSymbolAddress((void**)&wqT0l, g_wqT0_l);
    cudaGetSymbolAddress((void**)&piTh, g_piT_h);    cudaGetSymbolAddress((void**)&piTl, g_piT_l);
    cudaGetSymbolAddress((void**)&WqTh, g_WqT_h);    cudaGetSymbolAddress((void**)&WqTl, g_WqT_l);
    cudaGetSymbolAddress((void**)&wkTh, g_wkT_h);    cudaGetSymbolAddress((void**)&wkTl, g_wkT_l);
    cudaGetSymbolAddress((void**)&wvTh, g_wvT_h);    cudaGetSymbolAddress((void**)&wvTl, g_wvT_l);
    cudaGetSymbolAddress((void**)&poh, g_po_h);      cudaGetSymbolAddress((void**)&pol, g_po_l);
    cudaGetSymbolAddress((void**)&Zh, g_Z_h);        cudaGetSymbolAddress((void**)&Zl, g_Z_l);
    cudaGetSymbolAddress((void**)&cth, g_ctxT_h);    cudaGetSymbolAddress((void**)&ctl, g_ctxT_l);
    cudaGetSymbolAddress((void**)&Qh, g_Q_h);        cudaGetSymbolAddress((void**)&Ql, g_Q_l);
    cudaGetSymbolAddress((void**)&Kh, g_K_h);        cudaGetSymbolAddress((void**)&Kl, g_K_l);
    cudaGetSymbolAddress((void**)&VTh, g_VT_h);      cudaGetSymbolAddress((void**)&VTl, g_VT_l);
    cudaGetSymbolAddress((void**)&Ph, g_P_h);        cudaGetSymbolAddress((void**)&Pl, g_P_l);

    const float scale = 1.0f / sqrtf((float)EMB);
    dim3 tb(32, 8);

    // weight prep (blocked outputs)
    fold_bias_kernel<<<2, 256>>>(proj_in_b, wq_w, wq_b, bq);
    trans_convert_kernel<<<dim3(16,16,1), tb>>>(wq_w, 0, EMB, wqT0h, wqT0l, 0, EMB);
    trans_convert_kernel<<<dim3(16,16,1), tb>>>(proj_in_w, 0, EMB, piTh, piTl, 0, EMB);
    trans_convert_kernel<<<dim3(16,16,1), tb>>>(wk_w, 0, EMB, wkTh, wkTl, 0, EMB);
    trans_convert_kernel<<<dim3(16,16,1), tb>>>(wv_w, 0, EMB, wvTh, wvTl, 0, EMB);
    convert_split_kernel<<<(EMB*2*EMB)/256, 256>>>(proj_out_w, poh, pol, 2*EMB, EMB*2*EMB);
    trans_convert_kernel<<<dim3(32,16,BATCH), tb>>>(context, (long)EMB*LCTX, LCTX,
                                                    cth, ctl, (long)LCTX*EMB, EMB);
    trans_convert_kernel<<<dim3(128,16,BATCH), tb>>>(input, (long)EMB*HW, HW,
                                                     Zh, Zl, (long)HW*2*EMB, 2*EMB);

    // 1) WqT[f][c] = wqT0 · piT^T
    gemm_blk_kernel<true><<<dim3(4,4,1), 256, GEMM_SMEM>>>(
        wqT0h, wqT0l, EMB, 0, piTh, piTl, EMB, 0,
        nullptr, WqTh, WqTl, EMB, 0, 0, EMB, 1.0f, nullptr, nullptr);
    // 2) K[l][f] = ctxT · wkT^T + wk_b
    gemm_blk_kernel<true><<<dim3(4,8,BATCH), 256, GEMM_SMEM>>>(
        cth, ctl, EMB, (long)LCTX*EMB, wkTh, wkTl, EMB, 0,
        nullptr, Kh, Kl, EMB, (long)LCTX*EMB, 0, EMB, 1.0f, nullptr, wk_b);
    // 3) VT[e][l] = wvT · ctxT^T + wv_b[e]
    gemm_blk_kernel<true><<<dim3(8,4,BATCH), 256, GEMM_SMEM>>>(
        wvTh, wvTl, EMB, 0, cth, ctl, EMB, (long)LCTX*EMB,
        nullptr, VTh, VTl, LCTX, (long)EMB*LCTX, 0, EMB, 1.0f, wv_b, nullptr);
    // 4) Q[p][f] = Z[:, :512] · WqT^T + bq   (A KtA=1024, loop K=512 -> kblks 0..7)
    gemm_blk_kernel<true><<<dim3(4,32,BATCH), 256, GEMM_SMEM>>>(
        Zh, Zl, 2*EMB, (long)HW*2*EMB, WqTh, WqTl, EMB, 0,
        nullptr, Qh, Ql, EMB, (long)HW*EMB, 0, EMB, 1.0f, nullptr, bq);
    // 5) S[p][l] = scale * Q · K^T (fp32 linear)
    gemm_blk_kernel<false><<<dim3(8,32,BATCH), 256, GEMM_SMEM>>>(
        Qh, Ql, EMB, (long)HW*EMB, Kh, Kl, EMB, (long)LCTX*EMB,
        S, nullptr, nullptr, LCTX, (long)HW*LCTX, 0, EMB, scale, nullptr, nullptr);
    // 6) softmax + split (blocked P)
    softmax_split_kernel<<<BATCH*HW, 256>>>(S, Ph, Pl);
    // 7) O[p][e] = P · VT^T  -> Z k-cols [512,1024)
    gemm_blk_kernel<true><<<dim3(4,32,BATCH), 256, GEMM_SMEM>>>(
        Ph, Pl, LCTX, (long)HW*LCTX, VTh, VTl, LCTX, (long)EMB*LCTX,
        nullptr, Zh, Zl, 2*EMB, (long)HW*2*EMB, EMB, LCTX, 1.0f, nullptr, nullptr);
    // 8) out[o][p] = po · Z^T + proj_out_b[o] (fp32 linear)
    gemm_blk_kernel<false><<<dim3(32,4,BATCH), 256, GEMM_SMEM>>>(
        poh, pol, 2*EMB, 0, Zh, Zl, 2*EMB, (long)HW*2*EMB,
        out, nullptr, nullptr, HW, (long)EMB*HW, 0, 2*EMB, 1.0f, proj_out_b, nullptr);
}

// round 7
// speedup vs baseline: 5.5751x; 1.7531x over previous
#include <cuda_runtime.h>
#include <cuda_fp16.h>
#include <math.h>
#include <stdint.h>

#define BATCH 8
#define HW    4096
#define LCTX  1024
#define EMB   512

typedef __half h16;

// blocked layout: [rowblk][kblk][128x64 swizzled]; 16KB per block
#define BLK_ELEMS 8192
#define BLK_BYTES 16384
#define NSTAGE 3

// ---------------- device scratch ----------------
__device__ __align__(128) float g_bq[EMB];
__device__ __align__(128) float g_S[(long)BATCH * HW * LCTX];

__device__ __align__(128) h16 g_wqT0_h[EMB*EMB], g_wqT0_l[EMB*EMB];   // wq^T [f][e]
__device__ __align__(128) h16 g_piT_h [EMB*EMB], g_piT_l [EMB*EMB];   // pi^T [c][e]
__device__ __align__(128) h16 g_WqT_h [EMB*EMB], g_WqT_l [EMB*EMB];   // folded [f][c]
__device__ __align__(128) h16 g_wkT_h [EMB*EMB], g_wkT_l [EMB*EMB];   // [f][c]
__device__ __align__(128) h16 g_wvT_h [EMB*EMB], g_wvT_l [EMB*EMB];   // [e][c]
__device__ __align__(128) h16 g_po_h[EMB*2*EMB];                       // [o][k] h only

__device__ __align__(128) h16 g_Z_h[(long)BATCH*HW*2*EMB], g_Z_l[(long)BATCH*HW*2*EMB];
__device__ __align__(128) h16 g_ctxT_h[(long)BATCH*LCTX*EMB], g_ctxT_l[(long)BATCH*LCTX*EMB];
__device__ __align__(128) h16 g_Q_h[(long)BATCH*HW*EMB];
__device__ __align__(128) h16 g_K_h[(long)BATCH*LCTX*EMB];
__device__ __align__(128) h16 g_VT_h[(long)BATCH*EMB*LCTX];
__device__ __align__(128) h16 g_P_h[(long)BATCH*HW*LCTX];

// ---------------- helpers ----------------
__device__ __forceinline__ uint32_t smem_u32(const void* p) {
    uint32_t r;
    asm("{ .reg .u64 t; cvta.to.shared.u64 t, %1; cvt.u32.u64 %0, t; }" : "=r"(r) : "l"(p));
    return r;
}
__device__ __forceinline__ void mbar_init(uint32_t a, uint32_t c) {
    asm volatile("mbarrier.init.shared.b64 [%0], %1;" :: "r"(a), "r"(c) : "memory");
}
__device__ __forceinline__ void mbar_expect(uint32_t a, uint32_t bytes) {
    asm volatile("mbarrier.arrive.expect_tx.shared.b64 _, [%0], %1;" :: "r"(a), "r"(bytes) : "memory");
}
__device__ __forceinline__ void mbar_wait(uint32_t a, uint32_t par) {
    asm volatile(
        "{\n\t.reg .pred P1;\n\tW%=:\n\t"
        "mbarrier.try_wait.parity.acquire.cta.shared::cta.b64 P1, [%0], %1, 0x989680;\n\t"
        "@P1 bra D%=;\n\tbra W%=;\n\tD%=:\n\t}" :: "r"(a), "r"(par) : "memory");
}
__device__ __forceinline__ void bulk_g2s(uint32_t dst, const void* src, uint32_t bytes, uint32_t bar) {
    asm volatile("cp.async.bulk.shared::cluster.global.mbarrier::complete_tx::bytes [%0], [%1], %2, [%3];"
                 :: "r"(dst), "l"(src), "r"(bytes), "r"(bar) : "memory");
}
__device__ __forceinline__ void ldsm_x4(uint32_t (&r)[4], uint32_t addr) {
    asm volatile("ldmatrix.sync.aligned.m8n8.x4.shared.b16 {%0,%1,%2,%3}, [%4];"
                 : "=r"(r[0]), "=r"(r[1]), "=r"(r[2]), "=r"(r[3]) : "r"(addr));
}
__device__ __forceinline__ void mma16816(float (&d)[4], const uint32_t (&a)[4],
                                         uint32_t b0, uint32_t b1) {
    asm volatile(
        "mma.sync.aligned.m16n8k16.row.col.f32.f16.f16.f32 "
        "{%0,%1,%2,%3}, {%4,%5,%6,%7}, {%8,%9}, {%0,%1,%2,%3};"
        : "+f"(d[0]), "+f"(d[1]), "+f"(d[2]), "+f"(d[3])
        : "r"(a[0]), "r"(a[1]), "r"(a[2]), "r"(a[3]), "r"(b0), "r"(b1));
}
__device__ __forceinline__ uint32_t pack2(h16 a, h16 b) {
    return (uint32_t)__half_as_ushort(a) | ((uint32_t)__half_as_ushort(b) << 16);
}
// element offset of (row, k) in blocked+swizzled plane with total K = Kt
__device__ __forceinline__ long blk_off(int row, int k, int Kt) {
    long blk = (long)(row >> 7) * (Kt >> 6) + (k >> 6);
    uint32_t off = (uint32_t)((row & 127) * 128 + (k & 63) * 2);
    off ^= (off >> 3) & 0x70;
    return blk * BLK_ELEMS + (off >> 1);
}
__device__ __forceinline__ uint32_t swz_row(int r, int kbyte) {
    uint32_t o = (uint32_t)(r * 128 + kbyte);
    return o ^ ((o >> 3) & 0x70);
}

// ---------------- blocked fp16 GEMM (NT=1 or 3 emulation terms) ----------------
// D[m,n] = alpha * sum_k A[m,k]*B[n,k] + biasM[m] + biasN[n]
// OUT: 0 = fp32 linear, 1 = h-plane blocked, 2 = h+l planes blocked
template <int OUT, int NT>
__global__ void __launch_bounds__(256)
gemm_blk(const h16* __restrict__ Ah, const h16* __restrict__ Al, int KtA, long sA,
         const h16* __restrict__ Bh, const h16* __restrict__ Bl, int KtB, long sB,
         float* __restrict__ Cf, h16* __restrict__ Ch, h16* __restrict__ Cl,
         int ldKtC, long sC, int cOff,
         int K, float alpha, const float* __restrict__ biasM, const float* __restrict__ biasN)
{
    constexpr int NBLK = (NT == 3) ? 4 : 2;
    constexpr uint32_t STAGE = NBLK * BLK_BYTES;

    extern __shared__ __align__(128) char smem[];
    __shared__ __align__(8) uint64_t barsto[NSTAGE];

    const int tid = threadIdx.x, wid = tid >> 5, lane = tid & 31;
    const int b = blockIdx.z;
    const int m0 = blockIdx.y * 128, n0 = blockIdx.x * 128;
    const int wm = (wid & 3) * 32;
    const int wn = (wid >> 2) * 64;

    const h16* pAh = Ah + (long)b * sA + (long)(m0 >> 7) * (KtA >> 6) * BLK_ELEMS;
    const h16* pBh = Bh + (long)b * sB + (long)(n0 >> 7) * (KtB >> 6) * BLK_ELEMS;
    const h16* pAl = (NT == 3) ? Al + (long)b * sA + (long)(m0 >> 7) * (KtA >> 6) * BLK_ELEMS : nullptr;
    const h16* pBl = (NT == 3) ? Bl + (long)b * sB + (long)(n0 >> 7) * (KtB >> 6) * BLK_ELEMS : nullptr;

    const uint32_t s_base = smem_u32(smem);
    const uint32_t bar0 = smem_u32(barsto);
    const int nch = K >> 6;

    auto issue = [&](int c) {
        const int s = c % NSTAGE;
        const uint32_t sb = s_base + (uint32_t)s * STAGE;
        const uint32_t bar = bar0 + (uint32_t)s * 8;
        mbar_expect(bar, NBLK * BLK_BYTES);
        if (NT == 3) {
            bulk_g2s(sb + 0 * BLK_BYTES, pAh + (long)c * BLK_ELEMS, BLK_BYTES, bar);
            bulk_g2s(sb + 1 * BLK_BYTES, pAl + (long)c * BLK_ELEMS, BLK_BYTES, bar);
            bulk_g2s(sb + 2 * BLK_BYTES, pBh + (long)c * BLK_ELEMS, BLK_BYTES, bar);
            bulk_g2s(sb + 3 * BLK_BYTES, pBl + (long)c * BLK_ELEMS, BLK_BYTES, bar);
        } else {
            bulk_g2s(sb + 0 * BLK_BYTES, pAh + (long)c * BLK_ELEMS, BLK_BYTES, bar);
            bulk_g2s(sb + 1 * BLK_BYTES, pBh + (long)c * BLK_ELEMS, BLK_BYTES, bar);
        }
    };

    if (tid == 0) {
        for (int s = 0; s < NSTAGE; s++) mbar_init(bar0 + s * 8, 1);
        asm volatile("fence.proxy.async.shared::cta;" ::: "memory");
        const int pre = nch < NSTAGE ? nch : NSTAGE;
        for (int c = 0; c < pre; c++) issue(c);
    }
    __syncthreads();

    float acc[2][8][4];
#pragma unroll
    for (int i = 0; i < 2; i++)
#pragma unroll
        for (int j = 0; j < 8; j++)
#pragma unroll
            for (int q = 0; q < 4; q++) acc[i][j][q] = 0.f;

    const int lrow = lane & 15;
    const int lkby = ((lane >> 4) * 8) * 2;
    const uint32_t boff = (NT == 3) ? 2 * BLK_BYTES : 1 * BLK_BYTES;

    for (int c = 0; c < nch; c++) {
        const int s = c % NSTAGE;
        mbar_wait(bar0 + s * 8, (uint32_t)((c / NSTAGE) & 1));
        const uint32_t sb = s_base + (uint32_t)s * STAGE;

#pragma unroll
        for (int ks = 0; ks < 4; ks++) {
            const int kb = ks * 32 + lkby;
            uint32_t ah[2][4], al[2][4];
#pragma unroll
            for (int i = 0; i < 2; i++) {
                uint32_t o = swz_row(wm + i * 16 + lrow, kb);
                ldsm_x4(ah[i], sb + o);
                if (NT == 3) ldsm_x4(al[i], sb + BLK_BYTES + o);
            }
            uint32_t bh[4][4], bl[4][4];
#pragma unroll
            for (int jj = 0; jj < 4; jj++) {
                uint32_t o = swz_row(wn + jj * 16 + lrow, kb);
                ldsm_x4(bh[jj], sb + boff + o);
                if (NT == 3) ldsm_x4(bl[jj], sb + 3 * BLK_BYTES + o);
            }
#pragma unroll
            for (int t = 0; t < NT; t++) {
#pragma unroll
                for (int i = 0; i < 2; i++) {
#pragma unroll
                    for (int j = 0; j < 8; j++) {
                        const int jj = j >> 1, sel = j & 1;
                        if (t == 0)
                            mma16816(acc[i][j], ah[i], bh[jj][sel], bh[jj][sel + 2]);
                        else if (t == 1)
                            mma16816(acc[i][j], ah[i], bl[jj][sel], bl[jj][sel + 2]);
                        else
                            mma16816(acc[i][j], al[i], bh[jj][sel], bh[jj][sel + 2]);
                    }
                }
            }
        }
        __syncthreads();
        if (tid == 0 && c + NSTAGE < nch) issue(c + NSTAGE);
    }

    // ---------------- epilogue ----------------
    const int mrow = m0 + wm + (lane >> 2);
    const int ncol0 = n0 + wn + 2 * (lane & 3);

#pragma unroll
    for (int i = 0; i < 2; i++) {
        const int m = mrow + i * 16;
        const float bm0 = biasM ? biasM[m] : 0.f;
        const float bm8 = biasM ? biasM[m + 8] : 0.f;
#pragma unroll
        for (int j = 0; j < 8; j++) {
            const int n = ncol0 + j * 8;
            const float bn0 = biasN ? biasN[n] : 0.f;
            const float bn1 = biasN ? biasN[n + 1] : 0.f;
            float v0 = alpha * acc[i][j][0] + bm0 + bn0;
            float v1 = alpha * acc[i][j][1] + bm0 + bn1;
            float v2 = alpha * acc[i][j][2] + bm8 + bn0;
            float v3 = alpha * acc[i][j][3] + bm8 + bn1;
            if (OUT == 0) {
                float* co = Cf + (long)b * sC;
                *reinterpret_cast<float2*>(co + (long)m * ldKtC + n) = make_float2(v0, v1);
                *reinterpret_cast<float2*>(co + (long)(m + 8) * ldKtC + n) = make_float2(v2, v3);
            } else {
                h16* ch = Ch + (long)b * sC;
                const long o0 = blk_off(m,     n + cOff, ldKtC);
                const long o8 = blk_off(m + 8, n + cOff, ldKtC);
                h16 h0 = __float2half_rn(v0), h1 = __float2half_rn(v1);
                h16 h2 = __float2half_rn(v2), h3 = __float2half_rn(v3);
                *reinterpret_cast<uint32_t*>(ch + o0) = pack2(h0, h1);
                *reinterpret_cast<uint32_t*>(ch + o8) = pack2(h2, h3);
                if (OUT == 2) {
                    h16* cl = Cl + (long)b * sC;
                    *reinterpret_cast<uint32_t*>(cl + o0) =
                        pack2(__float2half_rn(v0 - __half2float(h0)),
                              __float2half_rn(v1 - __half2float(h1)));
                    *reinterpret_cast<uint32_t*>(cl + o8) =
                        pack2(__float2half_rn(v2 - __half2float(h2)),
                              __float2half_rn(v3 - __half2float(h3)));
                }
            }
        }
    }
}

// ---------------- aux kernels ----------------
__global__ void trans_convert_kernel(const float* __restrict__ src, long sstride, int src_ld,
                                     h16* __restrict__ dh, h16* __restrict__ dl,
                                     long dstride, int KtD)
{
    __shared__ float t[32][33];
    const float* S = src + (long)blockIdx.z * sstride;
    h16* DH = dh + (long)blockIdx.z * dstride;
    h16* DL = dl ? dl + (long)blockIdx.z * dstride : nullptr;
    const int c0 = blockIdx.x * 32, r0 = blockIdx.y * 32;
    const int tx = threadIdx.x, ty = threadIdx.y;
#pragma unroll
    for (int k = 0; k < 4; k++)
        t[ty + 8*k][tx] = S[(long)(r0 + ty + 8*k) * src_ld + c0 + tx];
    __syncthreads();
#pragma unroll
    for (int k = 0; k < 4; k++) {
        float x = t[tx][ty + 8*k];
        h16 h = __float2half_rn(x);
        long o = blk_off(c0 + ty + 8*k, r0 + tx, KtD);
        DH[o] = h;
        if (DL) DL[o] = __float2half_rn(x - __half2float(h));
    }
}

__global__ void convert_h_kernel(const float* __restrict__ s, h16* __restrict__ dh,
                                 int Kt, int n)
{
    int i = blockIdx.x * blockDim.x + threadIdx.x;
    if (i >= n) return;
    dh[blk_off(i / Kt, i % Kt, Kt)] = __float2half_rn(s[i]);
}

__global__ void fold_bias_kernel(const float* __restrict__ pib, const float* __restrict__ wq,
                                 const float* __restrict__ wqb, float* __restrict__ out)
{
    int f = blockIdx.x * blockDim.x + threadIdx.x;
    if (f >= EMB) return;
    float s = wqb[f];
    for (int e = 0; e < EMB; e++) s = fmaf(pib[e], wq[e * EMB + f], s);
    out[f] = s;
}

__global__ void __launch_bounds__(256) softmax_h_kernel(const float* __restrict__ S,
                                                        h16* __restrict__ Ph)
{
    const float* row = S + (long)blockIdx.x * LCTX;
    const int t = threadIdx.x;
    float v[4], mx = -INFINITY;
#pragma unroll
    for (int j = 0; j < 4; j++) { v[j] = row[t + j*256]; mx = fmaxf(mx, v[j]); }
    __shared__ float red[256];
    red[t] = mx; __syncthreads();
    for (int s = 128; s > 0; s >>= 1) { if (t < s) red[t] = fmaxf(red[t], red[t+s]); __syncthreads(); }
    mx = red[0]; __syncthreads();
    float sum = 0.f;
#pragma unroll
    for (int j = 0; j < 4; j++) { v[j] = __expf(v[j] - mx); sum += v[j]; }
    red[t] = sum; __syncthreads();
    for (int s = 128; s > 0; s >>= 1) { if (t < s) red[t] += red[t+s]; __syncthreads(); }
    const float inv = 1.f / red[0];
    const int b = blockIdx.x >> 12;
    const int p = blockIdx.x & 4095;
    const long base = (long)b * ((long)HW * LCTX);
#pragma unroll
    for (int j = 0; j < 4; j++)
        Ph[base + blk_off(p, t + j*256, LCTX)] = __float2half_rn(v[j] * inv);
}

// ---------------- launch ----------------
extern "C" void kernel_launch(void* const* d_in, const int* in_sizes, int n_in,
                              void* d_out, int out_size)
{
    const float* input      = (const float*)d_in[0];
    const float* context    = (const float*)d_in[1];
    const float* proj_in_w  = (const float*)d_in[2];
    const float* proj_in_b  = (const float*)d_in[3];
    const float* wq_w       = (const float*)d_in[4];
    const float* wq_b       = (const float*)d_in[5];
    const float* wk_w       = (const float*)d_in[6];
    const float* wk_b       = (const float*)d_in[7];
    const float* wv_w       = (const float*)d_in[8];
    const float* wv_b       = (const float*)d_in[9];
    const float* proj_out_w = (const float*)d_in[10];
    const float* proj_out_b = (const float*)d_in[11];
    float* out = (float*)d_out;

    const int SMEM3 = NSTAGE * 4 * BLK_BYTES;   // 196608
    const int SMEM1 = NSTAGE * 2 * BLK_BYTES;   // 98304
    cudaFuncSetAttribute(gemm_blk<2,3>, cudaFuncAttributeMaxDynamicSharedMemorySize, SMEM3);
    cudaFuncSetAttribute(gemm_blk<1,3>, cudaFuncAttributeMaxDynamicSharedMemorySize, SMEM3);
    cudaFuncSetAttribute(gemm_blk<0,1>, cudaFuncAttributeMaxDynamicSharedMemorySize, SMEM1);
    cudaFuncSetAttribute(gemm_blk<1,1>, cudaFuncAttributeMaxDynamicSharedMemorySize, SMEM1);

    float *bq, *S;
    h16 *wqT0h,*wqT0l,*piTh,*piTl,*WqTh,*WqTl,*wkTh,*wkTl,*wvTh,*wvTl,*poh;
    h16 *Zh,*Zl,*cth,*ctl,*Qh,*Kh,*VTh,*Ph;
    cudaGetSymbolAddress((void**)&bq, g_bq);         cudaGetSymbolAddress((void**)&S, g_S);
    cudaGetSymbolAddress((void**)&wqT0h, g_wqT0_h);  cudaGetSymbolAddress((void**)&wqT0l, g_wqT0_l);
    cudaGetSymbolAddress((void**)&piTh, g_piT_h);    cudaGetSymbolAddress((void**)&piTl, g_piT_l);
    cudaGetSymbolAddress((void**)&WqTh, g_WqT_h);    cudaGetSymbolAddress((void**)&WqTl, g_WqT_l);
    cudaGetSymbolAddress((void**)&wkTh, g_wkT_h);    cudaGetSymbolAddress((void**)&wkTl, g_wkT_l);
    cudaGetSymbolAddress((void**)&wvTh, g_wvT_h);    cudaGetSymbolAddress((void**)&wvTl, g_wvT_l);
    cudaGetSymbolAddress((void**)&poh, g_po_h);
    cudaGetSymbolAddress((void**)&Zh, g_Z_h);        cudaGetSymbolAddress((void**)&Zl, g_Z_l);
    cudaGetSymbolAddress((void**)&cth, g_ctxT_h);    cudaGetSymbolAddress((void**)&ctl, g_ctxT_l);
    cudaGetSymbolAddress((void**)&Qh, g_Q_h);        cudaGetSymbolAddress((void**)&Kh, g_K_h);
    cudaGetSymbolAddress((void**)&VTh, g_VT_h);      cudaGetSymbolAddress((void**)&Ph, g_P_h);

    const float scale = 1.0f / sqrtf((float)EMB);
    dim3 tb(32, 8);

    // weight prep
    fold_bias_kernel<<<2, 256>>>(proj_in_b, wq_w, wq_b, bq);
    trans_convert_kernel<<<dim3(16,16,1), tb>>>(wq_w, 0, EMB, wqT0h, wqT0l, 0, EMB);
    trans_convert_kernel<<<dim3(16,16,1), tb>>>(proj_in_w, 0, EMB, piTh, piTl, 0, EMB);
    trans_convert_kernel<<<dim3(16,16,1), tb>>>(wk_w, 0, EMB, wkTh, wkTl, 0, EMB);
    trans_convert_kernel<<<dim3(16,16,1), tb>>>(wv_w, 0, EMB, wvTh, wvTl, 0, EMB);
    convert_h_kernel<<<(EMB*2*EMB)/256, 256>>>(proj_out_w, poh, 2*EMB, EMB*2*EMB);
    trans_convert_kernel<<<dim3(32,16,BATCH), tb>>>(context, (long)EMB*LCTX, LCTX,
                                                    cth, ctl, (long)LCTX*EMB, EMB);
    trans_convert_kernel<<<dim3(128,16,BATCH), tb>>>(input, (long)EMB*HW, HW,
                                                     Zh, Zl, (long)HW*2*EMB, 2*EMB);

    // 1) WqT = wqT0 · piT^T   (3-term, h+l out)
    gemm_blk<2,3><<<dim3(4,4,1), 256, SMEM3>>>(
        wqT0h, wqT0l, EMB, 0, piTh, piTl, EMB, 0,
        nullptr, WqTh, WqTl, EMB, 0, 0, EMB, 1.0f, nullptr, nullptr);
    // 2) K[l][f] = ctxT · wkT^T + wk_b   (3-term, h out)
    gemm_blk<1,3><<<dim3(4,8,BATCH), 256, SMEM3>>>(
        cth, ctl, EMB, (long)LCTX*EMB, wkTh, wkTl, EMB, 0,
        nullptr, Kh, nullptr, EMB, (long)LCTX*EMB, 0, EMB, 1.0f, nullptr, wk_b);
    // 3) VT[e][l] = wvT · ctxT^T + wv_b[e]   (3-term, h out)
    gemm_blk<1,3><<<dim3(8,4,BATCH), 256, SMEM3>>>(
        wvTh, wvTl, EMB, 0, cth, ctl, EMB, (long)LCTX*EMB,
        nullptr, VTh, nullptr, LCTX, (long)EMB*LCTX, 0, EMB, 1.0f, wv_b, nullptr);
    // 4) Q[p][f] = Z[:, :512] · WqT^T + bq   (3-term, h out)
    gemm_blk<1,3><<<dim3(4,32,BATCH), 256, SMEM3>>>(
        Zh, Zl, 2*EMB, (long)HW*2*EMB, WqTh, WqTl, EMB, 0,
        nullptr, Qh, nullptr, EMB, (long)HW*EMB, 0, EMB, 1.0f, nullptr, bq);
    // 5) S = scale * Q · K^T   (1-term, fp32 out)
    gemm_blk<0,1><<<dim3(8,32,BATCH), 256, SMEM1>>>(
        Qh, nullptr, EMB, (long)HW*EMB, Kh, nullptr, EMB, (long)LCTX*EMB,
        S, nullptr, nullptr, LCTX, (long)HW*LCTX, 0, EMB, scale, nullptr, nullptr);
    // 6) softmax -> Ph
    softmax_h_kernel<<<BATCH*HW, 256>>>(S, Ph);
    // 7) O = P · VT^T -> Z k-cols [512,1024)   (1-term, h out)
    gemm_blk<1,1><<<dim3(4,32,BATCH), 256, SMEM1>>>(
        Ph, nullptr, LCTX, (long)HW*LCTX, VTh, nullptr, LCTX, (long)EMB*LCTX,
        nullptr, Zh, nullptr, 2*EMB, (long)HW*2*EMB, EMB, LCTX, 1.0f, nullptr, nullptr);
    // 8) out = po · Z^T + proj_out_b   (1-term, fp32 out)
    gemm_blk<0,1><<<dim3(32,4,BATCH), 256, SMEM1>>>(
        poh, nullptr, 2*EMB, 0, Zh, nullptr, 2*EMB, (long)HW*2*EMB,
        out, nullptr, nullptr, HW, (long)EMB*HW, 0, 2*EMB, 1.0f, proj_out_b, nullptr);
}

// round 8
// speedup vs baseline: 7.0374x; 1.2623x over previous
#include <cuda_runtime.h>
#include <cuda_fp16.h>
#include <math.h>
#include <stdint.h>

#define BATCH 8
#define HW    4096
#define LCTX  1024
#define EMB   512

typedef __half h16;

// blocked layout: [rowblk][kblk][128x64 swizzled]; 16KB per block
#define BLK_ELEMS 8192
#define BLK_BYTES 16384
#define NSTAGE 3

// ---------------- device scratch ----------------
__device__ __align__(128) float g_bq[EMB];
__device__ __align__(128) float g_S[(long)BATCH * HW * LCTX];

__device__ __align__(128) h16 g_wqT0_h[EMB*EMB], g_wqT0_l[EMB*EMB];   // wq^T [f][e] (fold in)
__device__ __align__(128) h16 g_piT_h [EMB*EMB], g_piT_l [EMB*EMB];   // pi^T [c][e] (fold in)
__device__ __align__(128) h16 g_WqT_h [EMB*EMB];                      // folded [f][c]
__device__ __align__(128) h16 g_wkT_h [EMB*EMB];                      // [f][c]
__device__ __align__(128) h16 g_wvT_h [EMB*EMB];                      // [e][c]
__device__ __align__(128) h16 g_po_h[EMB*2*EMB];                      // [o][k]

__device__ __align__(128) h16 g_Z_h[(long)BATCH*HW*2*EMB];            // [b][p][k]
__device__ __align__(128) h16 g_ctxT_h[(long)BATCH*LCTX*EMB];         // [b][l][c]
__device__ __align__(128) h16 g_Q_h[(long)BATCH*HW*EMB];
__device__ __align__(128) h16 g_K_h[(long)BATCH*LCTX*EMB];
__device__ __align__(128) h16 g_VT_h[(long)BATCH*EMB*LCTX];
__device__ __align__(128) h16 g_P_h[(long)BATCH*HW*LCTX];

// ---------------- helpers ----------------
__device__ __forceinline__ uint32_t smem_u32(const void* p) {
    uint32_t r;
    asm("{ .reg .u64 t; cvta.to.shared.u64 t, %1; cvt.u32.u64 %0, t; }" : "=r"(r) : "l"(p));
    return r;
}
__device__ __forceinline__ void mbar_init(uint32_t a, uint32_t c) {
    asm volatile("mbarrier.init.shared.b64 [%0], %1;" :: "r"(a), "r"(c) : "memory");
}
__device__ __forceinline__ void mbar_expect(uint32_t a, uint32_t bytes) {
    asm volatile("mbarrier.arrive.expect_tx.shared.b64 _, [%0], %1;" :: "r"(a), "r"(bytes) : "memory");
}
__device__ __forceinline__ void mbar_wait(uint32_t a, uint32_t par) {
    asm volatile(
        "{\n\t.reg .pred P1;\n\tW%=:\n\t"
        "mbarrier.try_wait.parity.acquire.cta.shared::cta.b64 P1, [%0], %1, 0x989680;\n\t"
        "@P1 bra D%=;\n\tbra W%=;\n\tD%=:\n\t}" :: "r"(a), "r"(par) : "memory");
}
__device__ __forceinline__ void bulk_g2s(uint32_t dst, const void* src, uint32_t bytes, uint32_t bar) {
    asm volatile("cp.async.bulk.shared::cluster.global.mbarrier::complete_tx::bytes [%0], [%1], %2, [%3];"
                 :: "r"(dst), "l"(src), "r"(bytes), "r"(bar) : "memory");
}
__device__ __forceinline__ void ldsm_x4(uint32_t (&r)[4], uint32_t addr) {
    asm volatile("ldmatrix.sync.aligned.m8n8.x4.shared.b16 {%0,%1,%2,%3}, [%4];"
                 : "=r"(r[0]), "=r"(r[1]), "=r"(r[2]), "=r"(r[3]) : "r"(addr));
}
__device__ __forceinline__ void mma16816(float (&d)[4], const uint32_t (&a)[4],
                                         uint32_t b0, uint32_t b1) {
    asm volatile(
        "mma.sync.aligned.m16n8k16.row.col.f32.f16.f16.f32 "
        "{%0,%1,%2,%3}, {%4,%5,%6,%7}, {%8,%9}, {%0,%1,%2,%3};"
        : "+f"(d[0]), "+f"(d[1]), "+f"(d[2]), "+f"(d[3])
        : "r"(a[0]), "r"(a[1]), "r"(a[2]), "r"(a[3]), "r"(b0), "r"(b1));
}
__device__ __forceinline__ uint32_t pack2(h16 a, h16 b) {
    return (uint32_t)__half_as_ushort(a) | ((uint32_t)__half_as_ushort(b) << 16);
}
__device__ __forceinline__ long blk_off(int row, int k, int Kt) {
    long blk = (long)(row >> 7) * (Kt >> 6) + (k >> 6);
    uint32_t off = (uint32_t)((row & 127) * 128 + (k & 63) * 2);
    off ^= (off >> 3) & 0x70;
    return blk * BLK_ELEMS + (off >> 1);
}
__device__ __forceinline__ uint32_t swz_row(int r, int kbyte) {
    uint32_t o = (uint32_t)(r * 128 + kbyte);
    return o ^ ((o >> 3) & 0x70);
}

// ---------------- blocked fp16 GEMM (NT = 1 or 3 emulation terms) ----------------
// D[m,n] = alpha * sum_k A[m,k]*B[n,k] + biasM[m] + biasN[n]
// OUT: 0 = fp32 linear, 1 = h-plane blocked
template <int OUT, int NT>
__global__ void __launch_bounds__(256)
gemm_blk(const h16* __restrict__ Ah, const h16* __restrict__ Al, int KtA, long sA,
         const h16* __restrict__ Bh, const h16* __restrict__ Bl, int KtB, long sB,
         float* __restrict__ Cf, h16* __restrict__ Ch,
         int ldKtC, long sC, int cOff,
         int K, float alpha, const float* __restrict__ biasM, const float* __restrict__ biasN)
{
    constexpr int NBLK = (NT == 3) ? 4 : 2;
    constexpr uint32_t STAGE = NBLK * BLK_BYTES;

    extern __shared__ __align__(128) char smem[];
    __shared__ __align__(8) uint64_t barsto[NSTAGE];

    const int tid = threadIdx.x, wid = tid >> 5, lane = tid & 31;
    const int b = blockIdx.z;
    const int m0 = blockIdx.y * 128, n0 = blockIdx.x * 128;
    const int wm = (wid & 3) * 32;
    const int wn = (wid >> 2) * 64;

    const h16* pAh = Ah + (long)b * sA + (long)(m0 >> 7) * (KtA >> 6) * BLK_ELEMS;
    const h16* pBh = Bh + (long)b * sB + (long)(n0 >> 7) * (KtB >> 6) * BLK_ELEMS;
    const h16* pAl = (NT == 3) ? Al + (long)b * sA + (long)(m0 >> 7) * (KtA >> 6) * BLK_ELEMS : nullptr;
    const h16* pBl = (NT == 3) ? Bl + (long)b * sB + (long)(n0 >> 7) * (KtB >> 6) * BLK_ELEMS : nullptr;

    const uint32_t s_base = smem_u32(smem);
    const uint32_t bar0 = smem_u32(barsto);
    const int nch = K >> 6;

    auto issue = [&](int c) {
        const int s = c % NSTAGE;
        const uint32_t sb = s_base + (uint32_t)s * STAGE;
        const uint32_t bar = bar0 + (uint32_t)s * 8;
        mbar_expect(bar, NBLK * BLK_BYTES);
        if (NT == 3) {
            bulk_g2s(sb + 0 * BLK_BYTES, pAh + (long)c * BLK_ELEMS, BLK_BYTES, bar);
            bulk_g2s(sb + 1 * BLK_BYTES, pAl + (long)c * BLK_ELEMS, BLK_BYTES, bar);
            bulk_g2s(sb + 2 * BLK_BYTES, pBh + (long)c * BLK_ELEMS, BLK_BYTES, bar);
            bulk_g2s(sb + 3 * BLK_BYTES, pBl + (long)c * BLK_ELEMS, BLK_BYTES, bar);
        } else {
            bulk_g2s(sb + 0 * BLK_BYTES, pAh + (long)c * BLK_ELEMS, BLK_BYTES, bar);
            bulk_g2s(sb + 1 * BLK_BYTES, pBh + (long)c * BLK_ELEMS, BLK_BYTES, bar);
        }
    };

    if (tid == 0) {
        for (int s = 0; s < NSTAGE; s++) mbar_init(bar0 + s * 8, 1);
        asm volatile("fence.proxy.async.shared::cta;" ::: "memory");
        const int pre = nch < NSTAGE ? nch : NSTAGE;
        for (int c = 0; c < pre; c++) issue(c);
    }
    __syncthreads();

    float acc[2][8][4];
#pragma unroll
    for (int i = 0; i < 2; i++)
#pragma unroll
        for (int j = 0; j < 8; j++)
#pragma unroll
            for (int q = 0; q < 4; q++) acc[i][j][q] = 0.f;

    const int lrow = lane & 15;
    const int lkby = ((lane >> 4) * 8) * 2;
    const uint32_t boff = (NT == 3) ? 2 * BLK_BYTES : 1 * BLK_BYTES;

    for (int c = 0; c < nch; c++) {
        const int s = c % NSTAGE;
        mbar_wait(bar0 + s * 8, (uint32_t)((c / NSTAGE) & 1));
        const uint32_t sb = s_base + (uint32_t)s * STAGE;

#pragma unroll
        for (int ks = 0; ks < 4; ks++) {
            const int kb = ks * 32 + lkby;
            uint32_t ah[2][4], al[2][4];
#pragma unroll
            for (int i = 0; i < 2; i++) {
                uint32_t o = swz_row(wm + i * 16 + lrow, kb);
                ldsm_x4(ah[i], sb + o);
                if (NT == 3) ldsm_x4(al[i], sb + BLK_BYTES + o);
            }
            uint32_t bh[4][4], bl[4][4];
#pragma unroll
            for (int jj = 0; jj < 4; jj++) {
                uint32_t o = swz_row(wn + jj * 16 + lrow, kb);
                ldsm_x4(bh[jj], sb + boff + o);
                if (NT == 3) ldsm_x4(bl[jj], sb + 3 * BLK_BYTES + o);
            }
#pragma unroll
            for (int t = 0; t < NT; t++) {
#pragma unroll
                for (int i = 0; i < 2; i++) {
#pragma unroll
                    for (int j = 0; j < 8; j++) {
                        const int jj = j >> 1, sel = j & 1;
                        if (t == 0)
                            mma16816(acc[i][j], ah[i], bh[jj][sel], bh[jj][sel + 2]);
                        else if (t == 1)
                            mma16816(acc[i][j], ah[i], bl[jj][sel], bl[jj][sel + 2]);
                        else
                            mma16816(acc[i][j], al[i], bh[jj][sel], bh[jj][sel + 2]);
                    }
                }
            }
        }
        __syncthreads();
        if (tid == 0 && c + NSTAGE < nch) issue(c + NSTAGE);
    }

    // ---------------- epilogue ----------------
    const int mrow = m0 + wm + (lane >> 2);
    const int ncol0 = n0 + wn + 2 * (lane & 3);

#pragma unroll
    for (int i = 0; i < 2; i++) {
        const int m = mrow + i * 16;
        const float bm0 = biasM ? biasM[m] : 0.f;
        const float bm8 = biasM ? biasM[m + 8] : 0.f;
#pragma unroll
        for (int j = 0; j < 8; j++) {
            const int n = ncol0 + j * 8;
            const float bn0 = biasN ? biasN[n] : 0.f;
            const float bn1 = biasN ? biasN[n + 1] : 0.f;
            float v0 = alpha * acc[i][j][0] + bm0 + bn0;
            float v1 = alpha * acc[i][j][1] + bm0 + bn1;
            float v2 = alpha * acc[i][j][2] + bm8 + bn0;
            float v3 = alpha * acc[i][j][3] + bm8 + bn1;
            if (OUT == 0) {
                float* co = Cf + (long)b * sC;
                *reinterpret_cast<float2*>(co + (long)m * ldKtC + n) = make_float2(v0, v1);
                *reinterpret_cast<float2*>(co + (long)(m + 8) * ldKtC + n) = make_float2(v2, v3);
            } else {
                h16* ch = Ch + (long)b * sC;
                const long o0 = blk_off(m,     n + cOff, ldKtC);
                const long o8 = blk_off(m + 8, n + cOff, ldKtC);
                *reinterpret_cast<uint32_t*>(ch + o0) = pack2(__float2half_rn(v0), __float2half_rn(v1));
                *reinterpret_cast<uint32_t*>(ch + o8) = pack2(__float2half_rn(v2), __float2half_rn(v3));
            }
        }
    }
}

// ---------------- aux kernels ----------------
__global__ void trans_convert_kernel(const float* __restrict__ src, long sstride, int src_ld,
                                     h16* __restrict__ dh, h16* __restrict__ dl,
                                     long dstride, int KtD)
{
    __shared__ float t[32][33];
    const float* S = src + (long)blockIdx.z * sstride;
    h16* DH = dh + (long)blockIdx.z * dstride;
    h16* DL = dl ? dl + (long)blockIdx.z * dstride : nullptr;
    const int c0 = blockIdx.x * 32, r0 = blockIdx.y * 32;
    const int tx = threadIdx.x, ty = threadIdx.y;
#pragma unroll
    for (int k = 0; k < 4; k++)
        t[ty + 8*k][tx] = S[(long)(r0 + ty + 8*k) * src_ld + c0 + tx];
    __syncthreads();
#pragma unroll
    for (int k = 0; k < 4; k++) {
        float x = t[tx][ty + 8*k];
        h16 h = __float2half_rn(x);
        long o = blk_off(c0 + ty + 8*k, r0 + tx, KtD);
        DH[o] = h;
        if (DL) DL[o] = __float2half_rn(x - __half2float(h));
    }
}

__global__ void convert_h_kernel(const float* __restrict__ s, h16* __restrict__ dh,
                                 int Kt, int n)
{
    int i = blockIdx.x * blockDim.x + threadIdx.x;
    if (i >= n) return;
    dh[blk_off(i / Kt, i % Kt, Kt)] = __float2half_rn(s[i]);
}

__global__ void fold_bias_kernel(const float* __restrict__ pib, const float* __restrict__ wq,
                                 const float* __restrict__ wqb, float* __restrict__ out)
{
    int f = blockIdx.x * blockDim.x + threadIdx.x;
    if (f >= EMB) return;
    float s = wqb[f];
    for (int e = 0; e < EMB; e++) s = fmaf(pib[e], wq[e * EMB + f], s);
    out[f] = s;
}

__global__ void __launch_bounds__(256) softmax_h_kernel(const float* __restrict__ S,
                                                        h16* __restrict__ Ph)
{
    const float* row = S + (long)blockIdx.x * LCTX;
    const int t = threadIdx.x;
    float v[4], mx = -INFINITY;
#pragma unroll
    for (int j = 0; j < 4; j++) { v[j] = row[t + j*256]; mx = fmaxf(mx, v[j]); }
    __shared__ float red[256];
    red[t] = mx; __syncthreads();
    for (int s = 128; s > 0; s >>= 1) { if (t < s) red[t] = fmaxf(red[t], red[t+s]); __syncthreads(); }
    mx = red[0]; __syncthreads();
    float sum = 0.f;
#pragma unroll
    for (int j = 0; j < 4; j++) { v[j] = __expf(v[j] - mx); sum += v[j]; }
    red[t] = sum; __syncthreads();
    for (int s = 128; s > 0; s >>= 1) { if (t < s) red[t] += red[t+s]; __syncthreads(); }
    const float inv = 1.f / red[0];
    const int b = blockIdx.x >> 12;
    const int p = blockIdx.x & 4095;
    const long base = (long)b * ((long)HW * LCTX);
#pragma unroll
    for (int j = 0; j < 4; j++)
        Ph[base + blk_off(p, t + j*256, LCTX)] = __float2half_rn(v[j] * inv);
}

// ---------------- launch ----------------
extern "C" void kernel_launch(void* const* d_in, const int* in_sizes, int n_in,
                              void* d_out, int out_size)
{
    const float* input      = (const float*)d_in[0];
    const float* context    = (const float*)d_in[1];
    const float* proj_in_w  = (const float*)d_in[2];
    const float* proj_in_b  = (const float*)d_in[3];
    const float* wq_w       = (const float*)d_in[4];
    const float* wq_b       = (const float*)d_in[5];
    const float* wk_w       = (const float*)d_in[6];
    const float* wk_b       = (const float*)d_in[7];
    const float* wv_w       = (const float*)d_in[8];
    const float* wv_b       = (const float*)d_in[9];
    const float* proj_out_w = (const float*)d_in[10];
    const float* proj_out_b = (const float*)d_in[11];
    float* out = (float*)d_out;

    const int SMEM3 = NSTAGE * 4 * BLK_BYTES;   // 196608
    const int SMEM1 = NSTAGE * 2 * BLK_BYTES;   // 98304
    cudaFuncSetAttribute(gemm_blk<1,3>, cudaFuncAttributeMaxDynamicSharedMemorySize, SMEM3);
    cudaFuncSetAttribute(gemm_blk<0,1>, cudaFuncAttributeMaxDynamicSharedMemorySize, SMEM1);
    cudaFuncSetAttribute(gemm_blk<1,1>, cudaFuncAttributeMaxDynamicSharedMemorySize, SMEM1);

    float *bq, *S;
    h16 *wqT0h,*wqT0l,*piTh,*piTl,*WqTh,*wkTh,*wvTh,*poh;
    h16 *Zh,*cth,*Qh,*Kh,*VTh,*Ph;
    cudaGetSymbolAddress((void**)&bq, g_bq);         cudaGetSymbolAddress((void**)&S, g_S);
    cudaGetSymbolAddress((void**)&wqT0h, g_wqT0_h);  cudaGetSymbolAddress((void**)&wqT0l, g_wqT0_l);
    cudaGetSymbolAddress((void**)&piTh, g_piT_h);    cudaGetSymbolAddress((void**)&piTl, g_piT_l);
    cudaGetSymbolAddress((void**)&WqTh, g_WqT_h);
    cudaGetSymbolAddress((void**)&wkTh, g_wkT_h);
    cudaGetSymbolAddress((void**)&wvTh, g_wvT_h);
    cudaGetSymbolAddress((void**)&poh, g_po_h);
    cudaGetSymbolAddress((void**)&Zh, g_Z_h);
    cudaGetSymbolAddress((void**)&cth, g_ctxT_h);
    cudaGetSymbolAddress((void**)&Qh, g_Q_h);        cudaGetSymbolAddress((void**)&Kh, g_K_h);
    cudaGetSymbolAddress((void**)&VTh, g_VT_h);      cudaGetSymbolAddress((void**)&Ph, g_P_h);

    const float scale = 1.0f / sqrtf((float)EMB);
    dim3 tb(32, 8);

    // weight prep (h+l only where 3-term fold consumes it)
    fold_bias_kernel<<<2, 256>>>(proj_in_b, wq_w, wq_b, bq);
    trans_convert_kernel<<<dim3(16,16,1), tb>>>(wq_w, 0, EMB, wqT0h, wqT0l, 0, EMB);
    trans_convert_kernel<<<dim3(16,16,1), tb>>>(proj_in_w, 0, EMB, piTh, piTl, 0, EMB);
    trans_convert_kernel<<<dim3(16,16,1), tb>>>(wk_w, 0, EMB, wkTh, nullptr, 0, EMB);
    trans_convert_kernel<<<dim3(16,16,1), tb>>>(wv_w, 0, EMB, wvTh, nullptr, 0, EMB);
    convert_h_kernel<<<(EMB*2*EMB)/256, 256>>>(proj_out_w, poh, 2*EMB, EMB*2*EMB);
    trans_convert_kernel<<<dim3(32,16,BATCH), tb>>>(context, (long)EMB*LCTX, LCTX,
                                                    cth, nullptr, (long)LCTX*EMB, EMB);
    trans_convert_kernel<<<dim3(128,16,BATCH), tb>>>(input, (long)EMB*HW, HW,
                                                     Zh, nullptr, (long)HW*2*EMB, 2*EMB);

    // 1) WqT = wqT0 · piT^T   (3-term for weight accuracy; h out)
    gemm_blk<1,3><<<dim3(4,4,1), 256, SMEM3>>>(
        wqT0h, wqT0l, EMB, 0, piTh, piTl, EMB, 0,
        nullptr, WqTh, EMB, 0, 0, EMB, 1.0f, nullptr, nullptr);
    // 2) K[l][f] = ctxT · wkT^T + wk_b   (1-term)
    gemm_blk<1,1><<<dim3(4,8,BATCH), 256, SMEM1>>>(
        cth, nullptr, EMB, (long)LCTX*EMB, wkTh, nullptr, EMB, 0,
        nullptr, Kh, EMB, (long)LCTX*EMB, 0, EMB, 1.0f, nullptr, wk_b);
    // 3) VT[e][l] = wvT · ctxT^T + wv_b[e]   (1-term)
    gemm_blk<1,1><<<dim3(8,4,BATCH), 256, SMEM1>>>(
        wvTh, nullptr, EMB, 0, cth, nullptr, EMB, (long)LCTX*EMB,
        nullptr, VTh, LCTX, (long)EMB*LCTX, 0, EMB, 1.0f, wv_b, nullptr);
    // 4) Q[p][f] = Z[:, :512] · WqT^T + bq   (1-term)
    gemm_blk<1,1><<<dim3(4,32,BATCH), 256, SMEM1>>>(
        Zh, nullptr, 2*EMB, (long)HW*2*EMB, WqTh, nullptr, EMB, 0,
        nullptr, Qh, EMB, (long)HW*EMB, 0, EMB, 1.0f, nullptr, bq);
    // 5) S = scale * Q · K^T   (1-term, fp32 out)
    gemm_blk<0,1><<<dim3(8,32,BATCH), 256, SMEM1>>>(
        Qh, nullptr, EMB, (long)HW*EMB, Kh, nullptr, EMB, (long)LCTX*EMB,
        S, nullptr, LCTX, (long)HW*LCTX, 0, EMB, scale, nullptr, nullptr);
    // 6) softmax -> Ph
    softmax_h_kernel<<<BATCH*HW, 256>>>(S, Ph);
    // 7) O = P · VT^T -> Z k-cols [512,1024)   (1-term)
    gemm_blk<1,1><<<dim3(4,32,BATCH), 256, SMEM1>>>(
        Ph, nullptr, LCTX, (long)HW*LCTX, VTh, nullptr, LCTX, (long)EMB*LCTX,
        nullptr, Zh, 2*EMB, (long)HW*2*EMB, EMB, LCTX, 1.0f, nullptr, nullptr);
    // 8) out = po · Z^T + proj_out_b   (1-term, fp32 out)
    gemm_blk<0,1><<<dim3(32,4,BATCH), 256, SMEM1>>>(
        poh, nullptr, 2*EMB, 0, Zh, nullptr, 2*EMB, (long)HW*2*EMB,
        out, nullptr, HW, (long)EMB*HW, 0, 2*EMB, 1.0f, proj_out_b, nullptr);
}

// round 9
// speedup vs baseline: 7.4298x; 1.0558x over previous
#include <cuda_runtime.h>
#include <cuda_fp16.h>
#include <math.h>
#include <stdint.h>

#define BATCH 8
#define HW    4096
#define LCTX  1024
#define EMB   512

typedef __half h16;

// blocked layout: [rowblk][kblk][128x64 swizzled]; 16KB per block
#define BLK_ELEMS 8192
#define BLK_BYTES 16384
#define NSTAGE 3

// ---------------- device scratch ----------------
__device__ __align__(128) float g_bq[EMB];

__device__ __align__(128) h16 g_wqT0_h[EMB*EMB], g_wqT0_l[EMB*EMB];   // wq^T [f][e]
__device__ __align__(128) h16 g_piT_h [EMB*EMB], g_piT_l [EMB*EMB];   // pi^T [c][e]
__device__ __align__(128) h16 g_WqT_h [EMB*EMB];                      // folded [f][c]
__device__ __align__(128) h16 g_wkT_h [EMB*EMB];                      // [f][c]
__device__ __align__(128) h16 g_wvT_h [EMB*EMB];                      // [e][c]
__device__ __align__(128) h16 g_po_h[EMB*2*EMB];                      // [o][k] blocked Kt=1024

__device__ __align__(128) h16 g_Z_h[(long)BATCH*HW*EMB];              // input^T [b][p][c]
__device__ __align__(128) h16 g_ctxT_h[(long)BATCH*LCTX*EMB];         // [b][l][c]
__device__ __align__(128) h16 g_Q_h[(long)BATCH*HW*EMB];
__device__ __align__(128) h16 g_K_h[(long)BATCH*LCTX*EMB];            // [b][l][f]
__device__ __align__(128) h16 g_V_h[(long)BATCH*LCTX*EMB];            // [b][l][e]
__device__ __align__(128) h16 g_S_h[(long)BATCH*HW*LCTX];             // fp16 logits blocked
__device__ __align__(128) h16 g_P_h[(long)BATCH*HW*LCTX];
__device__ __align__(128) h16 g_W2_h[(long)BATCH*EMB*LCTX];           // po2·V^T [b][o][l]

// ---------------- helpers ----------------
__device__ __forceinline__ uint32_t smem_u32(const void* p) {
    uint32_t r;
    asm("{ .reg .u64 t; cvta.to.shared.u64 t, %1; cvt.u32.u64 %0, t; }" : "=r"(r) : "l"(p));
    return r;
}
__device__ __forceinline__ void mbar_init(uint32_t a, uint32_t c) {
    asm volatile("mbarrier.init.shared.b64 [%0], %1;" :: "r"(a), "r"(c) : "memory");
}
__device__ __forceinline__ void mbar_expect(uint32_t a, uint32_t bytes) {
    asm volatile("mbarrier.arrive.expect_tx.shared.b64 _, [%0], %1;" :: "r"(a), "r"(bytes) : "memory");
}
__device__ __forceinline__ void mbar_wait(uint32_t a, uint32_t par) {
    asm volatile(
        "{\n\t.reg .pred P1;\n\tW%=:\n\t"
        "mbarrier.try_wait.parity.acquire.cta.shared::cta.b64 P1, [%0], %1, 0x989680;\n\t"
        "@P1 bra D%=;\n\tbra W%=;\n\tD%=:\n\t}" :: "r"(a), "r"(par) : "memory");
}
__device__ __forceinline__ void bulk_g2s(uint32_t dst, const void* src, uint32_t bytes, uint32_t bar) {
    asm volatile("cp.async.bulk.shared::cluster.global.mbarrier::complete_tx::bytes [%0], [%1], %2, [%3];"
                 :: "r"(dst), "l"(src), "r"(bytes), "r"(bar) : "memory");
}
__device__ __forceinline__ void ldsm_x4(uint32_t (&r)[4], uint32_t addr) {
    asm volatile("ldmatrix.sync.aligned.m8n8.x4.shared.b16 {%0,%1,%2,%3}, [%4];"
                 : "=r"(r[0]), "=r"(r[1]), "=r"(r[2]), "=r"(r[3]) : "r"(addr));
}
__device__ __forceinline__ void mma16816(float (&d)[4], const uint32_t (&a)[4],
                                         uint32_t b0, uint32_t b1) {
    asm volatile(
        "mma.sync.aligned.m16n8k16.row.col.f32.f16.f16.f32 "
        "{%0,%1,%2,%3}, {%4,%5,%6,%7}, {%8,%9}, {%0,%1,%2,%3};"
        : "+f"(d[0]), "+f"(d[1]), "+f"(d[2]), "+f"(d[3])
        : "r"(a[0]), "r"(a[1]), "r"(a[2]), "r"(a[3]), "r"(b0), "r"(b1));
}
__device__ __forceinline__ uint32_t pack2(h16 a, h16 b) {
    return (uint32_t)__half_as_ushort(a) | ((uint32_t)__half_as_ushort(b) << 16);
}
__device__ __forceinline__ long blk_off(int row, int k, int Kt) {
    long blk = (long)(row >> 7) * (Kt >> 6) + (k >> 6);
    uint32_t off = (uint32_t)((row & 127) * 128 + (k & 63) * 2);
    off ^= (off >> 3) & 0x70;
    return blk * BLK_ELEMS + (off >> 1);
}
__device__ __forceinline__ uint32_t swz_row(int r, int kbyte) {
    uint32_t o = (uint32_t)(r * 128 + kbyte);
    return o ^ ((o >> 3) & 0x70);
}

// ---------------- blocked fp16 GEMM ----------------
// D[m,n] = alpha * sum_k A[m,k]*B[n,k] + biasM[m] + biasN[n]   (+ C when OUT==2)
// OUT: 0 = fp32 write, 1 = h-plane blocked, 2 = fp32 accumulate ; NT = 1 or 3 terms
template <int OUT, int NT>
__global__ void __launch_bounds__(256)
gemm_blk(const h16* __restrict__ Ah, const h16* __restrict__ Al, int KtA, long sA,
         const h16* __restrict__ Bh, const h16* __restrict__ Bl, int KtB, long sB,
         float* __restrict__ Cf, h16* __restrict__ Ch,
         int ldKtC, long sC, int cOff,
         int K, float alpha, const float* __restrict__ biasM, const float* __restrict__ biasN)
{
    constexpr int NBLK = (NT == 3) ? 4 : 2;
    constexpr uint32_t STAGE = NBLK * BLK_BYTES;

    extern __shared__ __align__(128) char smem[];
    __shared__ __align__(8) uint64_t barsto[NSTAGE];

    const int tid = threadIdx.x, wid = tid >> 5, lane = tid & 31;
    const int b = blockIdx.z;
    const int m0 = blockIdx.y * 128, n0 = blockIdx.x * 128;
    const int wm = (wid & 3) * 32;
    const int wn = (wid >> 2) * 64;

    const h16* pAh = Ah + (long)b * sA + (long)(m0 >> 7) * (KtA >> 6) * BLK_ELEMS;
    const h16* pBh = Bh + (long)b * sB + (long)(n0 >> 7) * (KtB >> 6) * BLK_ELEMS;
    const h16* pAl = (NT == 3) ? Al + (long)b * sA + (long)(m0 >> 7) * (KtA >> 6) * BLK_ELEMS : nullptr;
    const h16* pBl = (NT == 3) ? Bl + (long)b * sB + (long)(n0 >> 7) * (KtB >> 6) * BLK_ELEMS : nullptr;

    const uint32_t s_base = smem_u32(smem);
    const uint32_t bar0 = smem_u32(barsto);
    const int nch = K >> 6;

    auto issue = [&](int c) {
        const int s = c % NSTAGE;
        const uint32_t sb = s_base + (uint32_t)s * STAGE;
        const uint32_t bar = bar0 + (uint32_t)s * 8;
        mbar_expect(bar, NBLK * BLK_BYTES);
        if (NT == 3) {
            bulk_g2s(sb + 0 * BLK_BYTES, pAh + (long)c * BLK_ELEMS, BLK_BYTES, bar);
            bulk_g2s(sb + 1 * BLK_BYTES, pAl + (long)c * BLK_ELEMS, BLK_BYTES, bar);
            bulk_g2s(sb + 2 * BLK_BYTES, pBh + (long)c * BLK_ELEMS, BLK_BYTES, bar);
            bulk_g2s(sb + 3 * BLK_BYTES, pBl + (long)c * BLK_ELEMS, BLK_BYTES, bar);
        } else {
            bulk_g2s(sb + 0 * BLK_BYTES, pAh + (long)c * BLK_ELEMS, BLK_BYTES, bar);
            bulk_g2s(sb + 1 * BLK_BYTES, pBh + (long)c * BLK_ELEMS, BLK_BYTES, bar);
        }
    };

    if (tid == 0) {
        for (int s = 0; s < NSTAGE; s++) mbar_init(bar0 + s * 8, 1);
        asm volatile("fence.proxy.async.shared::cta;" ::: "memory");
        const int pre = nch < NSTAGE ? nch : NSTAGE;
        for (int c = 0; c < pre; c++) issue(c);
    }
    __syncthreads();

    float acc[2][8][4];
#pragma unroll
    for (int i = 0; i < 2; i++)
#pragma unroll
        for (int j = 0; j < 8; j++)
#pragma unroll
            for (int q = 0; q < 4; q++) acc[i][j][q] = 0.f;

    const int lrow = lane & 15;
    const int lkby = ((lane >> 4) * 8) * 2;
    const uint32_t boff = (NT == 3) ? 2 * BLK_BYTES : 1 * BLK_BYTES;

    for (int c = 0; c < nch; c++) {
        const int s = c % NSTAGE;
        mbar_wait(bar0 + s * 8, (uint32_t)((c / NSTAGE) & 1));
        const uint32_t sb = s_base + (uint32_t)s * STAGE;

#pragma unroll
        for (int ks = 0; ks < 4; ks++) {
            const int kb = ks * 32 + lkby;
            uint32_t ah[2][4], al[2][4];
#pragma unroll
            for (int i = 0; i < 2; i++) {
                uint32_t o = swz_row(wm + i * 16 + lrow, kb);
                ldsm_x4(ah[i], sb + o);
                if (NT == 3) ldsm_x4(al[i], sb + BLK_BYTES + o);
            }
            uint32_t bh[4][4], bl[4][4];
#pragma unroll
            for (int jj = 0; jj < 4; jj++) {
                uint32_t o = swz_row(wn + jj * 16 + lrow, kb);
                ldsm_x4(bh[jj], sb + boff + o);
                if (NT == 3) ldsm_x4(bl[jj], sb + 3 * BLK_BYTES + o);
            }
#pragma unroll
            for (int t = 0; t < NT; t++) {
#pragma unroll
                for (int i = 0; i < 2; i++) {
#pragma unroll
                    for (int j = 0; j < 8; j++) {
                        const int jj = j >> 1, sel = j & 1;
                        if (t == 0)
                            mma16816(acc[i][j], ah[i], bh[jj][sel], bh[jj][sel + 2]);
                        else if (t == 1)
                            mma16816(acc[i][j], ah[i], bl[jj][sel], bl[jj][sel + 2]);
                        else
                            mma16816(acc[i][j], al[i], bh[jj][sel], bh[jj][sel + 2]);
                    }
                }
            }
        }
        __syncthreads();
        if (tid == 0 && c + NSTAGE < nch) issue(c + NSTAGE);
    }

    // ---------------- epilogue ----------------
    const int mrow = m0 + wm + (lane >> 2);
    const int ncol0 = n0 + wn + 2 * (lane & 3);

#pragma unroll
    for (int i = 0; i < 2; i++) {
        const int m = mrow + i * 16;
        const float bm0 = biasM ? biasM[m] : 0.f;
        const float bm8 = biasM ? biasM[m + 8] : 0.f;
#pragma unroll
        for (int j = 0; j < 8; j++) {
            const int n = ncol0 + j * 8;
            const float bn0 = biasN ? biasN[n] : 0.f;
            const float bn1 = biasN ? biasN[n + 1] : 0.f;
            float v0 = alpha * acc[i][j][0] + bm0 + bn0;
            float v1 = alpha * acc[i][j][1] + bm0 + bn1;
            float v2 = alpha * acc[i][j][2] + bm8 + bn0;
            float v3 = alpha * acc[i][j][3] + bm8 + bn1;
            if (OUT == 0 || OUT == 2) {
                float* co = Cf + (long)b * sC;
                float2* p0 = reinterpret_cast<float2*>(co + (long)m * ldKtC + n);
                float2* p8 = reinterpret_cast<float2*>(co + (long)(m + 8) * ldKtC + n);
                if (OUT == 2) {
                    float2 o0 = *p0, o8 = *p8;
                    v0 += o0.x; v1 += o0.y; v2 += o8.x; v3 += o8.y;
                }
                *p0 = make_float2(v0, v1);
                *p8 = make_float2(v2, v3);
            } else {
                h16* ch = Ch + (long)b * sC;
                const long o0 = blk_off(m,     n + cOff, ldKtC);
                const long o8 = blk_off(m + 8, n + cOff, ldKtC);
                *reinterpret_cast<uint32_t*>(ch + o0) = pack2(__float2half_rn(v0), __float2half_rn(v1));
                *reinterpret_cast<uint32_t*>(ch + o8) = pack2(__float2half_rn(v2), __float2half_rn(v3));
            }
        }
    }
}

// ---------------- aux kernels ----------------
struct TJob { const float* s; h16* dh; h16* dl; };

// four 512x512 transposes in one launch (z selects job)
__global__ void trans4_kernel(TJob j0, TJob j1, TJob j2, TJob j3)
{
    __shared__ float t[32][33];
    TJob j = (blockIdx.z == 0) ? j0 : (blockIdx.z == 1) ? j1 : (blockIdx.z == 2) ? j2 : j3;
    const int c0 = blockIdx.x * 32, r0 = blockIdx.y * 32;
    const int tx = threadIdx.x, ty = threadIdx.y;
#pragma unroll
    for (int k = 0; k < 4; k++)
        t[ty + 8*k][tx] = j.s[(long)(r0 + ty + 8*k) * EMB + c0 + tx];
    __syncthreads();
#pragma unroll
    for (int k = 0; k < 4; k++) {
        float x = t[tx][ty + 8*k];
        h16 h = __float2half_rn(x);
        long o = blk_off(c0 + ty + 8*k, r0 + tx, EMB);
        j.dh[o] = h;
        if (j.dl) j.dl[o] = __float2half_rn(x - __half2float(h));
    }
}

__global__ void trans_convert_kernel(const float* __restrict__ src, long sstride, int src_ld,
                                     h16* __restrict__ dh, long dstride, int KtD)
{
    __shared__ float t[32][33];
    const float* S = src + (long)blockIdx.z * sstride;
    h16* DH = dh + (long)blockIdx.z * dstride;
    const int c0 = blockIdx.x * 32, r0 = blockIdx.y * 32;
    const int tx = threadIdx.x, ty = threadIdx.y;
#pragma unroll
    for (int k = 0; k < 4; k++)
        t[ty + 8*k][tx] = S[(long)(r0 + ty + 8*k) * src_ld + c0 + tx];
    __syncthreads();
#pragma unroll
    for (int k = 0; k < 4; k++) {
        float x = t[tx][ty + 8*k];
        DH[blk_off(c0 + ty + 8*k, r0 + tx, KtD)] = __float2half_rn(x);
    }
}

__global__ void convert_h_kernel(const float* __restrict__ s, h16* __restrict__ dh,
                                 int Kt, int n)
{
    int i = blockIdx.x * blockDim.x + threadIdx.x;
    if (i >= n) return;
    dh[blk_off(i / Kt, i % Kt, Kt)] = __float2half_rn(s[i]);
}

__global__ void fold_bias_kernel(const float* __restrict__ pib, const float* __restrict__ wq,
                                 const float* __restrict__ wqb, float* __restrict__ out)
{
    int f = blockIdx.x * blockDim.x + threadIdx.x;
    if (f >= EMB) return;
    float s = wqb[f];
    for (int e = 0; e < EMB; e++) s = fmaf(pib[e], wq[e * EMB + f], s);
    out[f] = s;
}

// softmax over blocked fp16 rows
__global__ void __launch_bounds__(256) softmax_h_kernel(const h16* __restrict__ Sh,
                                                        h16* __restrict__ Ph)
{
    const int t = threadIdx.x;
    const int b = blockIdx.x >> 12;
    const int p = blockIdx.x & 4095;
    const long base = (long)b * ((long)HW * LCTX);
    long off[4];
    float v[4], mx = -INFINITY;
#pragma unroll
    for (int j = 0; j < 4; j++) {
        off[j] = base + blk_off(p, t + j*256, LCTX);
        v[j] = __half2float(Sh[off[j]]);
        mx = fmaxf(mx, v[j]);
    }
    __shared__ float red[256];
    red[t] = mx; __syncthreads();
    for (int s = 128; s > 0; s >>= 1) { if (t < s) red[t] = fmaxf(red[t], red[t+s]); __syncthreads(); }
    mx = red[0]; __syncthreads();
    float sum = 0.f;
#pragma unroll
    for (int j = 0; j < 4; j++) { v[j] = __expf(v[j] - mx); sum += v[j]; }
    red[t] = sum; __syncthreads();
    for (int s = 128; s > 0; s >>= 1) { if (t < s) red[t] += red[t+s]; __syncthreads(); }
    const float inv = 1.f / red[0];
#pragma unroll
    for (int j = 0; j < 4; j++)
        Ph[off[j]] = __float2half_rn(v[j] * inv);
}

// ---------------- launch ----------------
extern "C" void kernel_launch(void* const* d_in, const int* in_sizes, int n_in,
                              void* d_out, int out_size)
{
    const float* input      = (const float*)d_in[0];
    const float* context    = (const float*)d_in[1];
    const float* proj_in_w  = (const float*)d_in[2];
    const float* proj_in_b  = (const float*)d_in[3];
    const float* wq_w       = (const float*)d_in[4];
    const float* wq_b       = (const float*)d_in[5];
    const float* wk_w       = (const float*)d_in[6];
    const float* wk_b       = (const float*)d_in[7];
    const float* wv_w       = (const float*)d_in[8];
    const float* wv_b       = (const float*)d_in[9];
    const float* proj_out_w = (const float*)d_in[10];
    const float* proj_out_b = (const float*)d_in[11];
    float* out = (float*)d_out;

    const int SMEM3 = NSTAGE * 4 * BLK_BYTES;   // 196608
    const int SMEM1 = NSTAGE * 2 * BLK_BYTES;   // 98304
    cudaFuncSetAttribute(gemm_blk<1,3>, cudaFuncAttributeMaxDynamicSharedMemorySize, SMEM3);
    cudaFuncSetAttribute(gemm_blk<0,1>, cudaFuncAttributeMaxDynamicSharedMemorySize, SMEM1);
    cudaFuncSetAttribute(gemm_blk<1,1>, cudaFuncAttributeMaxDynamicSharedMemorySize, SMEM1);
    cudaFuncSetAttribute(gemm_blk<2,1>, cudaFuncAttributeMaxDynamicSharedMemorySize, SMEM1);

    float *bq;
    h16 *wqT0h,*wqT0l,*piTh,*piTl,*WqTh,*wkTh,*wvTh,*poh;
    h16 *Zh,*cth,*Qh,*Kh,*Vh,*Sh,*Ph,*W2h;
    cudaGetSymbolAddress((void**)&bq, g_bq);
    cudaGetSymbolAddress((void**)&wqT0h, g_wqT0_h);  cudaGetSymbolAddress((void**)&wqT0l, g_wqT0_l);
    cudaGetSymbolAddress((void**)&piTh, g_piT_h);    cudaGetSymbolAddress((void**)&piTl, g_piT_l);
    cudaGetSymbolAddress((void**)&WqTh, g_WqT_h);
    cudaGetSymbolAddress((void**)&wkTh, g_wkT_h);
    cudaGetSymbolAddress((void**)&wvTh, g_wvT_h);
    cudaGetSymbolAddress((void**)&poh, g_po_h);
    cudaGetSymbolAddress((void**)&Zh, g_Z_h);
    cudaGetSymbolAddress((void**)&cth, g_ctxT_h);
    cudaGetSymbolAddress((void**)&Qh, g_Q_h);        cudaGetSymbolAddress((void**)&Kh, g_K_h);
    cudaGetSymbolAddress((void**)&Vh, g_V_h);        cudaGetSymbolAddress((void**)&Sh, g_S_h);
    cudaGetSymbolAddress((void**)&Ph, g_P_h);        cudaGetSymbolAddress((void**)&W2h, g_W2_h);

    const float scale = 1.0f / sqrtf((float)EMB);
    dim3 tb(32, 8);

    // ---- prep ----
    fold_bias_kernel<<<2, 256>>>(proj_in_b, wq_w, wq_b, bq);
    {
        TJob j0{wq_w, wqT0h, wqT0l}, j1{proj_in_w, piTh, piTl},
             j2{wk_w, wkTh, nullptr}, j3{wv_w, wvTh, nullptr};
        trans4_kernel<<<dim3(16,16,4), tb>>>(j0, j1, j2, j3);
    }
    convert_h_kernel<<<(EMB*2*EMB)/256, 256>>>(proj_out_w, poh, 2*EMB, EMB*2*EMB);
    trans_convert_kernel<<<dim3(32,16,BATCH), tb>>>(context, (long)EMB*LCTX, LCTX,
                                                    cth, (long)LCTX*EMB, EMB);
    trans_convert_kernel<<<dim3(128,16,BATCH), tb>>>(input, (long)EMB*HW, HW,
                                                     Zh, (long)HW*EMB, EMB);

    // ---- GEMMs ----
    // fold: WqT[f][c] = wqT0 · piT^T (3-term)
    gemm_blk<1,3><<<dim3(4,4,1), 256, SMEM3>>>(
        wqT0h, wqT0l, EMB, 0, piTh, piTl, EMB, 0,
        nullptr, WqTh, EMB, 0, 0, EMB, 1.0f, nullptr, nullptr);
    // K[l][f] = ctxT · wkT^T + wk_b
    gemm_blk<1,1><<<dim3(4,8,BATCH), 256, SMEM1>>>(
        cth, nullptr, EMB, (long)LCTX*EMB, wkTh, nullptr, EMB, 0,
        nullptr, Kh, EMB, (long)LCTX*EMB, 0, EMB, 1.0f, nullptr, wk_b);
    // V[l][e] = ctxT · wvT^T + wv_b
    gemm_blk<1,1><<<dim3(4,8,BATCH), 256, SMEM1>>>(
        cth, nullptr, EMB, (long)LCTX*EMB, wvTh, nullptr, EMB, 0,
        nullptr, Vh, EMB, (long)LCTX*EMB, 0, EMB, 1.0f, nullptr, wv_b);
    // out1[o][p] = po1 · Zh^T + proj_out_b  (fp32 write)
    gemm_blk<0,1><<<dim3(32,4,BATCH), 256, SMEM1>>>(
        poh, nullptr, 2*EMB, 0, Zh, nullptr, EMB, (long)HW*EMB,
        out, nullptr, HW, (long)EMB*HW, 0, EMB, 1.0f, proj_out_b, nullptr);
    // W2[o][l] = po2 · V^T  (po2 = k-blocks 8..15 of po)
    gemm_blk<1,1><<<dim3(8,4,BATCH), 256, SMEM1>>>(
        poh + 8*BLK_ELEMS, nullptr, 2*EMB, 0, Vh, nullptr, EMB, (long)LCTX*EMB,
        nullptr, W2h, LCTX, (long)EMB*LCTX, 0, EMB, 1.0f, nullptr, nullptr);
    // Q[p][f] = Zh · WqT^T + bq
    gemm_blk<1,1><<<dim3(4,32,BATCH), 256, SMEM1>>>(
        Zh, nullptr, EMB, (long)HW*EMB, WqTh, nullptr, EMB, 0,
        nullptr, Qh, EMB, (long)HW*EMB, 0, EMB, 1.0f, nullptr, bq);
    // S = scale * Q · K^T  (fp16 blocked)
    gemm_blk<1,1><<<dim3(8,32,BATCH), 256, SMEM1>>>(
        Qh, nullptr, EMB, (long)HW*EMB, Kh, nullptr, EMB, (long)LCTX*EMB,
        nullptr, Sh, LCTX, (long)HW*LCTX, 0, EMB, scale, nullptr, nullptr);
    // softmax -> Ph
    softmax_h_kernel<<<BATCH*HW, 256>>>(Sh, Ph);
    // out2[o][p] = W2 · P^T  (fp32 accumulate onto out)
    gemm_blk<2,1><<<dim3(32,4,BATCH), 256, SMEM1>>>(
        W2h, nullptr, LCTX, (long)EMB*LCTX, Ph, nullptr, LCTX, (long)HW*LCTX,
        out, nullptr, HW, (long)EMB*HW, 0, LCTX, 1.0f, nullptr, nullptr);
}

// round 10
// speedup vs baseline: 8.4086x; 1.1317x over previous
#include <cuda_runtime.h>
#include <cuda_fp16.h>
#include <math.h>
#include <stdint.h>

#define BATCH 8
#define HW    4096
#define LCTX  1024
#define EMB   512

typedef __half h16;

// blocked layout: [rowblk][kblk][128x64 swizzled]; 16KB per block
#define BLK_ELEMS 8192
#define BLK_BYTES 16384
#define NSTAGE 3

// ---------------- device scratch ----------------
__device__ __align__(128) float g_bq[EMB];
__device__ __align__(128) float g_rsum[BATCH * HW];

__device__ __align__(128) h16 g_wqT0_h[EMB*EMB], g_wqT0_l[EMB*EMB];   // wq^T [f][e]
__device__ __align__(128) h16 g_piT_h [EMB*EMB], g_piT_l [EMB*EMB];   // pi^T [c][e]
__device__ __align__(128) h16 g_WqT_h [EMB*EMB];                      // folded [f][c]
__device__ __align__(128) h16 g_wkT_h [EMB*EMB];                      // [f][c]
__device__ __align__(128) h16 g_wvT_h [EMB*EMB];                      // [e][c]
__device__ __align__(128) h16 g_po_h[EMB*2*EMB];                      // [o][k] blocked Kt=1024

__device__ __align__(128) h16 g_Z_h[(long)BATCH*HW*EMB];              // input^T [b][p][c]
__device__ __align__(128) h16 g_ctxT_h[(long)BATCH*LCTX*EMB];         // [b][l][c]
__device__ __align__(128) h16 g_Q_h[(long)BATCH*HW*EMB];
__device__ __align__(128) h16 g_K_h[(long)BATCH*LCTX*EMB];            // [b][l][f]
__device__ __align__(128) h16 g_V_h[(long)BATCH*LCTX*EMB];            // [b][l][e]
__device__ __align__(128) h16 g_E_h[(long)BATCH*HW*LCTX];             // unnormalized exp(S)
__device__ __align__(128) h16 g_W2_h[(long)BATCH*EMB*LCTX];           // po2·V^T [b][o][l]

// ---------------- helpers ----------------
__device__ __forceinline__ uint32_t smem_u32(const void* p) {
    uint32_t r;
    asm("{ .reg .u64 t; cvta.to.shared.u64 t, %1; cvt.u32.u64 %0, t; }" : "=r"(r) : "l"(p));
    return r;
}
__device__ __forceinline__ void mbar_init(uint32_t a, uint32_t c) {
    asm volatile("mbarrier.init.shared.b64 [%0], %1;" :: "r"(a), "r"(c) : "memory");
}
__device__ __forceinline__ void mbar_expect(uint32_t a, uint32_t bytes) {
    asm volatile("mbarrier.arrive.expect_tx.shared.b64 _, [%0], %1;" :: "r"(a), "r"(bytes) : "memory");
}
__device__ __forceinline__ void mbar_wait(uint32_t a, uint32_t par) {
    asm volatile(
        "{\n\t.reg .pred P1;\n\tW%=:\n\t"
        "mbarrier.try_wait.parity.acquire.cta.shared::cta.b64 P1, [%0], %1, 0x989680;\n\t"
        "@P1 bra D%=;\n\tbra W%=;\n\tD%=:\n\t}" :: "r"(a), "r"(par) : "memory");
}
__device__ __forceinline__ void bulk_g2s(uint32_t dst, const void* src, uint32_t bytes, uint32_t bar) {
    asm volatile("cp.async.bulk.shared::cluster.global.mbarrier::complete_tx::bytes [%0], [%1], %2, [%3];"
                 :: "r"(dst), "l"(src), "r"(bytes), "r"(bar) : "memory");
}
__device__ __forceinline__ void ldsm_x4(uint32_t (&r)[4], uint32_t addr) {
    asm volatile("ldmatrix.sync.aligned.m8n8.x4.shared.b16 {%0,%1,%2,%3}, [%4];"
                 : "=r"(r[0]), "=r"(r[1]), "=r"(r[2]), "=r"(r[3]) : "r"(addr));
}
__device__ __forceinline__ void mma16816(float (&d)[4], const uint32_t (&a)[4],
                                         uint32_t b0, uint32_t b1) {
    asm volatile(
        "mma.sync.aligned.m16n8k16.row.col.f32.f16.f16.f32 "
        "{%0,%1,%2,%3}, {%4,%5,%6,%7}, {%8,%9}, {%0,%1,%2,%3};"
        : "+f"(d[0]), "+f"(d[1]), "+f"(d[2]), "+f"(d[3])
        : "r"(a[0]), "r"(a[1]), "r"(a[2]), "r"(a[3]), "r"(b0), "r"(b1));
}
__device__ __forceinline__ uint32_t pack2(h16 a, h16 b) {
    return (uint32_t)__half_as_ushort(a) | ((uint32_t)__half_as_ushort(b) << 16);
}
__device__ __forceinline__ long blk_off(int row, int k, int Kt) {
    long blk = (long)(row >> 7) * (Kt >> 6) + (k >> 6);
    uint32_t off = (uint32_t)((row & 127) * 128 + (k & 63) * 2);
    off ^= (off >> 3) & 0x70;
    return blk * BLK_ELEMS + (off >> 1);
}
__device__ __forceinline__ uint32_t swz_row(int r, int kbyte) {
    uint32_t o = (uint32_t)(r * 128 + kbyte);
    return o ^ ((o >> 3) & 0x70);
}

// ---------------- blocked fp16 GEMM ----------------
// OUT: 0 = fp32 write, 1 = h-plane blocked, 3 = fp32 accumulate scaled by scaleN[n]
// NT:  1 or 3 emulation terms
// EPI: 0 = normal, 1 = exp + row-sum atomics (uses Cf as row-sum buffer, sC = per-batch row stride)
template <int OUT, int NT, int EPI>
__global__ void __launch_bounds__(256, 2)
gemm_blk(const h16* __restrict__ Ah, const h16* __restrict__ Al, int KtA, long sA,
         const h16* __restrict__ Bh, const h16* __restrict__ Bl, int KtB, long sB,
         float* __restrict__ Cf, h16* __restrict__ Ch,
         int ldKtC, long sC, int cOff,
         int K, float alpha, const float* __restrict__ biasM, const float* __restrict__ biasN)
{
    constexpr int NBLK = (NT == 3) ? 4 : 2;
    constexpr uint32_t STAGE = NBLK * BLK_BYTES;

    extern __shared__ __align__(128) char smem[];
    __shared__ __align__(8) uint64_t barsto[NSTAGE];

    const int tid = threadIdx.x, wid = tid >> 5, lane = tid & 31;
    const int b = blockIdx.z;
    const int m0 = blockIdx.y * 128, n0 = blockIdx.x * 128;
    const int wm = (wid & 3) * 32;
    const int wn = (wid >> 2) * 64;

    const h16* pAh = Ah + (long)b * sA + (long)(m0 >> 7) * (KtA >> 6) * BLK_ELEMS;
    const h16* pBh = Bh + (long)b * sB + (long)(n0 >> 7) * (KtB >> 6) * BLK_ELEMS;
    const h16* pAl = (NT == 3) ? Al + (long)b * sA + (long)(m0 >> 7) * (KtA >> 6) * BLK_ELEMS : nullptr;
    const h16* pBl = (NT == 3) ? Bl + (long)b * sB + (long)(n0 >> 7) * (KtB >> 6) * BLK_ELEMS : nullptr;

    const uint32_t s_base = smem_u32(smem);
    const uint32_t bar0 = smem_u32(barsto);
    const int nch = K >> 6;

    auto issue = [&](int c) {
        const int s = c % NSTAGE;
        const uint32_t sb = s_base + (uint32_t)s * STAGE;
        const uint32_t bar = bar0 + (uint32_t)s * 8;
        mbar_expect(bar, NBLK * BLK_BYTES);
        if (NT == 3) {
            bulk_g2s(sb + 0 * BLK_BYTES, pAh + (long)c * BLK_ELEMS, BLK_BYTES, bar);
            bulk_g2s(sb + 1 * BLK_BYTES, pAl + (long)c * BLK_ELEMS, BLK_BYTES, bar);
            bulk_g2s(sb + 2 * BLK_BYTES, pBh + (long)c * BLK_ELEMS, BLK_BYTES, bar);
            bulk_g2s(sb + 3 * BLK_BYTES, pBl + (long)c * BLK_ELEMS, BLK_BYTES, bar);
        } else {
            bulk_g2s(sb + 0 * BLK_BYTES, pAh + (long)c * BLK_ELEMS, BLK_BYTES, bar);
            bulk_g2s(sb + 1 * BLK_BYTES, pBh + (long)c * BLK_ELEMS, BLK_BYTES, bar);
        }
    };

    if (tid == 0) {
        for (int s = 0; s < NSTAGE; s++) mbar_init(bar0 + s * 8, 1);
        asm volatile("fence.proxy.async.shared::cta;" ::: "memory");
        const int pre = nch < NSTAGE ? nch : NSTAGE;
        for (int c = 0; c < pre; c++) issue(c);
    }
    __syncthreads();

    float acc[2][8][4];
#pragma unroll
    for (int i = 0; i < 2; i++)
#pragma unroll
        for (int j = 0; j < 8; j++)
#pragma unroll
            for (int q = 0; q < 4; q++) acc[i][j][q] = 0.f;

    const int lrow = lane & 15;
    const int lkby = ((lane >> 4) * 8) * 2;
    const uint32_t boff = (NT == 3) ? 2 * BLK_BYTES : 1 * BLK_BYTES;

    for (int c = 0; c < nch; c++) {
        const int s = c % NSTAGE;
        mbar_wait(bar0 + s * 8, (uint32_t)((c / NSTAGE) & 1));
        const uint32_t sb = s_base + (uint32_t)s * STAGE;

#pragma unroll
        for (int ks = 0; ks < 4; ks++) {
            const int kb = ks * 32 + lkby;
            uint32_t ah[2][4], al[2][4];
#pragma unroll
            for (int i = 0; i < 2; i++) {
                uint32_t o = swz_row(wm + i * 16 + lrow, kb);
                ldsm_x4(ah[i], sb + o);
                if (NT == 3) ldsm_x4(al[i], sb + BLK_BYTES + o);
            }
            uint32_t bh[4][4], bl[4][4];
#pragma unroll
            for (int jj = 0; jj < 4; jj++) {
                uint32_t o = swz_row(wn + jj * 16 + lrow, kb);
                ldsm_x4(bh[jj], sb + boff + o);
                if (NT == 3) ldsm_x4(bl[jj], sb + 3 * BLK_BYTES + o);
            }
#pragma unroll
            for (int t = 0; t < NT; t++) {
#pragma unroll
                for (int i = 0; i < 2; i++) {
#pragma unroll
                    for (int j = 0; j < 8; j++) {
                        const int jj = j >> 1, sel = j & 1;
                        if (t == 0)
                            mma16816(acc[i][j], ah[i], bh[jj][sel], bh[jj][sel + 2]);
                        else if (t == 1)
                            mma16816(acc[i][j], ah[i], bl[jj][sel], bl[jj][sel + 2]);
                        else
                            mma16816(acc[i][j], al[i], bh[jj][sel], bh[jj][sel + 2]);
                    }
                }
            }
        }
        __syncthreads();
        if (tid == 0 && c + NSTAGE < nch) issue(c + NSTAGE);
    }

    // ---------------- epilogue ----------------
    const int mrow = m0 + wm + (lane >> 2);
    const int ncol0 = n0 + wn + 2 * (lane & 3);

    if (EPI == 1) {
        // exp + write unnormalized E + row-sum atomics (Cf = row sums, sC = rows/batch)
        h16* ch = Ch + (long)b * sC * 0 /*unused*/;
        ch = Ch + (long)b * ((long)HW * LCTX);
        float rs[2][2] = {{0.f, 0.f}, {0.f, 0.f}};
#pragma unroll
        for (int i = 0; i < 2; i++) {
            const int m = mrow + i * 16;
#pragma unroll
            for (int j = 0; j < 8; j++) {
                const int n = ncol0 + j * 8;
                float e0 = __expf(alpha * acc[i][j][0]);
                float e1 = __expf(alpha * acc[i][j][1]);
                float e2 = __expf(alpha * acc[i][j][2]);
                float e3 = __expf(alpha * acc[i][j][3]);
                *reinterpret_cast<uint32_t*>(ch + blk_off(m,     n, ldKtC)) =
                    pack2(__float2half_rn(e0), __float2half_rn(e1));
                *reinterpret_cast<uint32_t*>(ch + blk_off(m + 8, n, ldKtC)) =
                    pack2(__float2half_rn(e2), __float2half_rn(e3));
                rs[i][0] += e0 + e1;
                rs[i][1] += e2 + e3;
            }
        }
#pragma unroll
        for (int i = 0; i < 2; i++)
#pragma unroll
            for (int hh = 0; hh < 2; hh++) {
                float v = rs[i][hh];
                v += __shfl_xor_sync(0xFFFFFFFFu, v, 1);
                v += __shfl_xor_sync(0xFFFFFFFFu, v, 2);
                rs[i][hh] = v;
            }
        if ((lane & 3) == 0) {
            float* sums = Cf + (long)b * sC;
#pragma unroll
            for (int i = 0; i < 2; i++) {
                atomicAdd(&sums[mrow + i * 16],     rs[i][0]);
                atomicAdd(&sums[mrow + i * 16 + 8], rs[i][1]);
            }
        }
        return;
    }

#pragma unroll
    for (int i = 0; i < 2; i++) {
        const int m = mrow + i * 16;
        const float bm0 = biasM ? biasM[m] : 0.f;
        const float bm8 = biasM ? biasM[m + 8] : 0.f;
#pragma unroll
        for (int j = 0; j < 8; j++) {
            const int n = ncol0 + j * 8;
            float v0, v1, v2, v3;
            if (OUT == 3) {
                const float* sn = biasN + (long)b * HW;
                const float s0 = sn[n], s1 = sn[n + 1];
                v0 = acc[i][j][0] * s0;
                v1 = acc[i][j][1] * s1;
                v2 = acc[i][j][2] * s0;
                v3 = acc[i][j][3] * s1;
            } else {
                const float bn0 = biasN ? biasN[n] : 0.f;
                const float bn1 = biasN ? biasN[n + 1] : 0.f;
                v0 = alpha * acc[i][j][0] + bm0 + bn0;
                v1 = alpha * acc[i][j][1] + bm0 + bn1;
                v2 = alpha * acc[i][j][2] + bm8 + bn0;
                v3 = alpha * acc[i][j][3] + bm8 + bn1;
            }
            if (OUT == 0 || OUT == 3) {
                float* co = Cf + (long)b * sC;
                float2* p0 = reinterpret_cast<float2*>(co + (long)m * ldKtC + n);
                float2* p8 = reinterpret_cast<float2*>(co + (long)(m + 8) * ldKtC + n);
                if (OUT == 3) {
                    float2 o0 = *p0, o8 = *p8;
                    v0 += o0.x; v1 += o0.y; v2 += o8.x; v3 += o8.y;
                }
                *p0 = make_float2(v0, v1);
                *p8 = make_float2(v2, v3);
            } else {
                h16* ch = Ch + (long)b * sC;
                *reinterpret_cast<uint32_t*>(ch + blk_off(m,     n + cOff, ldKtC)) =
                    pack2(__float2half_rn(v0), __float2half_rn(v1));
                *reinterpret_cast<uint32_t*>(ch + blk_off(m + 8, n + cOff, ldKtC)) =
                    pack2(__float2half_rn(v2), __float2half_rn(v3));
            }
        }
    }
}

// ---------------- aux kernels ----------------
struct TJob { const float* s; h16* dh; h16* dl; };

__global__ void trans4_kernel(TJob j0, TJob j1, TJob j2, TJob j3)
{
    __shared__ float t[32][33];
    TJob j = (blockIdx.z == 0) ? j0 : (blockIdx.z == 1) ? j1 : (blockIdx.z == 2) ? j2 : j3;
    const int c0 = blockIdx.x * 32, r0 = blockIdx.y * 32;
    const int tx = threadIdx.x, ty = threadIdx.y;
#pragma unroll
    for (int k = 0; k < 4; k++)
        t[ty + 8*k][tx] = j.s[(long)(r0 + ty + 8*k) * EMB + c0 + tx];
    __syncthreads();
#pragma unroll
    for (int k = 0; k < 4; k++) {
        float x = t[tx][ty + 8*k];
        h16 h = __float2half_rn(x);
        long o = blk_off(c0 + ty + 8*k, r0 + tx, EMB);
        j.dh[o] = h;
        if (j.dl) j.dl[o] = __float2half_rn(x - __half2float(h));
    }
}

__global__ void trans_convert_kernel(const float* __restrict__ src, long sstride, int src_ld,
                                     h16* __restrict__ dh, long dstride, int KtD)
{
    __shared__ float t[32][33];
    const float* S = src + (long)blockIdx.z * sstride;
    h16* DH = dh + (long)blockIdx.z * dstride;
    const int c0 = blockIdx.x * 32, r0 = blockIdx.y * 32;
    const int tx = threadIdx.x, ty = threadIdx.y;
#pragma unroll
    for (int k = 0; k < 4; k++)
        t[ty + 8*k][tx] = S[(long)(r0 + ty + 8*k) * src_ld + c0 + tx];
    __syncthreads();
#pragma unroll
    for (int k = 0; k < 4; k++) {
        float x = t[tx][ty + 8*k];
        DH[blk_off(c0 + ty + 8*k, r0 + tx, KtD)] = __float2half_rn(x);
    }
}

__global__ void convert_h_kernel(const float* __restrict__ s, h16* __restrict__ dh,
                                 int Kt, int n)
{
    int i = blockIdx.x * blockDim.x + threadIdx.x;
    if (i >= n) return;
    dh[blk_off(i / Kt, i % Kt, Kt)] = __float2half_rn(s[i]);
}

__global__ void fold_bias_kernel(const float* __restrict__ pib, const float* __restrict__ wq,
                                 const float* __restrict__ wqb, float* __restrict__ out)
{
    int f = blockIdx.x * blockDim.x + threadIdx.x;
    if (f >= EMB) return;
    float s = wqb[f];
    for (int e = 0; e < EMB; e++) s = fmaf(pib[e], wq[e * EMB + f], s);
    out[f] = s;
}

__global__ void zero_kernel(float* __restrict__ p, int n)
{
    int i = blockIdx.x * blockDim.x + threadIdx.x;
    if (i < n) p[i] = 0.f;
}
__global__ void invert_kernel(float* __restrict__ p, int n)
{
    int i = blockIdx.x * blockDim.x + threadIdx.x;
    if (i < n) p[i] = 1.0f / p[i];
}

// ---------------- launch ----------------
extern "C" void kernel_launch(void* const* d_in, const int* in_sizes, int n_in,
                              void* d_out, int out_size)
{
    const float* input      = (const float*)d_in[0];
    const float* context    = (const float*)d_in[1];
    const float* proj_in_w  = (const float*)d_in[2];
    const float* proj_in_b  = (const float*)d_in[3];
    const float* wq_w       = (const float*)d_in[4];
    const float* wq_b       = (const float*)d_in[5];
    const float* wk_w       = (const float*)d_in[6];
    const float* wk_b       = (const float*)d_in[7];
    const float* wv_w       = (const float*)d_in[8];
    const float* wv_b       = (const float*)d_in[9];
    const float* proj_out_w = (const float*)d_in[10];
    const float* proj_out_b = (const float*)d_in[11];
    float* out = (float*)d_out;

    const int SMEM3 = NSTAGE * 4 * BLK_BYTES;   // 196608
    const int SMEM1 = NSTAGE * 2 * BLK_BYTES;   // 98304
    cudaFuncSetAttribute(gemm_blk<1,3,0>, cudaFuncAttributeMaxDynamicSharedMemorySize, SMEM3);
    cudaFuncSetAttribute(gemm_blk<0,1,0>, cudaFuncAttributeMaxDynamicSharedMemorySize, SMEM1);
    cudaFuncSetAttribute(gemm_blk<1,1,0>, cudaFuncAttributeMaxDynamicSharedMemorySize, SMEM1);
    cudaFuncSetAttribute(gemm_blk<1,1,1>, cudaFuncAttributeMaxDynamicSharedMemorySize, SMEM1);
    cudaFuncSetAttribute(gemm_blk<3,1,0>, cudaFuncAttributeMaxDynamicSharedMemorySize, SMEM1);

    float *bq, *rsum;
    h16 *wqT0h,*wqT0l,*piTh,*piTl,*WqTh,*wkTh,*wvTh,*poh;
    h16 *Zh,*cth,*Qh,*Kh,*Vh,*Eh,*W2h;
    cudaGetSymbolAddress((void**)&bq, g_bq);
    cudaGetSymbolAddress((void**)&rsum, g_rsum);
    cudaGetSymbolAddress((void**)&wqT0h, g_wqT0_h);  cudaGetSymbolAddress((void**)&wqT0l, g_wqT0_l);
    cudaGetSymbolAddress((void**)&piTh, g_piT_h);    cudaGetSymbolAddress((void**)&piTl, g_piT_l);
    cudaGetSymbolAddress((void**)&WqTh, g_WqT_h);
    cudaGetSymbolAddress((void**)&wkTh, g_wkT_h);
    cudaGetSymbolAddress((void**)&wvTh, g_wvT_h);
    cudaGetSymbolAddress((void**)&poh, g_po_h);
    cudaGetSymbolAddress((void**)&Zh, g_Z_h);
    cudaGetSymbolAddress((void**)&cth, g_ctxT_h);
    cudaGetSymbolAddress((void**)&Qh, g_Q_h);        cudaGetSymbolAddress((void**)&Kh, g_K_h);
    cudaGetSymbolAddress((void**)&Vh, g_V_h);        cudaGetSymbolAddress((void**)&Eh, g_E_h);
    cudaGetSymbolAddress((void**)&W2h, g_W2_h);

    const float scale = 1.0f / sqrtf((float)EMB);
    dim3 tb(32, 8);

    // ---- prep ----
    fold_bias_kernel<<<2, 256>>>(proj_in_b, wq_w, wq_b, bq);
    zero_kernel<<<(BATCH*HW)/256, 256>>>(rsum, BATCH*HW);
    {
        TJob j0{wq_w, wqT0h, wqT0l}, j1{proj_in_w, piTh, piTl},
             j2{wk_w, wkTh, nullptr}, j3{wv_w, wvTh, nullptr};
        trans4_kernel<<<dim3(16,16,4), tb>>>(j0, j1, j2, j3);
    }
    convert_h_kernel<<<(EMB*2*EMB)/256, 256>>>(proj_out_w, poh, 2*EMB, EMB*2*EMB);
    trans_convert_kernel<<<dim3(32,16,BATCH), tb>>>(context, (long)EMB*LCTX, LCTX,
                                                    cth, (long)LCTX*EMB, EMB);
    trans_convert_kernel<<<dim3(128,16,BATCH), tb>>>(input, (long)EMB*HW, HW,
                                                     Zh, (long)HW*EMB, EMB);

    // ---- GEMMs ----
    // fold: WqT[f][c] = wqT0 · piT^T (3-term)
    gemm_blk<1,3,0><<<dim3(4,4,1), 256, SMEM3>>>(
        wqT0h, wqT0l, EMB, 0, piTh, piTl, EMB, 0,
        nullptr, WqTh, EMB, 0, 0, EMB, 1.0f, nullptr, nullptr);
    // K[l][f] = ctxT · wkT^T + wk_b
    gemm_blk<1,1,0><<<dim3(4,8,BATCH), 256, SMEM1>>>(
        cth, nullptr, EMB, (long)LCTX*EMB, wkTh, nullptr, EMB, 0,
        nullptr, Kh, EMB, (long)LCTX*EMB, 0, EMB, 1.0f, nullptr, wk_b);
    // V[l][e] = ctxT · wvT^T + wv_b
    gemm_blk<1,1,0><<<dim3(4,8,BATCH), 256, SMEM1>>>(
        cth, nullptr, EMB, (long)LCTX*EMB, wvTh, nullptr, EMB, 0,
        nullptr, Vh, EMB, (long)LCTX*EMB, 0, EMB, 1.0f, nullptr, wv_b);
    // out1[o][p] = po1 · Zh^T + proj_out_b  (fp32 write)
    gemm_blk<0,1,0><<<dim3(32,4,BATCH), 256, SMEM1>>>(
        poh, nullptr, 2*EMB, 0, Zh, nullptr, EMB, (long)HW*EMB,
        out, nullptr, HW, (long)EMB*HW, 0, EMB, 1.0f, proj_out_b, nullptr);
    // W2[o][l] = po2 · V^T  (po2 = k-blocks 8..15 of po)
    gemm_blk<1,1,0><<<dim3(8,4,BATCH), 256, SMEM1>>>(
        poh + 8*BLK_ELEMS, nullptr, 2*EMB, 0, Vh, nullptr, EMB, (long)LCTX*EMB,
        nullptr, W2h, LCTX, (long)EMB*LCTX, 0, EMB, 1.0f, nullptr, nullptr);
    // Q[p][f] = Zh · WqT^T + bq
    gemm_blk<1,1,0><<<dim3(4,32,BATCH), 256, SMEM1>>>(
        Zh, nullptr, EMB, (long)HW*EMB, WqTh, nullptr, EMB, 0,
        nullptr, Qh, EMB, (long)HW*EMB, 0, EMB, 1.0f, nullptr, bq);
    // E = exp(scale * Q · K^T), row sums -> rsum (fused epilogue)
    gemm_blk<1,1,1><<<dim3(8,32,BATCH), 256, SMEM1>>>(
        Qh, nullptr, EMB, (long)HW*EMB, Kh, nullptr, EMB, (long)LCTX*EMB,
        rsum, Eh, LCTX, HW, 0, EMB, scale, nullptr, nullptr);
    // invert row sums
    invert_kernel<<<(BATCH*HW)/256, 256>>>(rsum, BATCH*HW);
    // out2[o][p] = (W2 · E^T) * invsum[p], accumulate onto out
    gemm_blk<3,1,0><<<dim3(32,4,BATCH), 256, SMEM1>>>(
        W2h, nullptr, LCTX, (long)EMB*LCTX, Eh, nullptr, LCTX, (long)HW*LCTX,
        out, nullptr, HW, (long)EMB*HW, 0, LCTX, 1.0f, nullptr, rsum);
}

// round 11
// speedup vs baseline: 8.9492x; 1.0643x over previous
#include <cuda_runtime.h>
#include <cuda_fp16.h>
#include <math.h>
#include <stdint.h>

#define BATCH 8
#define HW    4096
#define LCTX  1024
#define EMB   512

typedef __half h16;

// blocked layout: [rowblk][kblk][128x64 swizzled]; 16KB per block
#define BLK_ELEMS 8192
#define BLK_BYTES 16384
#define NSTAGE 3

// ---------------- device scratch ----------------
__device__ __align__(128) float g_bq[EMB];
__device__ __align__(128) float g_rsum[BATCH * HW];
__device__ __align__(128) float g_cvec[BATCH * LCTX];

__device__ __align__(128) h16 g_wqT0_h[EMB*EMB], g_wqT0_l[EMB*EMB];   // wq^T [f][e]
__device__ __align__(128) h16 g_piT_h [EMB*EMB], g_piT_l [EMB*EMB];   // pi^T [c][e]
__device__ __align__(128) h16 g_WqCF_h[EMB*EMB];                      // folded Wq [c][f]
__device__ __align__(128) h16 g_wkT_h [EMB*EMB];                      // [f][c]
__device__ __align__(128) h16 g_wvT_h [EMB*EMB];                      // [e][c]
__device__ __align__(128) h16 g_po_h[EMB*2*EMB];                      // [o][k] blocked Kt=1024

__device__ __align__(128) h16 g_Z_h[(long)BATCH*HW*EMB];              // input^T [b][p][c]
__device__ __align__(128) h16 g_ctxT_h[(long)BATCH*LCTX*EMB];         // [b][l][c]
__device__ __align__(128) h16 g_K_h[(long)BATCH*LCTX*EMB];            // [b][l][f]
__device__ __align__(128) h16 g_K2_h[(long)BATCH*LCTX*EMB];           // K' = K·Wq  [b][l][c]
__device__ __align__(128) h16 g_V_h[(long)BATCH*LCTX*EMB];            // [b][l][e]
__device__ __align__(128) h16 g_E_h[(long)BATCH*HW*LCTX];             // unnormalized exp(S)
__device__ __align__(128) h16 g_W2_h[(long)BATCH*EMB*LCTX];           // po2·V^T [b][o][l]

// ---------------- helpers ----------------
__device__ __forceinline__ uint32_t smem_u32(const void* p) {
    uint32_t r;
    asm("{ .reg .u64 t; cvta.to.shared.u64 t, %1; cvt.u32.u64 %0, t; }" : "=r"(r) : "l"(p));
    return r;
}
__device__ __forceinline__ void mbar_init(uint32_t a, uint32_t c) {
    asm volatile("mbarrier.init.shared.b64 [%0], %1;" :: "r"(a), "r"(c) : "memory");
}
__device__ __forceinline__ void mbar_expect(uint32_t a, uint32_t bytes) {
    asm volatile("mbarrier.arrive.expect_tx.shared.b64 _, [%0], %1;" :: "r"(a), "r"(bytes) : "memory");
}
__device__ __forceinline__ void mbar_wait(uint32_t a, uint32_t par) {
    asm volatile(
        "{\n\t.reg .pred P1;\n\tW%=:\n\t"
        "mbarrier.try_wait.parity.acquire.cta.shared::cta.b64 P1, [%0], %1, 0x989680;\n\t"
        "@P1 bra D%=;\n\tbra W%=;\n\tD%=:\n\t}" :: "r"(a), "r"(par) : "memory");
}
__device__ __forceinline__ void bulk_g2s(uint32_t dst, const void* src, uint32_t bytes, uint32_t bar) {
    asm volatile("cp.async.bulk.shared::cluster.global.mbarrier::complete_tx::bytes [%0], [%1], %2, [%3];"
                 :: "r"(dst), "l"(src), "r"(bytes), "r"(bar) : "memory");
}
__device__ __forceinline__ void ldsm_x4(uint32_t (&r)[4], uint32_t addr) {
    asm volatile("ldmatrix.sync.aligned.m8n8.x4.shared.b16 {%0,%1,%2,%3}, [%4];"
                 : "=r"(r[0]), "=r"(r[1]), "=r"(r[2]), "=r"(r[3]) : "r"(addr));
}
__device__ __forceinline__ void mma16816(float (&d)[4], const uint32_t (&a)[4],
                                         uint32_t b0, uint32_t b1) {
    asm volatile(
        "mma.sync.aligned.m16n8k16.row.col.f32.f16.f16.f32 "
        "{%0,%1,%2,%3}, {%4,%5,%6,%7}, {%8,%9}, {%0,%1,%2,%3};"
        : "+f"(d[0]), "+f"(d[1]), "+f"(d[2]), "+f"(d[3])
        : "r"(a[0]), "r"(a[1]), "r"(a[2]), "r"(a[3]), "r"(b0), "r"(b1));
}
__device__ __forceinline__ uint32_t pack2(h16 a, h16 b) {
    return (uint32_t)__half_as_ushort(a) | ((uint32_t)__half_as_ushort(b) << 16);
}
__device__ __forceinline__ long blk_off(int row, int k, int Kt) {
    long blk = (long)(row >> 7) * (Kt >> 6) + (k >> 6);
    uint32_t off = (uint32_t)((row & 127) * 128 + (k & 63) * 2);
    off ^= (off >> 3) & 0x70;
    return blk * BLK_ELEMS + (off >> 1);
}
__device__ __forceinline__ uint32_t swz_row(int r, int kbyte) {
    uint32_t o = (uint32_t)(r * 128 + kbyte);
    return o ^ ((o >> 3) & 0x70);
}

// ---------------- blocked fp16 GEMM ----------------
// OUT: 0 = fp32 write, 1 = h-plane blocked, 3 = fp32 accumulate scaled by scaleN[n] (biasN, batch-strided HW)
// NT:  1 or 3 emulation terms
// EPI: 0 = normal
//      1 = exp(alpha*(acc + biasN[b-strided LCTX])) + row-sum atomics into Cf (b-stride HW)
//      2 = normal blocked write (+biasN) AND weighted row-sum sum_n biasM[n]*v -> atomics into Cf (b-stride LCTX)
template <int OUT, int NT, int EPI>
__global__ void __launch_bounds__(256, 2)
gemm_blk(const h16* __restrict__ Ah, const h16* __restrict__ Al, int KtA, long sA,
         const h16* __restrict__ Bh, const h16* __restrict__ Bl, int KtB, long sB,
         float* __restrict__ Cf, h16* __restrict__ Ch,
         int ldKtC, long sC, int cOff,
         int K, float alpha, const float* __restrict__ biasM, const float* __restrict__ biasN)
{
    constexpr int NBLK = (NT == 3) ? 4 : 2;
    constexpr uint32_t STAGE = NBLK * BLK_BYTES;

    extern __shared__ __align__(128) char smem[];
    __shared__ __align__(8) uint64_t barsto[NSTAGE];

    const int tid = threadIdx.x, wid = tid >> 5, lane = tid & 31;
    const int b = blockIdx.z;
    const int m0 = blockIdx.y * 128, n0 = blockIdx.x * 128;
    const int wm = (wid & 3) * 32;
    const int wn = (wid >> 2) * 64;

    const h16* pAh = Ah + (long)b * sA + (long)(m0 >> 7) * (KtA >> 6) * BLK_ELEMS;
    const h16* pBh = Bh + (long)b * sB + (long)(n0 >> 7) * (KtB >> 6) * BLK_ELEMS;
    const h16* pAl = (NT == 3) ? Al + (long)b * sA + (long)(m0 >> 7) * (KtA >> 6) * BLK_ELEMS : nullptr;
    const h16* pBl = (NT == 3) ? Bl + (long)b * sB + (long)(n0 >> 7) * (KtB >> 6) * BLK_ELEMS : nullptr;

    const uint32_t s_base = smem_u32(smem);
    const uint32_t bar0 = smem_u32(barsto);
    const int nch = K >> 6;

    auto issue = [&](int c) {
        const int s = c % NSTAGE;
        const uint32_t sb = s_base + (uint32_t)s * STAGE;
        const uint32_t bar = bar0 + (uint32_t)s * 8;
        mbar_expect(bar, NBLK * BLK_BYTES);
        if (NT == 3) {
            bulk_g2s(sb + 0 * BLK_BYTES, pAh + (long)c * BLK_ELEMS, BLK_BYTES, bar);
            bulk_g2s(sb + 1 * BLK_BYTES, pAl + (long)c * BLK_ELEMS, BLK_BYTES, bar);
            bulk_g2s(sb + 2 * BLK_BYTES, pBh + (long)c * BLK_ELEMS, BLK_BYTES, bar);
            bulk_g2s(sb + 3 * BLK_BYTES, pBl + (long)c * BLK_ELEMS, BLK_BYTES, bar);
        } else {
            bulk_g2s(sb + 0 * BLK_BYTES, pAh + (long)c * BLK_ELEMS, BLK_BYTES, bar);
            bulk_g2s(sb + 1 * BLK_BYTES, pBh + (long)c * BLK_ELEMS, BLK_BYTES, bar);
        }
    };

    if (tid == 0) {
        for (int s = 0; s < NSTAGE; s++) mbar_init(bar0 + s * 8, 1);
        asm volatile("fence.proxy.async.shared::cta;" ::: "memory");
        const int pre = nch < NSTAGE ? nch : NSTAGE;
        for (int c = 0; c < pre; c++) issue(c);
    }
    __syncthreads();

    float acc[2][8][4];
#pragma unroll
    for (int i = 0; i < 2; i++)
#pragma unroll
        for (int j = 0; j < 8; j++)
#pragma unroll
            for (int q = 0; q < 4; q++) acc[i][j][q] = 0.f;

    const int lrow = lane & 15;
    const int lkby = ((lane >> 4) * 8) * 2;
    const uint32_t boff = (NT == 3) ? 2 * BLK_BYTES : 1 * BLK_BYTES;

    for (int c = 0; c < nch; c++) {
        const int s = c % NSTAGE;
        mbar_wait(bar0 + s * 8, (uint32_t)((c / NSTAGE) & 1));
        const uint32_t sb = s_base + (uint32_t)s * STAGE;

#pragma unroll
        for (int ks = 0; ks < 4; ks++) {
            const int kb = ks * 32 + lkby;
            uint32_t ah[2][4], al[2][4];
#pragma unroll
            for (int i = 0; i < 2; i++) {
                uint32_t o = swz_row(wm + i * 16 + lrow, kb);
                ldsm_x4(ah[i], sb + o);
                if (NT == 3) ldsm_x4(al[i], sb + BLK_BYTES + o);
            }
            uint32_t bh[4][4], bl[4][4];
#pragma unroll
            for (int jj = 0; jj < 4; jj++) {
                uint32_t o = swz_row(wn + jj * 16 + lrow, kb);
                ldsm_x4(bh[jj], sb + boff + o);
                if (NT == 3) ldsm_x4(bl[jj], sb + 3 * BLK_BYTES + o);
            }
#pragma unroll
            for (int t = 0; t < NT; t++) {
#pragma unroll
                for (int i = 0; i < 2; i++) {
#pragma unroll
                    for (int j = 0; j < 8; j++) {
                        const int jj = j >> 1, sel = j & 1;
                        if (t == 0)
                            mma16816(acc[i][j], ah[i], bh[jj][sel], bh[jj][sel + 2]);
                        else if (t == 1)
                            mma16816(acc[i][j], ah[i], bl[jj][sel], bl[jj][sel + 2]);
                        else
                            mma16816(acc[i][j], al[i], bh[jj][sel], bh[jj][sel + 2]);
                    }
                }
            }
        }
        __syncthreads();
        if (tid == 0 && c + NSTAGE < nch) issue(c + NSTAGE);
    }

    // ---------------- epilogue ----------------
    const int mrow = m0 + wm + (lane >> 2);
    const int ncol0 = n0 + wn + 2 * (lane & 3);

    if (EPI == 1) {
        // E = exp(alpha*(acc + cvec[n])), unnormalized; row sums -> Cf (b-stride HW)
        h16* ch = Ch + (long)b * sC;
        const float* cv = biasN + (long)b * LCTX;
        float rs[2][2] = {{0.f, 0.f}, {0.f, 0.f}};
#pragma unroll
        for (int i = 0; i < 2; i++) {
            const int m = mrow + i * 16;
#pragma unroll
            for (int j = 0; j < 8; j++) {
                const int n = ncol0 + j * 8;
                const float c0 = cv[n], c1 = cv[n + 1];
                float e0 = __expf(alpha * (acc[i][j][0] + c0));
                float e1 = __expf(alpha * (acc[i][j][1] + c1));
                float e2 = __expf(alpha * (acc[i][j][2] + c0));
                float e3 = __expf(alpha * (acc[i][j][3] + c1));
                *reinterpret_cast<uint32_t*>(ch + blk_off(m,     n, ldKtC)) =
                    pack2(__float2half_rn(e0), __float2half_rn(e1));
                *reinterpret_cast<uint32_t*>(ch + blk_off(m + 8, n, ldKtC)) =
                    pack2(__float2half_rn(e2), __float2half_rn(e3));
                rs[i][0] += e0 + e1;
                rs[i][1] += e2 + e3;
            }
        }
#pragma unroll
        for (int i = 0; i < 2; i++)
#pragma unroll
            for (int hh = 0; hh < 2; hh++) {
                float v = rs[i][hh];
                v += __shfl_xor_sync(0xFFFFFFFFu, v, 1);
                v += __shfl_xor_sync(0xFFFFFFFFu, v, 2);
                rs[i][hh] = v;
            }
        if ((lane & 3) == 0) {
            float* sums = Cf + (long)b * HW;
#pragma unroll
            for (int i = 0; i < 2; i++) {
                atomicAdd(&sums[mrow + i * 16],     rs[i][0]);
                atomicAdd(&sums[mrow + i * 16 + 8], rs[i][1]);
            }
        }
        return;
    }

    if (EPI == 2) {
        // blocked fp16 write (v = acc + biasN) AND c[m] += sum_n biasM[n]*v  (b-stride LCTX)
        h16* ch = Ch + (long)b * sC;
        float ws[2][2] = {{0.f, 0.f}, {0.f, 0.f}};
#pragma unroll
        for (int i = 0; i < 2; i++) {
            const int m = mrow + i * 16;
#pragma unroll
            for (int j = 0; j < 8; j++) {
                const int n = ncol0 + j * 8;
                const float bn0 = biasN ? biasN[n] : 0.f;
                const float bn1 = biasN ? biasN[n + 1] : 0.f;
                float v0 = acc[i][j][0] + bn0;
                float v1 = acc[i][j][1] + bn1;
                float v2 = acc[i][j][2] + bn0;
                float v3 = acc[i][j][3] + bn1;
                *reinterpret_cast<uint32_t*>(ch + blk_off(m,     n, ldKtC)) =
                    pack2(__float2half_rn(v0), __float2half_rn(v1));
                *reinterpret_cast<uint32_t*>(ch + blk_off(m + 8, n, ldKtC)) =
                    pack2(__float2half_rn(v2), __float2half_rn(v3));
                const float w0 = biasM[n], w1 = biasM[n + 1];
                ws[i][0] += w0 * v0 + w1 * v1;
                ws[i][1] += w0 * v2 + w1 * v3;
            }
        }
#pragma unroll
        for (int i = 0; i < 2; i++)
#pragma unroll
            for (int hh = 0; hh < 2; hh++) {
                float v = ws[i][hh];
                v += __shfl_xor_sync(0xFFFFFFFFu, v, 1);
                v += __shfl_xor_sync(0xFFFFFFFFu, v, 2);
                ws[i][hh] = v;
            }
        if ((lane & 3) == 0) {
            float* cv = Cf + (long)b * LCTX;
#pragma unroll
            for (int i = 0; i < 2; i++) {
                atomicAdd(&cv[mrow + i * 16],     ws[i][0]);
                atomicAdd(&cv[mrow + i * 16 + 8], ws[i][1]);
            }
        }
        return;
    }

#pragma unroll
    for (int i = 0; i < 2; i++) {
        const int m = mrow + i * 16;
        const float bm0 = biasM ? biasM[m] : 0.f;
        const float bm8 = biasM ? biasM[m + 8] : 0.f;
#pragma unroll
        for (int j = 0; j < 8; j++) {
            const int n = ncol0 + j * 8;
            float v0, v1, v2, v3;
            if (OUT == 3) {
                const float* sn = biasN + (long)b * HW;
                const float s0 = sn[n], s1 = sn[n + 1];
                v0 = acc[i][j][0] * s0;
                v1 = acc[i][j][1] * s1;
                v2 = acc[i][j][2] * s0;
                v3 = acc[i][j][3] * s1;
            } else {
                const float bn0 = biasN ? biasN[n] : 0.f;
                const float bn1 = biasN ? biasN[n + 1] : 0.f;
                v0 = alpha * acc[i][j][0] + bm0 + bn0;
                v1 = alpha * acc[i][j][1] + bm0 + bn1;
                v2 = alpha * acc[i][j][2] + bm8 + bn0;
                v3 = alpha * acc[i][j][3] + bm8 + bn1;
            }
            if (OUT == 0 || OUT == 3) {
                float* co = Cf + (long)b * sC;
                float2* p0 = reinterpret_cast<float2*>(co + (long)m * ldKtC + n);
                float2* p8 = reinterpret_cast<float2*>(co + (long)(m + 8) * ldKtC + n);
                if (OUT == 3) {
                    float2 o0 = *p0, o8 = *p8;
                    v0 += o0.x; v1 += o0.y; v2 += o8.x; v3 += o8.y;
                }
                *p0 = make_float2(v0, v1);
                *p8 = make_float2(v2, v3);
            } else {
                h16* ch = Ch + (long)b * sC;
                *reinterpret_cast<uint32_t*>(ch + blk_off(m,     n + cOff, ldKtC)) =
                    pack2(__float2half_rn(v0), __float2half_rn(v1));
                *reinterpret_cast<uint32_t*>(ch + blk_off(m + 8, n + cOff, ldKtC)) =
                    pack2(__float2half_rn(v2), __float2half_rn(v3));
            }
        }
    }
}

// ---------------- aux kernels ----------------
struct TJob { const float* s; h16* dh; h16* dl; };

__global__ void trans4_kernel(TJob j0, TJob j1, TJob j2, TJob j3)
{
    __shared__ float t[32][33];
    TJob j = (blockIdx.z == 0) ? j0 : (blockIdx.z == 1) ? j1 : (blockIdx.z == 2) ? j2 : j3;
    const int c0 = blockIdx.x * 32, r0 = blockIdx.y * 32;
    const int tx = threadIdx.x, ty = threadIdx.y;
#pragma unroll
    for (int k = 0; k < 4; k++)
        t[ty + 8*k][tx] = j.s[(long)(r0 + ty + 8*k) * EMB + c0 + tx];
    __syncthreads();
#pragma unroll
    for (int k = 0; k < 4; k++) {
        float x = t[tx][ty + 8*k];
        h16 h = __float2half_rn(x);
        long o = blk_off(c0 + ty + 8*k, r0 + tx, EMB);
        j.dh[o] = h;
        if (j.dl) j.dl[o] = __float2half_rn(x - __half2float(h));
    }
}

__global__ void trans_convert_kernel(const float* __restrict__ src, long sstride, int src_ld,
                                     h16* __restrict__ dh, long dstride, int KtD)
{
    __shared__ float t[32][33];
    const float* S = src + (long)blockIdx.z * sstride;
    h16* DH = dh + (long)blockIdx.z * dstride;
    const int c0 = blockIdx.x * 32, r0 = blockIdx.y * 32;
    const int tx = threadIdx.x, ty = threadIdx.y;
#pragma unroll
    for (int k = 0; k < 4; k++)
        t[ty + 8*k][tx] = S[(long)(r0 + ty + 8*k) * src_ld + c0 + tx];
    __syncthreads();
#pragma unroll
    for (int k = 0; k < 4; k++) {
        float x = t[tx][ty + 8*k];
        DH[blk_off(c0 + ty + 8*k, r0 + tx, KtD)] = __float2half_rn(x);
    }
}

__global__ void convert_h_kernel(const float* __restrict__ s, h16* __restrict__ dh,
                                 int Kt, int n)
{
    int i = blockIdx.x * blockDim.x + threadIdx.x;
    if (i >= n) return;
    dh[blk_off(i / Kt, i % Kt, Kt)] = __float2half_rn(s[i]);
}

__global__ void fold_bias_kernel(const float* __restrict__ pib, const float* __restrict__ wq,
                                 const float* __restrict__ wqb, float* __restrict__ out)
{
    int f = blockIdx.x * blockDim.x + threadIdx.x;
    if (f >= EMB) return;
    float s = wqb[f];
    for (int e = 0; e < EMB; e++) s = fmaf(pib[e], wq[e * EMB + f], s);
    out[f] = s;
}

__global__ void zero2_kernel(float* __restrict__ p, int n, float* __restrict__ q, int nq)
{
    int i = blockIdx.x * blockDim.x + threadIdx.x;
    if (i < n) p[i] = 0.f;
    if (i < nq) q[i] = 0.f;
}
__global__ void invert_kernel(float* __restrict__ p, int n)
{
    int i = blockIdx.x * blockDim.x + threadIdx.x;
    if (i < n) p[i] = 1.0f / p[i];
}

// ---------------- launch ----------------
extern "C" void kernel_launch(void* const* d_in, const int* in_sizes, int n_in,
                              void* d_out, int out_size)
{
    const float* input      = (const float*)d_in[0];
    const float* context    = (const float*)d_in[1];
    const float* proj_in_w  = (const float*)d_in[2];
    const float* proj_in_b  = (const float*)d_in[3];
    const float* wq_w       = (const float*)d_in[4];
    const float* wq_b       = (const float*)d_in[5];
    const float* wk_w       = (const float*)d_in[6];
    const float* wk_b       = (const float*)d_in[7];
    const float* wv_w       = (const float*)d_in[8];
    const float* wv_b       = (const float*)d_in[9];
    const float* proj_out_w = (const float*)d_in[10];
    const float* proj_out_b = (const float*)d_in[11];
    float* out = (float*)d_out;

    const int SMEM3 = NSTAGE * 4 * BLK_BYTES;   // 196608
    const int SMEM1 = NSTAGE * 2 * BLK_BYTES;   // 98304
    cudaFuncSetAttribute(gemm_blk<1,3,0>, cudaFuncAttributeMaxDynamicSharedMemorySize, SMEM3);
    cudaFuncSetAttribute(gemm_blk<0,1,0>, cudaFuncAttributeMaxDynamicSharedMemorySize, SMEM1);
    cudaFuncSetAttribute(gemm_blk<1,1,0>, cudaFuncAttributeMaxDynamicSharedMemorySize, SMEM1);
    cudaFuncSetAttribute(gemm_blk<1,1,1>, cudaFuncAttributeMaxDynamicSharedMemorySize, SMEM1);
    cudaFuncSetAttribute(gemm_blk<1,1,2>, cudaFuncAttributeMaxDynamicSharedMemorySize, SMEM1);
    cudaFuncSetAttribute(gemm_blk<3,1,0>, cudaFuncAttributeMaxDynamicSharedMemorySize, SMEM1);

    float *bq, *rsum, *cvec;
    h16 *wqT0h,*wqT0l,*piTh,*piTl,*WqCFh,*wkTh,*wvTh,*poh;
    h16 *Zh,*cth,*Kh,*K2h,*Vh,*Eh,*W2h;
    cudaGetSymbolAddress((void**)&bq, g_bq);
    cudaGetSymbolAddress((void**)&rsum, g_rsum);
    cudaGetSymbolAddress((void**)&cvec, g_cvec);
    cudaGetSymbolAddress((void**)&wqT0h, g_wqT0_h);  cudaGetSymbolAddress((void**)&wqT0l, g_wqT0_l);
    cudaGetSymbolAddress((void**)&piTh, g_piT_h);    cudaGetSymbolAddress((void**)&piTl, g_piT_l);
    cudaGetSymbolAddress((void**)&WqCFh, g_WqCF_h);
    cudaGetSymbolAddress((void**)&wkTh, g_wkT_h);
    cudaGetSymbolAddress((void**)&wvTh, g_wvT_h);
    cudaGetSymbolAddress((void**)&poh, g_po_h);
    cudaGetSymbolAddress((void**)&Zh, g_Z_h);
    cudaGetSymbolAddress((void**)&cth, g_ctxT_h);
    cudaGetSymbolAddress((void**)&Kh, g_K_h);        cudaGetSymbolAddress((void**)&K2h, g_K2_h);
    cudaGetSymbolAddress((void**)&Vh, g_V_h);        cudaGetSymbolAddress((void**)&Eh, g_E_h);
    cudaGetSymbolAddress((void**)&W2h, g_W2_h);

    const float scale = 1.0f / sqrtf((float)EMB);
    dim3 tb(32, 8);

    // ---- prep ----
    fold_bias_kernel<<<2, 256>>>(proj_in_b, wq_w, wq_b, bq);
    zero2_kernel<<<(BATCH*HW)/256, 256>>>(rsum, BATCH*HW, cvec, BATCH*LCTX);
    {
        TJob j0{wq_w, wqT0h, wqT0l}, j1{proj_in_w, piTh, piTl},
             j2{wk_w, wkTh, nullptr}, j3{wv_w, wvTh, nullptr};
        trans4_kernel<<<dim3(16,16,4), tb>>>(j0, j1, j2, j3);
    }
    convert_h_kernel<<<(EMB*2*EMB)/256, 256>>>(proj_out_w, poh, 2*EMB, EMB*2*EMB);
    trans_convert_kernel<<<dim3(32,16,BATCH), tb>>>(context, (long)EMB*LCTX, LCTX,
                                                    cth, (long)LCTX*EMB, EMB);
    trans_convert_kernel<<<dim3(128,16,BATCH), tb>>>(input, (long)EMB*HW, HW,
                                                     Zh, (long)HW*EMB, EMB);

    // ---- GEMMs ----
    // fold: WqCF[c][f] = piT · wqT0^T (3-term)
    gemm_blk<1,3,0><<<dim3(4,4,1), 256, SMEM3>>>(
        piTh, piTl, EMB, 0, wqT0h, wqT0l, EMB, 0,
        nullptr, WqCFh, EMB, 0, 0, EMB, 1.0f, nullptr, nullptr);
    // K[l][f] = ctxT · wkT^T + wk_b; epilogue also cvec[l] += sum_f bq[f]*K[l][f]
    gemm_blk<1,1,2><<<dim3(4,8,BATCH), 256, SMEM1>>>(
        cth, nullptr, EMB, (long)LCTX*EMB, wkTh, nullptr, EMB, 0,
        cvec, Kh, EMB, (long)LCTX*EMB, 0, EMB, 1.0f, bq, wk_b);
    // V[l][e] = ctxT · wvT^T + wv_b
    gemm_blk<1,1,0><<<dim3(4,8,BATCH), 256, SMEM1>>>(
        cth, nullptr, EMB, (long)LCTX*EMB, wvTh, nullptr, EMB, 0,
        nullptr, Vh, EMB, (long)LCTX*EMB, 0, EMB, 1.0f, nullptr, wv_b);
    // out1[o][p] = po1 · Zh^T + proj_out_b  (fp32 write)
    gemm_blk<0,1,0><<<dim3(32,4,BATCH), 256, SMEM1>>>(
        poh, nullptr, 2*EMB, 0, Zh, nullptr, EMB, (long)HW*EMB,
        out, nullptr, HW, (long)EMB*HW, 0, EMB, 1.0f, proj_out_b, nullptr);
    // W2[o][l] = po2 · V^T  (po2 = k-blocks 8..15 of po)
    gemm_blk<1,1,0><<<dim3(8,4,BATCH), 256, SMEM1>>>(
        poh + 8*BLK_ELEMS, nullptr, 2*EMB, 0, Vh, nullptr, EMB, (long)LCTX*EMB,
        nullptr, W2h, LCTX, (long)EMB*LCTX, 0, EMB, 1.0f, nullptr, nullptr);
    // K'[l][c] = K · WqCF^T   (replaces the Q GEMM: S = Z·K'^T + cvec)
    gemm_blk<1,1,0><<<dim3(4,8,BATCH), 256, SMEM1>>>(
        Kh, nullptr, EMB, (long)LCTX*EMB, WqCFh, nullptr, EMB, 0,
        nullptr, K2h, EMB, (long)LCTX*EMB, 0, EMB, 1.0f, nullptr, nullptr);
    // E = exp(scale * (Z·K'^T + cvec[l])), row sums -> rsum (fused epilogue)
    gemm_blk<1,1,1><<<dim3(8,32,BATCH), 256, SMEM1>>>(
        Zh, nullptr, EMB, (long)HW*EMB, K2h, nullptr, EMB, (long)LCTX*EMB,
        rsum, Eh, LCTX, (long)HW*LCTX, 0, EMB, scale, nullptr, cvec);
    // invert row sums
    invert_kernel<<<(BATCH*HW)/256, 256>>>(rsum, BATCH*HW);
    // out2[o][p] = (W2 · E^T) * invsum[p], accumulate onto out
    gemm_blk<3,1,0><<<dim3(32,4,BATCH), 256, SMEM1>>>(
        W2h, nullptr, LCTX, (long)EMB*LCTX, Eh, nullptr, LCTX, (long)HW*LCTX,
        out, nullptr, HW, (long)EMB*HW, 0, LCTX, 1.0f, nullptr, rsum);
}